// round 5
// baseline (speedup 1.0000x reference)
#include <cuda_runtime.h>
#include <cuda_bf16.h>
#include <cstdint>
#include <cstddef>

// ---------------------------------------------------------------------------
// Transformer forward (encoder-decoder), tf32 tensor cores, R5:
// fused attention (scores+softmax+ctx), split-K GEMMs for N=1024 outputs,
// batched cross-attention K/V projections.
// ---------------------------------------------------------------------------

#define BB   2
#define SS   512
#define DD   1024
#define HH   16
#define DKK  64
#define DFFF 4096
#define LL   4
#define MROWS (BB*SS)          // 1024
#define EPSF 1e-5f
#define INV_SCALE 0.125f       // 1/sqrt(DK)

static const size_t MEG = 1u << 20;
__device__ __align__(16) float g_scratch[31u * (1u << 20)];   // 124 MB

// ---------------------------------------------------------------------------
// tf32 helpers
// ---------------------------------------------------------------------------
__device__ __forceinline__ uint32_t f2t(float x) {
    uint32_t r; asm("cvt.rna.tf32.f32 %0, %1;" : "=r"(r) : "f"(x)); return r;
}
__device__ __forceinline__ void mma8(float* c, const uint32_t* a, const uint32_t* b) {
    asm volatile(
        "mma.sync.aligned.m16n8k8.row.col.f32.tf32.tf32.f32 "
        "{%0,%1,%2,%3}, {%4,%5,%6,%7}, {%8,%9}, {%0,%1,%2,%3};\n"
        : "+f"(c[0]), "+f"(c[1]), "+f"(c[2]), "+f"(c[3])
        : "r"(a[0]), "r"(a[1]), "r"(a[2]), "r"(a[3]), "r"(b[0]), "r"(b[1]));
}
__device__ __forceinline__ uint4 cvt4(float4 v) {
    uint4 u; u.x = f2t(v.x); u.y = f2t(v.y); u.z = f2t(v.z); u.w = f2t(v.w);
    return u;
}

// ---------------------------------------------------------------------------
// Wide tf32 GEMM: C[M, totalN] = A[M,K] @ W + bias, optional ReLU.
// Blocked-N (fused QKV / per-layer batched KV): blk = colg/nb;
//   W += blk*wstride; bias += blk*bstride; C += blk*cstride;
//   inner row strides of W and C are nb.
// 64x128 tile, 256 thr (8 warps, 32x32 each), K-step 32, double buffer.
// Grid: (totalN/128, M/64). Dyn smem: 2*(64*36 + 32*136)*4 = 53248 B.
// ---------------------------------------------------------------------------
__global__ __launch_bounds__(256, 2)
void gemm_wide(const float* __restrict__ A, const float* __restrict__ W,
               const float* __restrict__ bias, float* __restrict__ C,
               int K, int nb, int relu,
               long long wstride, long long bstride, long long cstride)
{
    constexpr int ASTR = 36, BSTR = 136;
    constexpr int ASZ = 64 * ASTR, BSZ = 32 * BSTR, STG = ASZ + BSZ;
    extern __shared__ uint32_t smg[];

    const int t = threadIdx.x;
    const int lane = t & 31, w = t >> 5;
    const int g = lane >> 2, cc = lane & 3;
    const int wm = w >> 2, wn = w & 3;          // 2x4 warp grid, 32x32 tiles
    const int row0 = blockIdx.y * 64;
    const int colg = blockIdx.x * 128;
    const int blk  = colg / nb;
    const int col0 = colg - blk * nb;
    const float* Wp = W + (size_t)blk * (size_t)wstride;
    const float* bp = bias + (size_t)blk * (size_t)bstride;
    float* Cp = C + (size_t)blk * (size_t)cstride;

    const int ar = t >> 3, ac = (t & 7) << 2;   // A: 64x32, 2 f4/thread
    const int bk0 = t >> 5, bc = (t & 31) << 2; // B: 32x128, 4 f4/thread

    float4 aR[2], bR[4];
    auto loadAB = [&](int k0) {
#pragma unroll
        for (int i = 0; i < 2; i++)
            aR[i] = *(const float4*)&A[(size_t)(row0 + ar + i * 32) * K + k0 + ac];
#pragma unroll
        for (int i = 0; i < 4; i++)
            bR[i] = *(const float4*)&Wp[(size_t)(k0 + bk0 + i * 8) * nb + col0 + bc];
    };
    auto storeAB = [&](int p) {
        uint32_t* as_ = smg + p * STG;
        uint32_t* bs_ = smg + p * STG + ASZ;
#pragma unroll
        for (int i = 0; i < 2; i++)
            *(uint4*)&as_[(ar + i * 32) * ASTR + ac] = cvt4(aR[i]);
#pragma unroll
        for (int i = 0; i < 4; i++)
            *(uint4*)&bs_[(bk0 + i * 8) * BSTR + bc] = cvt4(bR[i]);
    };

    float acc[2][4][4] = {};
    const int NK = K >> 5;
    loadAB(0);
    storeAB(0);
    if (NK > 1) loadAB(32);
    __syncthreads();

    for (int it = 0; it < NK; it++) {
        const int p = it & 1;
        if (it + 1 < NK) storeAB(p ^ 1);
        if (it + 2 < NK) loadAB((it + 2) << 5);

        const uint32_t* as_ = smg + p * STG;
        const uint32_t* bs_ = smg + p * STG + ASZ;
        uint32_t af[2][4], bf[4][2];
#pragma unroll
        for (int ks = 0; ks < 4; ks++) {
            const int kb = ks * 8 + cc;
#pragma unroll
            for (int mi = 0; mi < 2; mi++) {
                const int mb = wm * 32 + mi * 16;
                af[mi][0] = as_[(mb + g) * ASTR + kb];
                af[mi][1] = as_[(mb + g + 8) * ASTR + kb];
                af[mi][2] = as_[(mb + g) * ASTR + kb + 4];
                af[mi][3] = as_[(mb + g + 8) * ASTR + kb + 4];
            }
#pragma unroll
            for (int nj = 0; nj < 4; nj++) {
                const int nbase = wn * 32 + nj * 8;
                bf[nj][0] = bs_[kb * BSTR + nbase + g];
                bf[nj][1] = bs_[(kb + 4) * BSTR + nbase + g];
            }
#pragma unroll
            for (int mi = 0; mi < 2; mi++)
#pragma unroll
                for (int nj = 0; nj < 4; nj++)
                    mma8(acc[mi][nj], af[mi], bf[nj]);
        }
        __syncthreads();
    }

#pragma unroll
    for (int mi = 0; mi < 2; mi++) {
        const int r0 = row0 + wm * 32 + mi * 16 + g;
#pragma unroll
        for (int nj = 0; nj < 4; nj++) {
            const int c = col0 + wn * 32 + nj * 8 + 2 * cc;
            const float b0v = bp[c], b1v = bp[c + 1];
            float v0 = acc[mi][nj][0] + b0v, v1 = acc[mi][nj][1] + b1v;
            float v2 = acc[mi][nj][2] + b0v, v3 = acc[mi][nj][3] + b1v;
            if (relu) {
                v0 = fmaxf(v0, 0.f); v1 = fmaxf(v1, 0.f);
                v2 = fmaxf(v2, 0.f); v3 = fmaxf(v3, 0.f);
            }
            *(float2*)&Cp[(size_t)r0 * nb + c]       = make_float2(v0, v1);
            *(float2*)&Cp[(size_t)(r0 + 8) * nb + c] = make_float2(v2, v3);
        }
    }
}

// ---------------------------------------------------------------------------
// Split-K tf32 GEMM, N=1024 fixed: parts[z] = A[:, z*Kc:(z+1)*Kc] @ W-slice.
// 64x64 tile, 128 thr (4 warps 2x2, 32x32 each), K-step 32, double buffer.
// Grid: (16, 16, nsplit). No bias (applied in reduce).
// ---------------------------------------------------------------------------
__global__ __launch_bounds__(128, 4)
void gemm_sk(const float* __restrict__ A, const float* __restrict__ W,
             float* __restrict__ parts, int lda, int Kc)
{
    constexpr int ASTR = 36, BSTR = 72;
    constexpr int ASZ = 64 * ASTR, BSZ = 32 * BSTR, STG = ASZ + BSZ;
    __shared__ uint32_t smg[2 * STG];   // 36864 B

    const int z = blockIdx.z;
    const float* Az = A + (size_t)z * Kc;
    const float* Wz = W + (size_t)z * Kc * 1024;
    float* Cp = parts + (size_t)z * MEG;

    const int t = threadIdx.x;
    const int lane = t & 31, w = t >> 5;
    const int g = lane >> 2, cc = lane & 3;
    const int wm = w >> 1, wn = w & 1;
    const int row0 = blockIdx.y * 64;
    const int col0 = blockIdx.x * 64;

    const int ar = t >> 3, ac = (t & 7) << 2;    // A: 64x32, 4 rows apart 16
    const int bk = t >> 4, bc = (t & 15) << 2;   // B: 32x64, 4 rows apart 8

    float4 aR[4], bR[4];
    auto loadAB = [&](int k0) {
#pragma unroll
        for (int i = 0; i < 4; i++)
            aR[i] = *(const float4*)&Az[(size_t)(row0 + ar + i * 16) * lda + k0 + ac];
#pragma unroll
        for (int i = 0; i < 4; i++)
            bR[i] = *(const float4*)&Wz[(size_t)(k0 + bk + i * 8) * 1024 + col0 + bc];
    };
    auto storeAB = [&](int p) {
        uint32_t* as_ = smg + p * STG;
        uint32_t* bs_ = smg + p * STG + ASZ;
#pragma unroll
        for (int i = 0; i < 4; i++)
            *(uint4*)&as_[(ar + i * 16) * ASTR + ac] = cvt4(aR[i]);
#pragma unroll
        for (int i = 0; i < 4; i++)
            *(uint4*)&bs_[(bk + i * 8) * BSTR + bc] = cvt4(bR[i]);
    };

    float acc[2][4][4] = {};
    const int NK = Kc >> 5;
    loadAB(0);
    storeAB(0);
    if (NK > 1) loadAB(32);
    __syncthreads();

    for (int it = 0; it < NK; it++) {
        const int p = it & 1;
        if (it + 1 < NK) storeAB(p ^ 1);
        if (it + 2 < NK) loadAB((it + 2) << 5);

        const uint32_t* as_ = smg + p * STG;
        const uint32_t* bs_ = smg + p * STG + ASZ;
        uint32_t af[2][4], bf[4][2];
#pragma unroll
        for (int ks = 0; ks < 4; ks++) {
            const int kb = ks * 8 + cc;
#pragma unroll
            for (int mi = 0; mi < 2; mi++) {
                const int mb = wm * 32 + mi * 16;
                af[mi][0] = as_[(mb + g) * ASTR + kb];
                af[mi][1] = as_[(mb + g + 8) * ASTR + kb];
                af[mi][2] = as_[(mb + g) * ASTR + kb + 4];
                af[mi][3] = as_[(mb + g + 8) * ASTR + kb + 4];
            }
#pragma unroll
            for (int nj = 0; nj < 4; nj++) {
                const int nbase = wn * 32 + nj * 8;
                bf[nj][0] = bs_[kb * BSTR + nbase + g];
                bf[nj][1] = bs_[(kb + 4) * BSTR + nbase + g];
            }
#pragma unroll
            for (int mi = 0; mi < 2; mi++)
#pragma unroll
                for (int nj = 0; nj < 4; nj++)
                    mma8(acc[mi][nj], af[mi], bf[nj]);
        }
        __syncthreads();
    }

#pragma unroll
    for (int mi = 0; mi < 2; mi++) {
        const int r0 = row0 + wm * 32 + mi * 16 + g;
#pragma unroll
        for (int nj = 0; nj < 4; nj++) {
            const int c = col0 + wn * 32 + nj * 8 + 2 * cc;
            *(float2*)&Cp[(size_t)r0 * 1024 + c] =
                make_float2(acc[mi][nj][0], acc[mi][nj][1]);
            *(float2*)&Cp[(size_t)(r0 + 8) * 1024 + c] =
                make_float2(acc[mi][nj][2], acc[mi][nj][3]);
        }
    }
}

// ---------------------------------------------------------------------------
// Reduce split-K partials + bias (+ReLU). 1M elems, N=1024.
// ---------------------------------------------------------------------------
__global__ __launch_bounds__(256)
void reduce_bias(const float* __restrict__ parts, int nparts,
                 const float* __restrict__ bias, float* __restrict__ C, int relu)
{
    const size_t idx = ((size_t)blockIdx.x * 256 + threadIdx.x) * 4;
    float4 s = *(const float4*)&parts[idx];
    for (int p = 1; p < nparts; p++) {
        float4 q = *(const float4*)&parts[p * MEG + idx];
        s.x += q.x; s.y += q.y; s.z += q.z; s.w += q.w;
    }
    const int col = (int)(idx & 1023);
    float4 bv = *(const float4*)&bias[col];
    s.x += bv.x; s.y += bv.y; s.z += bv.z; s.w += bv.w;
    if (relu) {
        s.x = fmaxf(s.x, 0.f); s.y = fmaxf(s.y, 0.f);
        s.z = fmaxf(s.z, 0.f); s.w = fmaxf(s.w, 0.f);
    }
    *(float4*)&C[idx] = s;
}

// ---------------------------------------------------------------------------
// Fused attention: scores (tf32 mma) + mask + softmax + P stream-out + P.V.
// Block: 64 q-rows x all 512 keys; grid (S/64, B*H); 256 threads.
// Dyn smem: Qs(64x68 u32) + KVs(64x68 u32) + S(64x516 f32) = 166912 B.
// ctx written to ctxb (may alias qf: each CTA's read/write sets are disjoint
// per (row,head) and Q is consumed into smem before writes).
// ---------------------------------------------------------------------------
__global__ __launch_bounds__(256)
void attn_fused(const float* __restrict__ qf, const float* __restrict__ kf,
                const float* __restrict__ vf, const int* __restrict__ mask,
                int causal, float* __restrict__ attn, float* __restrict__ ctxb)
{
    extern __shared__ float smemf[];
    uint32_t* Qs  = (uint32_t*)smemf;       // 64*68
    uint32_t* KVs = Qs + 64 * 68;           // 64*68 (K chunks, then V chunks)
    float* Ssm = smemf + 2 * 64 * 68;       // 64*516

    const int bh = blockIdx.y, b = bh >> 4, h = bh & 15;
    const int q0 = blockIdx.x * 64;
    const int t = threadIdx.x, lane = t & 31, w = t >> 5;
    const int g = lane >> 2, cc = lane & 3;
    const int qslot = w & 3, kslot = w >> 2;   // 4x2 warp grid, 16x32 tiles

    // ---- Phase 1: S = Q.K^T ----
#pragma unroll
    for (int i = 0; i < 4; i++) {
        const int idx = t + i * 256;
        const int r = idx >> 4, cq = (idx & 15) << 2;
        float4 v = *(const float4*)&qf[(size_t)(b * SS + q0 + r) * DD + h * DKK + cq];
        *(uint4*)&Qs[r * 68 + cq] = cvt4(v);
    }

    for (int kt = 0; kt < 8; kt++) {
        float4 kv[4];
#pragma unroll
        for (int i = 0; i < 4; i++) {
            const int idx = t + i * 256;
            const int r = idx >> 4, cq = (idx & 15) << 2;
            kv[i] = *(const float4*)&kf[(size_t)(b * SS + kt * 64 + r) * DD + h * DKK + cq];
        }
        __syncthreads();
#pragma unroll
        for (int i = 0; i < 4; i++) {
            const int idx = t + i * 256;
            const int r = idx >> 4, cq = (idx & 15) << 2;
            *(uint4*)&KVs[r * 68 + cq] = cvt4(kv[i]);
        }
        __syncthreads();

        float acc[4][4] = {};
        uint32_t af[4];
#pragma unroll
        for (int ks = 0; ks < 8; ks++) {
            const int kb = ks * 8 + cc;
            const int mb = qslot * 16;
            af[0] = Qs[(mb + g) * 68 + kb];
            af[1] = Qs[(mb + g + 8) * 68 + kb];
            af[2] = Qs[(mb + g) * 68 + kb + 4];
            af[3] = Qs[(mb + g + 8) * 68 + kb + 4];
#pragma unroll
            for (int nj = 0; nj < 4; nj++) {
                const int nbase = kslot * 32 + nj * 8;
                uint32_t bf[2];
                bf[0] = KVs[(nbase + g) * 68 + kb];
                bf[1] = KVs[(nbase + g) * 68 + kb + 4];
                mma8(acc[nj], af, bf);
            }
        }
#pragma unroll
        for (int nj = 0; nj < 4; nj++) {
            const int colb = kt * 64 + kslot * 32 + nj * 8 + 2 * cc;
            const int rr = qslot * 16 + g;
            *(float2*)&Ssm[rr * 516 + colb]       = make_float2(acc[nj][0], acc[nj][1]);
            *(float2*)&Ssm[(rr + 8) * 516 + colb] = make_float2(acc[nj][2], acc[nj][3]);
        }
    }
    __syncthreads();

    // ---- Phase 2: softmax; write P to gmem (output) and back to Ssm ----
    for (int i = 0; i < 8; i++) {
        const int rloc = w * 8 + i;
        const int q = q0 + rloc;
        float vals[16];
        float mx = -1e30f;
#pragma unroll
        for (int j = 0; j < 16; j++) {
            const int col = lane + j * 32;
            float v = Ssm[rloc * 516 + col] * INV_SCALE;
            const int m = causal ? mask[((size_t)b * SS + q) * SS + col]
                                 : mask[(size_t)b * SS + col];
            if (m == 0) v = -1e9f;
            vals[j] = v;
            mx = fmaxf(mx, v);
        }
#pragma unroll
        for (int o = 16; o > 0; o >>= 1)
            mx = fmaxf(mx, __shfl_xor_sync(0xffffffffu, mx, o));
        float sum = 0.0f;
#pragma unroll
        for (int j = 0; j < 16; j++) {
            vals[j] = expf(vals[j] - mx);
            sum += vals[j];
        }
#pragma unroll
        for (int o = 16; o > 0; o >>= 1)
            sum += __shfl_xor_sync(0xffffffffu, sum, o);
        const float inv = 1.0f / sum;
        float* dst = attn + ((size_t)bh * SS + q) * SS;
#pragma unroll
        for (int j = 0; j < 16; j++) {
            const float p = vals[j] * inv;
            dst[lane + j * 32] = p;
            Ssm[rloc * 516 + lane + j * 32] = p;
        }
    }
    __syncthreads();

    // ---- Phase 3: ctx = P.V ----
    float acc[4][4] = {};
    const int dslot = kslot;                   // 2 column slots of 32
    for (int kt = 0; kt < 8; kt++) {
        float4 vv[4];
#pragma unroll
        for (int i = 0; i < 4; i++) {
            const int idx = t + i * 256;
            const int r = idx >> 4, cq = (idx & 15) << 2;
            vv[i] = *(const float4*)&vf[(size_t)(b * SS + kt * 64 + r) * DD + h * DKK + cq];
        }
        __syncthreads();
#pragma unroll
        for (int i = 0; i < 4; i++) {
            const int idx = t + i * 256;
            const int r = idx >> 4, cq = (idx & 15) << 2;
            *(uint4*)&KVs[r * 68 + cq] = cvt4(vv[i]);
        }
        __syncthreads();

        uint32_t af[4];
#pragma unroll
        for (int ks = 0; ks < 8; ks++) {
            const int kb = ks * 8 + cc;
            const int colb = kt * 64 + kb;
            const int mb = qslot * 16;
            af[0] = f2t(Ssm[(mb + g) * 516 + colb]);
            af[1] = f2t(Ssm[(mb + g + 8) * 516 + colb]);
            af[2] = f2t(Ssm[(mb + g) * 516 + colb + 4]);
            af[3] = f2t(Ssm[(mb + g + 8) * 516 + colb + 4]);
#pragma unroll
            for (int nj = 0; nj < 4; nj++) {
                const int nbase = dslot * 32 + nj * 8;
                uint32_t bf[2];
                bf[0] = KVs[kb * 68 + nbase + g];
                bf[1] = KVs[(kb + 4) * 68 + nbase + g];
                mma8(acc[nj], af, bf);
            }
        }
    }

    float* Cp = ctxb + (size_t)b * SS * DD + h * DKK;
#pragma unroll
    for (int nj = 0; nj < 4; nj++) {
        const int c = dslot * 32 + nj * 8 + 2 * cc;
        const int r = q0 + qslot * 16 + g;
        *(float2*)&Cp[(size_t)r * DD + c]       = make_float2(acc[nj][0], acc[nj][1]);
        *(float2*)&Cp[(size_t)(r + 8) * DD + c] = make_float2(acc[nj][2], acc[nj][3]);
    }
}

// ---------------------------------------------------------------------------
// y = LayerNorm(x + a). a may be nullptr. One block per row (D=1024).
// ---------------------------------------------------------------------------
__global__ __launch_bounds__(256)
void add_ln_kernel(const float* __restrict__ x,
                   const float* __restrict__ a,
                   const float* __restrict__ g,
                   const float* __restrict__ bt,
                   float* __restrict__ y)
{
    const int row = blockIdx.x;
    const int t = threadIdx.x;
    __shared__ float red[256];

    float v[4];
#pragma unroll
    for (int i = 0; i < 4; i++) {
        const int c = t + i * 256;
        float vv = x[(size_t)row * DD + c];
        if (a) vv += a[(size_t)row * DD + c];
        v[i] = vv;
    }
    float s = v[0] + v[1] + v[2] + v[3];
    red[t] = s;
    __syncthreads();
    for (int o = 128; o > 0; o >>= 1) {
        if (t < o) red[t] += red[t + o];
        __syncthreads();
    }
    const float mean = red[0] * (1.0f / DD);
    __syncthreads();

    float s2 = 0.0f;
#pragma unroll
    for (int i = 0; i < 4; i++) {
        const float d = v[i] - mean;
        s2 += d * d;
    }
    red[t] = s2;
    __syncthreads();
    for (int o = 128; o > 0; o >>= 1) {
        if (t < o) red[t] += red[t + o];
        __syncthreads();
    }
    const float var = red[0] * (1.0f / DD);
    const float inv = rsqrtf(var + EPSF);

#pragma unroll
    for (int i = 0; i < 4; i++) {
        const int c = t + i * 256;
        y[(size_t)row * DD + c] = g[c] * (v[i] - mean) * inv + bt[c];
    }
}

// ---------------------------------------------------------------------------
// Host orchestration
// ---------------------------------------------------------------------------
extern "C" void kernel_launch(void* const* d_in, const int* in_sizes, int n_in,
                              void* d_out, int out_size)
{
    const float* src     = (const float*)d_in[0];
    const float* tgt     = (const float*)d_in[1];
    const float* enc_W   = (const float*)d_in[2];
    const float* enc_b   = (const float*)d_in[3];
    const float* enc_W1  = (const float*)d_in[4];
    const float* enc_b1  = (const float*)d_in[5];
    const float* enc_W2  = (const float*)d_in[6];
    const float* enc_b2  = (const float*)d_in[7];
    const float* enc_lng = (const float*)d_in[8];
    const float* enc_lnb = (const float*)d_in[9];
    const float* enc_fg  = (const float*)d_in[10];
    const float* enc_fb  = (const float*)d_in[11];
    const float* dsW     = (const float*)d_in[12];
    const float* dsb     = (const float*)d_in[13];
    const float* dcW     = (const float*)d_in[14];
    const float* dcb     = (const float*)d_in[15];
    const float* dW1     = (const float*)d_in[16];
    const float* db1     = (const float*)d_in[17];
    const float* dW2     = (const float*)d_in[18];
    const float* db2     = (const float*)d_in[19];
    const float* dlng    = (const float*)d_in[20];
    const float* dlnb    = (const float*)d_in[21];
    const float* dfg     = (const float*)d_in[22];
    const float* dfb     = (const float*)d_in[23];
    const int*   src_mask = (const int*)d_in[24];
    const int*   tgt_mask = (const int*)d_in[25];
    float* out = (float*)d_out;

    float* scratch = nullptr;
    cudaGetSymbolAddress((void**)&scratch, g_scratch);

    float* X    = scratch + 0 * MEG;
    float* X2   = scratch + 1 * MEG;
    float* Qb   = scratch + 2 * MEG;   // Q/K/V contiguous for fused QKV gemm
    float* Kb   = scratch + 3 * MEG;
    float* Vb   = scratch + 4 * MEG;
    float* Ab   = scratch + 5 * MEG;
    float* H1   = scratch + 6 * MEG;   // 4M floats
    float* ATT  = scratch + 10 * MEG;  // 8M floats (fallback only)
    float* ENC  = scratch + 18 * MEG;
    float* PRT  = scratch + 19 * MEG;  // 4M floats (split-K partials)
    float* CK   = scratch + 23 * MEG;  // 4M floats (cross K, all layers)
    float* CV   = scratch + 27 * MEG;  // 4M floats (cross V, all layers)

    const size_t SLAB      = (size_t)BB * HH * SS * SS;
    const size_t OFF_ENC   = (size_t)BB * SS * DD;
    const size_t OFF_SELF  = OFF_ENC + (size_t)LL * SLAB;
    const size_t OFF_CROSS = OFF_SELF + (size_t)LL * SLAB;
    const size_t TOTAL     = OFF_CROSS + (size_t)LL * SLAB;
    const bool full = ((size_t)out_size >= TOTAL);

    const int SM_W = 2 * (64 * 36 + 32 * 136) * 4;  // 53248 B
    cudaFuncSetAttribute(gemm_wide, cudaFuncAttributeMaxDynamicSharedMemorySize, SM_W);
    const size_t SC_SMEM = (size_t)(2 * 64 * 68 + 64 * 516) * sizeof(float);
    cudaFuncSetAttribute(attn_fused,
                         cudaFuncAttributeMaxDynamicSharedMemorySize, (int)SC_SMEM);

    dim3 gQKV(3072 / 128, MROWS / 64);    // 24 x 16 = 384
    dim3 gKVB(4096 / 128, MROWS / 64);    // 32 x 16 = 512 (batched cross K or V)
    dim3 gF1(DFFF / 128, MROWS / 64);     // 32 x 16 = 512
    dim3 gSK2(16, 16, 2);                 // 512 CTAs (K=1024 split 2)
    dim3 gSK4(16, 16, 4);                 // 1024 CTAs (K=4096 split 4)
    dim3 gS(SS / 64, BB * HH);            // 8 x 32
    const long long WS = (long long)DD * DD;
    const long long CS = (long long)MEG;

    // ------------------------- Encoder -------------------------
    const float* cur = src;
    for (int l = 0; l < LL; l++) {
        const float* W  = enc_W + (size_t)l * 4 * DD * DD;
        const float* bb = enc_b + (size_t)l * 4 * DD;
        gemm_wide<<<gQKV, 256, SM_W>>>(cur, W, bb, Qb, DD, DD, 0, WS, DD, CS);
        float* adst = full ? out + OFF_ENC + (size_t)l * SLAB : ATT;
        attn_fused<<<gS, 256, SC_SMEM>>>(Qb, Kb, Vb, src_mask, 0, adst, Qb);
        gemm_sk<<<gSK2, 128>>>(Qb, W + 3 * DD * DD, PRT, DD, 512);
        reduce_bias<<<1024, 256>>>(PRT, 2, bb + 3 * DD, Ab, 0);
        add_ln_kernel<<<MROWS, 256>>>(cur, Ab, enc_lng + (size_t)l * 2 * DD,
                                      enc_lnb + (size_t)l * 2 * DD, X2);
        gemm_wide<<<gF1, 256, SM_W>>>(X2, enc_W1 + (size_t)l * DD * DFFF,
                                      enc_b1 + (size_t)l * DFFF, H1, DD, DFFF, 1, 0, 0, 0);
        gemm_sk<<<gSK4, 128>>>(H1, enc_W2 + (size_t)l * DFFF * DD, PRT, DFFF, 1024);
        reduce_bias<<<1024, 256>>>(PRT, 4, enc_b2 + (size_t)l * DD, Ab, 0);
        add_ln_kernel<<<MROWS, 256>>>(X2, Ab, enc_lng + (size_t)l * 2 * DD + DD,
                                      enc_lnb + (size_t)l * 2 * DD + DD, X);
        cur = X;
    }
    add_ln_kernel<<<MROWS, 256>>>(cur, nullptr, enc_fg, enc_fb, ENC);

    // Batched cross-attention K/V for all decoder layers (blk = layer)
    gemm_wide<<<gKVB, 256, SM_W>>>(ENC, dcW + (size_t)DD * DD, dcb + DD, CK,
                                   DD, DD, 0, 4LL * DD * DD, 4LL * DD, CS);
    gemm_wide<<<gKVB, 256, SM_W>>>(ENC, dcW + 2 * (size_t)DD * DD, dcb + 2 * DD, CV,
                                   DD, DD, 0, 4LL * DD * DD, 4LL * DD, CS);

    // ------------------------- Decoder -------------------------
    cur = tgt;
    for (int l = 0; l < LL; l++) {
        // self-attention (causal)
        const float* Ws = dsW + (size_t)l * 4 * DD * DD;
        const float* bs = dsb + (size_t)l * 4 * DD;
        gemm_wide<<<gQKV, 256, SM_W>>>(cur, Ws, bs, Qb, DD, DD, 0, WS, DD, CS);
        float* adst = full ? out + OFF_SELF + (size_t)l * SLAB : ATT;
        attn_fused<<<gS, 256, SC_SMEM>>>(Qb, Kb, Vb, tgt_mask, 1, adst, Qb);
        gemm_sk<<<gSK2, 128>>>(Qb, Ws + 3 * DD * DD, PRT, DD, 512);
        reduce_bias<<<1024, 256>>>(PRT, 2, bs + 3 * DD, Ab, 0);
        add_ln_kernel<<<MROWS, 256>>>(cur, Ab, dlng + (size_t)l * 3 * DD,
                                      dlnb + (size_t)l * 3 * DD, X);

        // cross-attention (K/V precomputed)
        const float* Wc = dcW + (size_t)l * 4 * DD * DD;
        const float* bc = dcb + (size_t)l * 4 * DD;
        gemm_sk<<<gSK2, 128>>>(X, Wc, PRT, DD, 512);
        reduce_bias<<<1024, 256>>>(PRT, 2, bc, Qb, 0);
        adst = full ? out + OFF_CROSS + (size_t)l * SLAB : ATT;
        attn_fused<<<gS, 256, SC_SMEM>>>(Qb, CK + (size_t)l * MEG, CV + (size_t)l * MEG,
                                         src_mask, 0, adst, Qb);
        gemm_sk<<<gSK2, 128>>>(Qb, Wc + 3 * DD * DD, PRT, DD, 512);
        reduce_bias<<<1024, 256>>>(PRT, 2, bc + 3 * DD, Ab, 0);
        add_ln_kernel<<<MROWS, 256>>>(X, Ab, dlng + (size_t)l * 3 * DD + DD,
                                      dlnb + (size_t)l * 3 * DD + DD, X2);

        // FFN
        gemm_wide<<<gF1, 256, SM_W>>>(X2, dW1 + (size_t)l * DD * DFFF,
                                      db1 + (size_t)l * DFFF, H1, DD, DFFF, 1, 0, 0, 0);
        gemm_sk<<<gSK4, 128>>>(H1, dW2 + (size_t)l * DFFF * DD, PRT, DFFF, 1024);
        reduce_bias<<<1024, 256>>>(PRT, 4, db2 + (size_t)l * DD, Ab, 0);
        add_ln_kernel<<<MROWS, 256>>>(X2, Ab, dlng + (size_t)l * 3 * DD + 2 * DD,
                                      dlnb + (size_t)l * 3 * DD + 2 * DD, X);
        cur = X;
    }
    add_ln_kernel<<<MROWS, 256>>>(cur, nullptr, dfg, dfb, out);
}

// round 6
// speedup vs baseline: 1.4728x; 1.4728x over previous
#include <cuda_runtime.h>
#include <cuda_bf16.h>
#include <cstdint>
#include <cstddef>

// ---------------------------------------------------------------------------
// Transformer forward (encoder-decoder), tf32 tensor cores, R6:
// R4 structure (separate attn kernels, double-buffered GEMMs) +
// split-K for FFN2 (K=4096) + batched decoder cross-K/V projections.
// ---------------------------------------------------------------------------

#define BB   2
#define SS   512
#define DD   1024
#define HH   16
#define DKK  64
#define DFFF 4096
#define LL   4
#define MROWS (BB*SS)          // 1024
#define EPSF 1e-5f
#define INV_SCALE 0.125f       // 1/sqrt(DK)

static const size_t MEG = 1u << 20;
__device__ __align__(16) float g_scratch[31u * (1u << 20)];   // 124 MB

// ---------------------------------------------------------------------------
// tf32 helpers
// ---------------------------------------------------------------------------
__device__ __forceinline__ uint32_t f2t(float x) {
    uint32_t r; asm("cvt.rna.tf32.f32 %0, %1;" : "=r"(r) : "f"(x)); return r;
}
__device__ __forceinline__ void mma8(float* c, const uint32_t* a, const uint32_t* b) {
    asm volatile(
        "mma.sync.aligned.m16n8k8.row.col.f32.tf32.tf32.f32 "
        "{%0,%1,%2,%3}, {%4,%5,%6,%7}, {%8,%9}, {%0,%1,%2,%3};\n"
        : "+f"(c[0]), "+f"(c[1]), "+f"(c[2]), "+f"(c[3])
        : "r"(a[0]), "r"(a[1]), "r"(a[2]), "r"(a[3]), "r"(b[0]), "r"(b[1]));
}
__device__ __forceinline__ uint4 cvt4(float4 v) {
    uint4 u; u.x = f2t(v.x); u.y = f2t(v.y); u.z = f2t(v.z); u.w = f2t(v.w);
    return u;
}

// ---------------------------------------------------------------------------
// tf32 GEMM, templated tile: C[M, totalN] = A[M,K] @ W + bias, optional ReLU.
// Blocked-N support: blk = colg/nb; W += blk*wstride; bias += blk*bstride;
// C += blk*cstride; inner row strides of W and C are nb.
// TM x TN block tile, 8 warps (WR x WC grid), K-step 32, double buffer.
// Grid: (totalN/TN, M/TM). Dyn smem: 2*(TM*36 + 32*(TN+8))*4.
// ---------------------------------------------------------------------------
template<int TM, int TN, int WR, int WC>
__global__ __launch_bounds__(256, 2)
void gemm_tf32(const float* __restrict__ A, const float* __restrict__ W,
               const float* __restrict__ bias, float* __restrict__ C,
               int K, int nb, int relu,
               long long wstride, long long bstride, long long cstride)
{
    constexpr int ASTR = 36;
    constexpr int BSTR = TN + 8;
    constexpr int ASZ  = TM * ASTR;
    constexpr int BSZ  = 32 * BSTR;
    constexpr int STG  = ASZ + BSZ;
    constexpr int WM = TM / WR, WN = TN / WC;
    constexpr int MI = WM / 16, NJ = WN / 8;
    constexpr int NA = TM / 32;
    constexpr int NB = TN / 32;
    constexpr int BPR = TN / 4;
    constexpr int BRP = 256 / BPR;

    extern __shared__ uint32_t smg[];

    const int t = threadIdx.x;
    const int lane = t & 31, w = t >> 5;
    const int g = lane >> 2, cc = lane & 3;
    const int wm = w / WC, wn = w % WC;
    const int row0 = blockIdx.y * TM;
    const int colg = blockIdx.x * TN;
    const int blk  = colg / nb;
    const int col0 = colg - blk * nb;
    const float* Wp = W + (size_t)blk * (size_t)wstride;
    const float* bp = bias + (size_t)blk * (size_t)bstride;
    float* Cp = C + (size_t)blk * (size_t)cstride;

    const int ar = t >> 3;
    const int ac = (t & 7) << 2;
    const int bk0 = t / BPR;
    const int bc  = (t % BPR) << 2;

    float4 aR[NA], bR[NB];

    auto loadAB = [&](int k0) {
#pragma unroll
        for (int i = 0; i < NA; i++)
            aR[i] = *(const float4*)&A[(size_t)(row0 + ar + i * 32) * K + k0 + ac];
#pragma unroll
        for (int i = 0; i < NB; i++)
            bR[i] = *(const float4*)&Wp[(size_t)(k0 + bk0 + i * BRP) * nb + col0 + bc];
    };
    auto storeAB = [&](int p) {
        uint32_t* as_ = smg + p * STG;
        uint32_t* bs_ = smg + p * STG + ASZ;
#pragma unroll
        for (int i = 0; i < NA; i++)
            *(uint4*)&as_[(ar + i * 32) * ASTR + ac] = cvt4(aR[i]);
#pragma unroll
        for (int i = 0; i < NB; i++)
            *(uint4*)&bs_[(bk0 + i * BRP) * BSTR + bc] = cvt4(bR[i]);
    };

    float acc[MI][NJ][4];
#pragma unroll
    for (int a_ = 0; a_ < MI; a_++)
#pragma unroll
        for (int b_ = 0; b_ < NJ; b_++)
#pragma unroll
            for (int c_ = 0; c_ < 4; c_++) acc[a_][b_][c_] = 0.f;

    const int NK = K >> 5;
    loadAB(0);
    storeAB(0);
    if (NK > 1) loadAB(32);
    __syncthreads();

    for (int it = 0; it < NK; it++) {
        const int p = it & 1;
        if (it + 1 < NK) storeAB(p ^ 1);
        if (it + 2 < NK) loadAB((it + 2) << 5);

        const uint32_t* as_ = smg + p * STG;
        const uint32_t* bs_ = smg + p * STG + ASZ;
        uint32_t af[MI][4], bf[NJ][2];
#pragma unroll
        for (int ks = 0; ks < 4; ks++) {
            const int kb = ks * 8 + cc;
#pragma unroll
            for (int mi = 0; mi < MI; mi++) {
                const int mb = wm * WM + mi * 16;
                af[mi][0] = as_[(mb + g) * ASTR + kb];
                af[mi][1] = as_[(mb + g + 8) * ASTR + kb];
                af[mi][2] = as_[(mb + g) * ASTR + kb + 4];
                af[mi][3] = as_[(mb + g + 8) * ASTR + kb + 4];
            }
#pragma unroll
            for (int nj = 0; nj < NJ; nj++) {
                const int nbase = wn * WN + nj * 8;
                bf[nj][0] = bs_[kb * BSTR + nbase + g];
                bf[nj][1] = bs_[(kb + 4) * BSTR + nbase + g];
            }
#pragma unroll
            for (int mi = 0; mi < MI; mi++)
#pragma unroll
                for (int nj = 0; nj < NJ; nj++)
                    mma8(acc[mi][nj], af[mi], bf[nj]);
        }
        __syncthreads();
    }

#pragma unroll
    for (int mi = 0; mi < MI; mi++) {
        const int r0 = row0 + wm * WM + mi * 16 + g;
#pragma unroll
        for (int nj = 0; nj < NJ; nj++) {
            const int c = col0 + wn * WN + nj * 8 + 2 * cc;
            const float b0v = bp[c], b1v = bp[c + 1];
            float v0 = acc[mi][nj][0] + b0v, v1 = acc[mi][nj][1] + b1v;
            float v2 = acc[mi][nj][2] + b0v, v3 = acc[mi][nj][3] + b1v;
            if (relu) {
                v0 = fmaxf(v0, 0.f); v1 = fmaxf(v1, 0.f);
                v2 = fmaxf(v2, 0.f); v3 = fmaxf(v3, 0.f);
            }
            *(float2*)&Cp[(size_t)r0 * nb + c]       = make_float2(v0, v1);
            *(float2*)&Cp[(size_t)(r0 + 8) * nb + c] = make_float2(v2, v3);
        }
    }
}

// ---------------------------------------------------------------------------
// Split-K tf32 GEMM, N=1024: parts[z] = A[:, z*Kc:(z+1)*Kc] @ W-slice.
// 64x64 tile, 128 thr (2x2 warps, 32x32 each), K-step 32, double buffer.
// Grid: (16, 16, nsplit). No bias (applied in reduce).
// ---------------------------------------------------------------------------
__global__ __launch_bounds__(128, 4)
void gemm_sk(const float* __restrict__ A, const float* __restrict__ W,
             float* __restrict__ parts, int lda, int Kc)
{
    constexpr int ASTR = 36, BSTR = 72;
    constexpr int ASZ = 64 * ASTR, BSZ = 32 * BSTR, STG = ASZ + BSZ;
    __shared__ uint32_t smg[2 * STG];

    const int z = blockIdx.z;
    const float* Az = A + (size_t)z * Kc;
    const float* Wz = W + (size_t)z * Kc * 1024;
    float* Cp = parts + (size_t)z * MEG;

    const int t = threadIdx.x;
    const int lane = t & 31, w = t >> 5;
    const int g = lane >> 2, cc = lane & 3;
    const int wm = w >> 1, wn = w & 1;
    const int row0 = blockIdx.y * 64;
    const int col0 = blockIdx.x * 64;

    const int ar = t >> 3, ac = (t & 7) << 2;
    const int bk = t >> 4, bc = (t & 15) << 2;

    float4 aR[4], bR[4];
    auto loadAB = [&](int k0) {
#pragma unroll
        for (int i = 0; i < 4; i++)
            aR[i] = *(const float4*)&Az[(size_t)(row0 + ar + i * 16) * lda + k0 + ac];
#pragma unroll
        for (int i = 0; i < 4; i++)
            bR[i] = *(const float4*)&Wz[(size_t)(k0 + bk + i * 8) * 1024 + col0 + bc];
    };
    auto storeAB = [&](int p) {
        uint32_t* as_ = smg + p * STG;
        uint32_t* bs_ = smg + p * STG + ASZ;
#pragma unroll
        for (int i = 0; i < 4; i++)
            *(uint4*)&as_[(ar + i * 16) * ASTR + ac] = cvt4(aR[i]);
#pragma unroll
        for (int i = 0; i < 4; i++)
            *(uint4*)&bs_[(bk + i * 8) * BSTR + bc] = cvt4(bR[i]);
    };

    float acc[2][4][4] = {};
    const int NK = Kc >> 5;
    loadAB(0);
    storeAB(0);
    if (NK > 1) loadAB(32);
    __syncthreads();

    for (int it = 0; it < NK; it++) {
        const int p = it & 1;
        if (it + 1 < NK) storeAB(p ^ 1);
        if (it + 2 < NK) loadAB((it + 2) << 5);

        const uint32_t* as_ = smg + p * STG;
        const uint32_t* bs_ = smg + p * STG + ASZ;
        uint32_t af[2][4], bf[4][2];
#pragma unroll
        for (int ks = 0; ks < 4; ks++) {
            const int kb = ks * 8 + cc;
#pragma unroll
            for (int mi = 0; mi < 2; mi++) {
                const int mb = wm * 32 + mi * 16;
                af[mi][0] = as_[(mb + g) * ASTR + kb];
                af[mi][1] = as_[(mb + g + 8) * ASTR + kb];
                af[mi][2] = as_[(mb + g) * ASTR + kb + 4];
                af[mi][3] = as_[(mb + g + 8) * ASTR + kb + 4];
            }
#pragma unroll
            for (int nj = 0; nj < 4; nj++) {
                const int nbase = wn * 32 + nj * 8;
                bf[nj][0] = bs_[kb * BSTR + nbase + g];
                bf[nj][1] = bs_[(kb + 4) * BSTR + nbase + g];
            }
#pragma unroll
            for (int mi = 0; mi < 2; mi++)
#pragma unroll
                for (int nj = 0; nj < 4; nj++)
                    mma8(acc[mi][nj], af[mi], bf[nj]);
        }
        __syncthreads();
    }

#pragma unroll
    for (int mi = 0; mi < 2; mi++) {
        const int r0 = row0 + wm * 32 + mi * 16 + g;
#pragma unroll
        for (int nj = 0; nj < 4; nj++) {
            const int c = col0 + wn * 32 + nj * 8 + 2 * cc;
            *(float2*)&Cp[(size_t)r0 * 1024 + c] =
                make_float2(acc[mi][nj][0], acc[mi][nj][1]);
            *(float2*)&Cp[(size_t)(r0 + 8) * 1024 + c] =
                make_float2(acc[mi][nj][2], acc[mi][nj][3]);
        }
    }
}

// ---------------------------------------------------------------------------
// Reduce split-K partials + bias. 1M elems, N=1024.
// ---------------------------------------------------------------------------
__global__ __launch_bounds__(256)
void reduce_bias(const float* __restrict__ parts, int nparts,
                 const float* __restrict__ bias, float* __restrict__ C)
{
    const size_t idx = ((size_t)blockIdx.x * 256 + threadIdx.x) * 4;
    float4 s = *(const float4*)&parts[idx];
    for (int p = 1; p < nparts; p++) {
        float4 q = *(const float4*)&parts[p * MEG + idx];
        s.x += q.x; s.y += q.y; s.z += q.z; s.w += q.w;
    }
    const int col = (int)(idx & 1023);
    float4 bv = *(const float4*)&bias[col];
    s.x += bv.x; s.y += bv.y; s.z += bv.z; s.w += bv.w;
    *(float4*)&C[idx] = s;
}

// ---------------------------------------------------------------------------
// Scores + mask + softmax (tf32 mma for Q.K^T, softmax in smem).
// Block: 64 q-rows x 512 keys; grid (S/64, B*H); 256 threads.
// ---------------------------------------------------------------------------
__global__ __launch_bounds__(256)
void attn_scores_tf32(const float* __restrict__ qf,
                      const float* __restrict__ kf,
                      const int* __restrict__ mask,
                      int causal,
                      float* __restrict__ attn)
{
    extern __shared__ float smemf[];
    uint32_t* Qs = (uint32_t*)smemf;        // 64*68
    uint32_t* Ks = Qs + 64 * 68;            // 64*68
    float* Ssm = smemf + 2 * 64 * 68;       // 64*516

    const int bh = blockIdx.y, b = bh >> 4, h = bh & 15;
    const int q0 = blockIdx.x * 64;
    const int t = threadIdx.x, lane = t & 31, w = t >> 5;
    const int g = lane >> 2, cc = lane & 3;
    const int qslot = w & 3, kslot = w >> 2;

#pragma unroll
    for (int i = 0; i < 4; i++) {
        const int idx = t + i * 256;
        const int r = idx >> 4, cq = (idx & 15) << 2;
        float4 v = *(const float4*)&qf[(size_t)(b * SS + q0 + r) * DD + h * DKK + cq];
        *(uint4*)&Qs[r * 68 + cq] = cvt4(v);
    }

    for (int kt = 0; kt < 8; kt++) {
        __syncthreads();
#pragma unroll
        for (int i = 0; i < 4; i++) {
            const int idx = t + i * 256;
            const int r = idx >> 4, cq = (idx & 15) << 2;
            float4 v = *(const float4*)&kf[(size_t)(b * SS + kt * 64 + r) * DD + h * DKK + cq];
            *(uint4*)&Ks[r * 68 + cq] = cvt4(v);
        }
        __syncthreads();

        float acc[4][4] = {};
        uint32_t af[4];
#pragma unroll
        for (int ks = 0; ks < 8; ks++) {
            const int kb = ks * 8 + cc;
            const int mb = qslot * 16;
            af[0] = Qs[(mb + g) * 68 + kb];
            af[1] = Qs[(mb + g + 8) * 68 + kb];
            af[2] = Qs[(mb + g) * 68 + kb + 4];
            af[3] = Qs[(mb + g + 8) * 68 + kb + 4];
#pragma unroll
            for (int nj = 0; nj < 4; nj++) {
                const int nbase = kslot * 32 + nj * 8;
                uint32_t bf[2];
                bf[0] = Ks[(nbase + g) * 68 + kb];
                bf[1] = Ks[(nbase + g) * 68 + kb + 4];
                mma8(acc[nj], af, bf);
            }
        }
#pragma unroll
        for (int nj = 0; nj < 4; nj++) {
            const int colb = kt * 64 + kslot * 32 + nj * 8 + 2 * cc;
            const int rr = qslot * 16 + g;
            *(float2*)&Ssm[rr * 516 + colb]       = make_float2(acc[nj][0], acc[nj][1]);
            *(float2*)&Ssm[(rr + 8) * 516 + colb] = make_float2(acc[nj][2], acc[nj][3]);
        }
    }
    __syncthreads();

    for (int i = 0; i < 8; i++) {
        const int rloc = w * 8 + i;
        const int q = q0 + rloc;
        float vals[16];
        float mx = -1e30f;
#pragma unroll
        for (int j = 0; j < 16; j++) {
            const int col = lane + j * 32;
            float v = Ssm[rloc * 516 + col] * INV_SCALE;
            const int m = causal ? mask[((size_t)b * SS + q) * SS + col]
                                 : mask[(size_t)b * SS + col];
            if (m == 0) v = -1e9f;
            vals[j] = v;
            mx = fmaxf(mx, v);
        }
#pragma unroll
        for (int o = 16; o > 0; o >>= 1)
            mx = fmaxf(mx, __shfl_xor_sync(0xffffffffu, mx, o));
        float sum = 0.0f;
#pragma unroll
        for (int j = 0; j < 16; j++) {
            vals[j] = expf(vals[j] - mx);
            sum += vals[j];
        }
#pragma unroll
        for (int o = 16; o > 0; o >>= 1)
            sum += __shfl_xor_sync(0xffffffffu, sum, o);
        const float inv = 1.0f / sum;
        float* dst = attn + ((size_t)bh * SS + q) * SS;
#pragma unroll
        for (int j = 0; j < 16; j++)
            dst[lane + j * 32] = vals[j] * inv;
    }
}

// ---------------------------------------------------------------------------
// Context: ctx[q,d] = sum_k attn[q,k] * V[k,d], tf32 mma.
// ---------------------------------------------------------------------------
__global__ __launch_bounds__(256)
void attn_ctx_tf32(const float* __restrict__ attn,
                   const float* __restrict__ vf,
                   float* __restrict__ ctx)
{
    __shared__ uint32_t As[64 * 20];
    __shared__ uint32_t Vs[16 * 72];
    const int bh = blockIdx.y, b = bh >> 4, h = bh & 15;
    const int q0 = blockIdx.x * 64;
    const int t = threadIdx.x, lane = t & 31, w = t >> 5;
    const int g = lane >> 2, cc = lane & 3;
    const int qslot = w & 3, dslot = w >> 2;
    const float* Ap = attn + (size_t)bh * SS * SS;
    const float* Vp = vf + (size_t)b * SS * DD + h * DKK;

    float acc[4][4] = {};
    for (int k0 = 0; k0 < SS; k0 += 16) {
        {
            const int r = t >> 2, ak = (t & 3) << 2;
            float4 v = *(const float4*)&Ap[(size_t)(q0 + r) * SS + k0 + ak];
            *(uint4*)&As[r * 20 + ak] = cvt4(v);
        }
        {
            const int kr = t >> 4, cq = (t & 15) << 2;
            float4 v = *(const float4*)&Vp[(size_t)(k0 + kr) * DD + cq];
            *(uint4*)&Vs[kr * 72 + cq] = cvt4(v);
        }
        __syncthreads();

        uint32_t af[4], bf[2];
#pragma unroll
        for (int ks = 0; ks < 2; ks++) {
            const int kb = ks * 8 + cc;
            const int mb = qslot * 16;
            af[0] = As[(mb + g) * 20 + kb];
            af[1] = As[(mb + g + 8) * 20 + kb];
            af[2] = As[(mb + g) * 20 + kb + 4];
            af[3] = As[(mb + g + 8) * 20 + kb + 4];
#pragma unroll
            for (int nj = 0; nj < 4; nj++) {
                const int nbase = dslot * 32 + nj * 8;
                bf[0] = Vs[kb * 72 + nbase + g];
                bf[1] = Vs[(kb + 4) * 72 + nbase + g];
                mma8(acc[nj], af, bf);
            }
        }
        __syncthreads();
    }

    float* Cp = ctx + (size_t)b * SS * DD + h * DKK;
#pragma unroll
    for (int nj = 0; nj < 4; nj++) {
        const int c = dslot * 32 + nj * 8 + 2 * cc;
        const int r = q0 + qslot * 16 + g;
        *(float2*)&Cp[(size_t)r * DD + c]       = make_float2(acc[nj][0], acc[nj][1]);
        *(float2*)&Cp[(size_t)(r + 8) * DD + c] = make_float2(acc[nj][2], acc[nj][3]);
    }
}

// ---------------------------------------------------------------------------
// y = LayerNorm(x + a). a may be nullptr. One block per row (D=1024).
// ---------------------------------------------------------------------------
__global__ __launch_bounds__(256)
void add_ln_kernel(const float* __restrict__ x,
                   const float* __restrict__ a,
                   const float* __restrict__ g,
                   const float* __restrict__ bt,
                   float* __restrict__ y)
{
    const int row = blockIdx.x;
    const int t = threadIdx.x;
    __shared__ float red[256];

    float v[4];
#pragma unroll
    for (int i = 0; i < 4; i++) {
        const int c = t + i * 256;
        float vv = x[(size_t)row * DD + c];
        if (a) vv += a[(size_t)row * DD + c];
        v[i] = vv;
    }
    float s = v[0] + v[1] + v[2] + v[3];
    red[t] = s;
    __syncthreads();
    for (int o = 128; o > 0; o >>= 1) {
        if (t < o) red[t] += red[t + o];
        __syncthreads();
    }
    const float mean = red[0] * (1.0f / DD);
    __syncthreads();

    float s2 = 0.0f;
#pragma unroll
    for (int i = 0; i < 4; i++) {
        const float d = v[i] - mean;
        s2 += d * d;
    }
    red[t] = s2;
    __syncthreads();
    for (int o = 128; o > 0; o >>= 1) {
        if (t < o) red[t] += red[t + o];
        __syncthreads();
    }
    const float var = red[0] * (1.0f / DD);
    const float inv = rsqrtf(var + EPSF);

#pragma unroll
    for (int i = 0; i < 4; i++) {
        const int c = t + i * 256;
        y[(size_t)row * DD + c] = g[c] * (v[i] - mean) * inv + bt[c];
    }
}

// ---------------------------------------------------------------------------
// Host orchestration
// ---------------------------------------------------------------------------
extern "C" void kernel_launch(void* const* d_in, const int* in_sizes, int n_in,
                              void* d_out, int out_size)
{
    const float* src     = (const float*)d_in[0];
    const float* tgt     = (const float*)d_in[1];
    const float* enc_W   = (const float*)d_in[2];
    const float* enc_b   = (const float*)d_in[3];
    const float* enc_W1  = (const float*)d_in[4];
    const float* enc_b1  = (const float*)d_in[5];
    const float* enc_W2  = (const float*)d_in[6];
    const float* enc_b2  = (const float*)d_in[7];
    const float* enc_lng = (const float*)d_in[8];
    const float* enc_lnb = (const float*)d_in[9];
    const float* enc_fg  = (const float*)d_in[10];
    const float* enc_fb  = (const float*)d_in[11];
    const float* dsW     = (const float*)d_in[12];
    const float* dsb     = (const float*)d_in[13];
    const float* dcW     = (const float*)d_in[14];
    const float* dcb     = (const float*)d_in[15];
    const float* dW1     = (const float*)d_in[16];
    const float* db1     = (const float*)d_in[17];
    const float* dW2     = (const float*)d_in[18];
    const float* db2     = (const float*)d_in[19];
    const float* dlng    = (const float*)d_in[20];
    const float* dlnb    = (const float*)d_in[21];
    const float* dfg     = (const float*)d_in[22];
    const float* dfb     = (const float*)d_in[23];
    const int*   src_mask = (const int*)d_in[24];
    const int*   tgt_mask = (const int*)d_in[25];
    float* out = (float*)d_out;

    float* scratch = nullptr;
    cudaGetSymbolAddress((void**)&scratch, g_scratch);

    float* X    = scratch + 0 * MEG;
    float* X2   = scratch + 1 * MEG;
    float* Qb   = scratch + 2 * MEG;   // Q/K/V contiguous for fused QKV gemm
    float* Kb   = scratch + 3 * MEG;
    float* Vb   = scratch + 4 * MEG;
    float* Ab   = scratch + 5 * MEG;
    float* H1   = scratch + 6 * MEG;   // 4M floats
    float* ATT  = scratch + 10 * MEG;  // 8M floats (fallback only)
    float* ENC  = scratch + 18 * MEG;
    float* PRT  = scratch + 19 * MEG;  // 4M floats (split-K partials)
    float* CK   = scratch + 23 * MEG;  // 4M floats (cross K, all layers)
    float* CV   = scratch + 27 * MEG;  // 4M floats (cross V, all layers)

    const size_t SLAB      = (size_t)BB * HH * SS * SS;
    const size_t OFF_ENC   = (size_t)BB * SS * DD;
    const size_t OFF_SELF  = OFF_ENC + (size_t)LL * SLAB;
    const size_t OFF_CROSS = OFF_SELF + (size_t)LL * SLAB;
    const size_t TOTAL     = OFF_CROSS + (size_t)LL * SLAB;
    const bool full = ((size_t)out_size >= TOTAL);

    const int SM_A = 2 * (64 * 36 + 32 * 136) * 4;  // 53248 B (TN=128)
    const int SM_B = 2 * (64 * 36 + 32 * 72) * 4;   // 36864 B (TN=64)
    auto gemmA = gemm_tf32<64, 128, 2, 4>;
    auto gemmB = gemm_tf32<64, 64, 4, 2>;
    cudaFuncSetAttribute(gemmA, cudaFuncAttributeMaxDynamicSharedMemorySize, SM_A);
    cudaFuncSetAttribute(gemmB, cudaFuncAttributeMaxDynamicSharedMemorySize, SM_B);

    const size_t SC_SMEM = (size_t)(2 * 64 * 68 + 64 * 516) * sizeof(float);
    cudaFuncSetAttribute(attn_scores_tf32,
                         cudaFuncAttributeMaxDynamicSharedMemorySize, (int)SC_SMEM);

    dim3 gQKV(3072 / 128, MROWS / 64);   // 384 CTAs (config A)
    dim3 gKVB(4096 / 128, MROWS / 64);   // 512 CTAs (batched cross K or V)
    dim3 gF1(DFFF / 128, MROWS / 64);    // 512 CTAs (config A)
    dim3 gO(DD / 64, MROWS / 64);        // 256 CTAs (config B)
    dim3 gSK4(16, 16, 4);                // 1024 CTAs (FFN2 split-K)
    dim3 gS(SS / 64, BB * HH);
    dim3 gC(SS / 64, BB * HH);
    const long long WS = (long long)DD * DD;
    const long long CS = (long long)MEG;

    // ------------------------- Encoder -------------------------
    const float* cur = src;
    for (int l = 0; l < LL; l++) {
        const float* W  = enc_W + (size_t)l * 4 * DD * DD;
        const float* bb = enc_b + (size_t)l * 4 * DD;
        gemmA<<<gQKV, 256, SM_A>>>(cur, W, bb, Qb, DD, DD, 0, WS, DD, CS);
        float* adst = full ? out + OFF_ENC + (size_t)l * SLAB : ATT;
        attn_scores_tf32<<<gS, 256, SC_SMEM>>>(Qb, Kb, src_mask, 0, adst);
        attn_ctx_tf32<<<gC, 256>>>(adst, Vb, Qb);
        gemmB<<<gO, 256, SM_B>>>(Qb, W + 3 * DD * DD, bb + 3 * DD, Ab, DD, DD, 0, 0, 0, 0);
        add_ln_kernel<<<MROWS, 256>>>(cur, Ab, enc_lng + (size_t)l * 2 * DD,
                                      enc_lnb + (size_t)l * 2 * DD, X2);
        gemmA<<<gF1, 256, SM_A>>>(X2, enc_W1 + (size_t)l * DD * DFFF,
                                  enc_b1 + (size_t)l * DFFF, H1, DD, DFFF, 1, 0, 0, 0);
        gemm_sk<<<gSK4, 128>>>(H1, enc_W2 + (size_t)l * DFFF * DD, PRT, DFFF, 1024);
        reduce_bias<<<1024, 256>>>(PRT, 4, enc_b2 + (size_t)l * DD, Ab);
        add_ln_kernel<<<MROWS, 256>>>(X2, Ab, enc_lng + (size_t)l * 2 * DD + DD,
                                      enc_lnb + (size_t)l * 2 * DD + DD, X);
        cur = X;
    }
    add_ln_kernel<<<MROWS, 256>>>(cur, nullptr, enc_fg, enc_fb, ENC);

    // Batched cross-attention K/V for all decoder layers (blk = layer)
    gemmA<<<gKVB, 256, SM_A>>>(ENC, dcW + (size_t)DD * DD, dcb + DD, CK,
                               DD, DD, 0, 4LL * DD * DD, 4LL * DD, CS);
    gemmA<<<gKVB, 256, SM_A>>>(ENC, dcW + 2 * (size_t)DD * DD, dcb + 2 * DD, CV,
                               DD, DD, 0, 4LL * DD * DD, 4LL * DD, CS);

    // ------------------------- Decoder -------------------------
    cur = tgt;
    for (int l = 0; l < LL; l++) {
        // self-attention (causal)
        const float* Ws = dsW + (size_t)l * 4 * DD * DD;
        const float* bs = dsb + (size_t)l * 4 * DD;
        gemmA<<<gQKV, 256, SM_A>>>(cur, Ws, bs, Qb, DD, DD, 0, WS, DD, CS);
        float* adst = full ? out + OFF_SELF + (size_t)l * SLAB : ATT;
        attn_scores_tf32<<<gS, 256, SC_SMEM>>>(Qb, Kb, tgt_mask, 1, adst);
        attn_ctx_tf32<<<gC, 256>>>(adst, Vb, Qb);
        gemmB<<<gO, 256, SM_B>>>(Qb, Ws + 3 * DD * DD, bs + 3 * DD, Ab, DD, DD, 0, 0, 0, 0);
        add_ln_kernel<<<MROWS, 256>>>(cur, Ab, dlng + (size_t)l * 3 * DD,
                                      dlnb + (size_t)l * 3 * DD, X);

        // cross-attention (K/V precomputed, batched)
        const float* Wc = dcW + (size_t)l * 4 * DD * DD;
        const float* bc = dcb + (size_t)l * 4 * DD;
        gemmB<<<gO, 256, SM_B>>>(X, Wc, bc, Qb, DD, DD, 0, 0, 0, 0);
        adst = full ? out + OFF_CROSS + (size_t)l * SLAB : ATT;
        attn_scores_tf32<<<gS, 256, SC_SMEM>>>(Qb, CK + (size_t)l * MEG, src_mask, 0, adst);
        attn_ctx_tf32<<<gC, 256>>>(adst, CV + (size_t)l * MEG, Qb);
        gemmB<<<gO, 256, SM_B>>>(Qb, Wc + 3 * DD * DD, bc + 3 * DD, Ab, DD, DD, 0, 0, 0, 0);
        add_ln_kernel<<<MROWS, 256>>>(X, Ab, dlng + (size_t)l * 3 * DD + DD,
                                      dlnb + (size_t)l * 3 * DD + DD, X2);

        // FFN
        gemmA<<<gF1, 256, SM_A>>>(X2, dW1 + (size_t)l * DD * DFFF,
                                  db1 + (size_t)l * DFFF, H1, DD, DFFF, 1, 0, 0, 0);
        gemm_sk<<<gSK4, 128>>>(H1, dW2 + (size_t)l * DFFF * DD, PRT, DFFF, 1024);
        reduce_bias<<<1024, 256>>>(PRT, 4, db2 + (size_t)l * DD, Ab);
        add_ln_kernel<<<MROWS, 256>>>(X2, Ab, dlng + (size_t)l * 3 * DD + 2 * DD,
                                      dlnb + (size_t)l * 3 * DD + 2 * DD, X);
        cur = X;
    }
    add_ln_kernel<<<MROWS, 256>>>(cur, nullptr, dfg, dfb, out);
}

// round 7
// speedup vs baseline: 1.5221x; 1.0335x over previous
#include <cuda_runtime.h>
#include <cuda_bf16.h>
#include <cstdint>
#include <cstddef>

// ---------------------------------------------------------------------------
// Transformer forward (encoder-decoder), tf32 tensor cores, R7:
// R6 + 128-thread 64x64 GEMM (2x2 warps, 32x32 warp tiles) for D-output GEMMs.
// ---------------------------------------------------------------------------

#define BB   2
#define SS   512
#define DD   1024
#define HH   16
#define DKK  64
#define DFFF 4096
#define LL   4
#define MROWS (BB*SS)          // 1024
#define EPSF 1e-5f
#define INV_SCALE 0.125f       // 1/sqrt(DK)

static const size_t MEG = 1u << 20;
__device__ __align__(16) float g_scratch[31u * (1u << 20)];   // 124 MB

// ---------------------------------------------------------------------------
// tf32 helpers
// ---------------------------------------------------------------------------
__device__ __forceinline__ uint32_t f2t(float x) {
    uint32_t r; asm("cvt.rna.tf32.f32 %0, %1;" : "=r"(r) : "f"(x)); return r;
}
__device__ __forceinline__ void mma8(float* c, const uint32_t* a, const uint32_t* b) {
    asm volatile(
        "mma.sync.aligned.m16n8k8.row.col.f32.tf32.tf32.f32 "
        "{%0,%1,%2,%3}, {%4,%5,%6,%7}, {%8,%9}, {%0,%1,%2,%3};\n"
        : "+f"(c[0]), "+f"(c[1]), "+f"(c[2]), "+f"(c[3])
        : "r"(a[0]), "r"(a[1]), "r"(a[2]), "r"(a[3]), "r"(b[0]), "r"(b[1]));
}
__device__ __forceinline__ uint4 cvt4(float4 v) {
    uint4 u; u.x = f2t(v.x); u.y = f2t(v.y); u.z = f2t(v.z); u.w = f2t(v.w);
    return u;
}

// ---------------------------------------------------------------------------
// Wide tf32 GEMM (64x128 tile, 256 thr, 8 warps 2x4, 32x32 warp tiles).
// Blocked-N support: blk = colg/nb; W += blk*wstride; bias += blk*bstride;
// C += blk*cstride; inner row strides of W and C are nb.
// K-step 32, double buffer. Grid: (totalN/128, M/64). Dyn smem 53248 B.
// ---------------------------------------------------------------------------
__global__ __launch_bounds__(256, 2)
void gemm_wide(const float* __restrict__ A, const float* __restrict__ W,
               const float* __restrict__ bias, float* __restrict__ C,
               int K, int nb, int relu,
               long long wstride, long long bstride, long long cstride)
{
    constexpr int ASTR = 36, BSTR = 136;
    constexpr int ASZ = 64 * ASTR, BSZ = 32 * BSTR, STG = ASZ + BSZ;
    extern __shared__ uint32_t smg[];

    const int t = threadIdx.x;
    const int lane = t & 31, w = t >> 5;
    const int g = lane >> 2, cc = lane & 3;
    const int wm = w >> 2, wn = w & 3;
    const int row0 = blockIdx.y * 64;
    const int colg = blockIdx.x * 128;
    const int blk  = colg / nb;
    const int col0 = colg - blk * nb;
    const float* Wp = W + (size_t)blk * (size_t)wstride;
    const float* bp = bias + (size_t)blk * (size_t)bstride;
    float* Cp = C + (size_t)blk * (size_t)cstride;

    const int ar = t >> 3, ac = (t & 7) << 2;
    const int bk0 = t >> 5, bc = (t & 31) << 2;

    float4 aR[2], bR[4];
    auto loadAB = [&](int k0) {
#pragma unroll
        for (int i = 0; i < 2; i++)
            aR[i] = *(const float4*)&A[(size_t)(row0 + ar + i * 32) * K + k0 + ac];
#pragma unroll
        for (int i = 0; i < 4; i++)
            bR[i] = *(const float4*)&Wp[(size_t)(k0 + bk0 + i * 8) * nb + col0 + bc];
    };
    auto storeAB = [&](int p) {
        uint32_t* as_ = smg + p * STG;
        uint32_t* bs_ = smg + p * STG + ASZ;
#pragma unroll
        for (int i = 0; i < 2; i++)
            *(uint4*)&as_[(ar + i * 32) * ASTR + ac] = cvt4(aR[i]);
#pragma unroll
        for (int i = 0; i < 4; i++)
            *(uint4*)&bs_[(bk0 + i * 8) * BSTR + bc] = cvt4(bR[i]);
    };

    float acc[2][4][4] = {};
    const int NK = K >> 5;
    loadAB(0);
    storeAB(0);
    if (NK > 1) loadAB(32);
    __syncthreads();

    for (int it = 0; it < NK; it++) {
        const int p = it & 1;
        if (it + 1 < NK) storeAB(p ^ 1);
        if (it + 2 < NK) loadAB((it + 2) << 5);

        const uint32_t* as_ = smg + p * STG;
        const uint32_t* bs_ = smg + p * STG + ASZ;
        uint32_t af[2][4], bf[4][2];
#pragma unroll
        for (int ks = 0; ks < 4; ks++) {
            const int kb = ks * 8 + cc;
#pragma unroll
            for (int mi = 0; mi < 2; mi++) {
                const int mb = wm * 32 + mi * 16;
                af[mi][0] = as_[(mb + g) * ASTR + kb];
                af[mi][1] = as_[(mb + g + 8) * ASTR + kb];
                af[mi][2] = as_[(mb + g) * ASTR + kb + 4];
                af[mi][3] = as_[(mb + g + 8) * ASTR + kb + 4];
            }
#pragma unroll
            for (int nj = 0; nj < 4; nj++) {
                const int nbase = wn * 32 + nj * 8;
                bf[nj][0] = bs_[kb * BSTR + nbase + g];
                bf[nj][1] = bs_[(kb + 4) * BSTR + nbase + g];
            }
#pragma unroll
            for (int mi = 0; mi < 2; mi++)
#pragma unroll
                for (int nj = 0; nj < 4; nj++)
                    mma8(acc[mi][nj], af[mi], bf[nj]);
        }
        __syncthreads();
    }

#pragma unroll
    for (int mi = 0; mi < 2; mi++) {
        const int r0 = row0 + wm * 32 + mi * 16 + g;
#pragma unroll
        for (int nj = 0; nj < 4; nj++) {
            const int c = col0 + wn * 32 + nj * 8 + 2 * cc;
            const float b0v = bp[c], b1v = bp[c + 1];
            float v0 = acc[mi][nj][0] + b0v, v1 = acc[mi][nj][1] + b1v;
            float v2 = acc[mi][nj][2] + b0v, v3 = acc[mi][nj][3] + b1v;
            if (relu) {
                v0 = fmaxf(v0, 0.f); v1 = fmaxf(v1, 0.f);
                v2 = fmaxf(v2, 0.f); v3 = fmaxf(v3, 0.f);
            }
            *(float2*)&Cp[(size_t)r0 * nb + c]       = make_float2(v0, v1);
            *(float2*)&Cp[(size_t)(r0 + 8) * nb + c] = make_float2(v2, v3);
        }
    }
}

// ---------------------------------------------------------------------------
// 128-thread 64x64 GEMM with fused bias: C = A[M,1024] @ W[1024,1024] + bias.
// 2x2 warps, 32x32 warp tiles (2 LDS/MMA), K-step 32, double buffer.
// Grid: (16, 16). Static smem 36864 B -> multiple CTAs/SM.
// ---------------------------------------------------------------------------
__global__ __launch_bounds__(128, 4)
void gemm64(const float* __restrict__ A, const float* __restrict__ W,
            const float* __restrict__ bias, float* __restrict__ C)
{
    constexpr int ASTR = 36, BSTR = 72;
    constexpr int ASZ = 64 * ASTR, BSZ = 32 * BSTR, STG = ASZ + BSZ;
    __shared__ uint32_t smg[2 * STG];

    const int t = threadIdx.x;
    const int lane = t & 31, w = t >> 5;
    const int g = lane >> 2, cc = lane & 3;
    const int wm = w >> 1, wn = w & 1;
    const int row0 = blockIdx.y * 64;
    const int col0 = blockIdx.x * 64;

    const int ar = t >> 3, ac = (t & 7) << 2;    // A: 64x32
    const int bk = t >> 4, bc = (t & 15) << 2;   // B: 32x64

    float4 aR[4], bR[4];
    auto loadAB = [&](int k0) {
#pragma unroll
        for (int i = 0; i < 4; i++)
            aR[i] = *(const float4*)&A[(size_t)(row0 + ar + i * 16) * 1024 + k0 + ac];
#pragma unroll
        for (int i = 0; i < 4; i++)
            bR[i] = *(const float4*)&W[(size_t)(k0 + bk + i * 8) * 1024 + col0 + bc];
    };
    auto storeAB = [&](int p) {
        uint32_t* as_ = smg + p * STG;
        uint32_t* bs_ = smg + p * STG + ASZ;
#pragma unroll
        for (int i = 0; i < 4; i++)
            *(uint4*)&as_[(ar + i * 16) * ASTR + ac] = cvt4(aR[i]);
#pragma unroll
        for (int i = 0; i < 4; i++)
            *(uint4*)&bs_[(bk + i * 8) * BSTR + bc] = cvt4(bR[i]);
    };

    float acc[2][4][4] = {};
    const int NK = 32;   // 1024/32
    loadAB(0);
    storeAB(0);
    loadAB(32);
    __syncthreads();

    for (int it = 0; it < NK; it++) {
        const int p = it & 1;
        if (it + 1 < NK) storeAB(p ^ 1);
        if (it + 2 < NK) loadAB((it + 2) << 5);

        const uint32_t* as_ = smg + p * STG;
        const uint32_t* bs_ = smg + p * STG + ASZ;
        uint32_t af[2][4], bf[4][2];
#pragma unroll
        for (int ks = 0; ks < 4; ks++) {
            const int kb = ks * 8 + cc;
#pragma unroll
            for (int mi = 0; mi < 2; mi++) {
                const int mb = wm * 32 + mi * 16;
                af[mi][0] = as_[(mb + g) * ASTR + kb];
                af[mi][1] = as_[(mb + g + 8) * ASTR + kb];
                af[mi][2] = as_[(mb + g) * ASTR + kb + 4];
                af[mi][3] = as_[(mb + g + 8) * ASTR + kb + 4];
            }
#pragma unroll
            for (int nj = 0; nj < 4; nj++) {
                const int nbase = wn * 32 + nj * 8;
                bf[nj][0] = bs_[kb * BSTR + nbase + g];
                bf[nj][1] = bs_[(kb + 4) * BSTR + nbase + g];
            }
#pragma unroll
            for (int mi = 0; mi < 2; mi++)
#pragma unroll
                for (int nj = 0; nj < 4; nj++)
                    mma8(acc[mi][nj], af[mi], bf[nj]);
        }
        __syncthreads();
    }

#pragma unroll
    for (int mi = 0; mi < 2; mi++) {
        const int r0 = row0 + wm * 32 + mi * 16 + g;
#pragma unroll
        for (int nj = 0; nj < 4; nj++) {
            const int c = col0 + wn * 32 + nj * 8 + 2 * cc;
            const float b0v = bias[c], b1v = bias[c + 1];
            *(float2*)&C[(size_t)r0 * 1024 + c] =
                make_float2(acc[mi][nj][0] + b0v, acc[mi][nj][1] + b1v);
            *(float2*)&C[(size_t)(r0 + 8) * 1024 + c] =
                make_float2(acc[mi][nj][2] + b0v, acc[mi][nj][3] + b1v);
        }
    }
}

// ---------------------------------------------------------------------------
// Split-K tf32 GEMM, N=1024: parts[z] = A[:, z*Kc:(z+1)*Kc] @ W-slice.
// Grid: (16, 16, nsplit).
// ---------------------------------------------------------------------------
__global__ __launch_bounds__(128, 4)
void gemm_sk(const float* __restrict__ A, const float* __restrict__ W,
             float* __restrict__ parts, int lda, int Kc)
{
    constexpr int ASTR = 36, BSTR = 72;
    constexpr int ASZ = 64 * ASTR, BSZ = 32 * BSTR, STG = ASZ + BSZ;
    __shared__ uint32_t smg[2 * STG];

    const int z = blockIdx.z;
    const float* Az = A + (size_t)z * Kc;
    const float* Wz = W + (size_t)z * Kc * 1024;
    float* Cp = parts + (size_t)z * MEG;

    const int t = threadIdx.x;
    const int lane = t & 31, w = t >> 5;
    const int g = lane >> 2, cc = lane & 3;
    const int wm = w >> 1, wn = w & 1;
    const int row0 = blockIdx.y * 64;
    const int col0 = blockIdx.x * 64;

    const int ar = t >> 3, ac = (t & 7) << 2;
    const int bk = t >> 4, bc = (t & 15) << 2;

    float4 aR[4], bR[4];
    auto loadAB = [&](int k0) {
#pragma unroll
        for (int i = 0; i < 4; i++)
            aR[i] = *(const float4*)&Az[(size_t)(row0 + ar + i * 16) * lda + k0 + ac];
#pragma unroll
        for (int i = 0; i < 4; i++)
            bR[i] = *(const float4*)&Wz[(size_t)(k0 + bk + i * 8) * 1024 + col0 + bc];
    };
    auto storeAB = [&](int p) {
        uint32_t* as_ = smg + p * STG;
        uint32_t* bs_ = smg + p * STG + ASZ;
#pragma unroll
        for (int i = 0; i < 4; i++)
            *(uint4*)&as_[(ar + i * 16) * ASTR + ac] = cvt4(aR[i]);
#pragma unroll
        for (int i = 0; i < 4; i++)
            *(uint4*)&bs_[(bk + i * 8) * BSTR + bc] = cvt4(bR[i]);
    };

    float acc[2][4][4] = {};
    const int NK = Kc >> 5;
    loadAB(0);
    storeAB(0);
    if (NK > 1) loadAB(32);
    __syncthreads();

    for (int it = 0; it < NK; it++) {
        const int p = it & 1;
        if (it + 1 < NK) storeAB(p ^ 1);
        if (it + 2 < NK) loadAB((it + 2) << 5);

        const uint32_t* as_ = smg + p * STG;
        const uint32_t* bs_ = smg + p * STG + ASZ;
        uint32_t af[2][4], bf[4][2];
#pragma unroll
        for (int ks = 0; ks < 4; ks++) {
            const int kb = ks * 8 + cc;
#pragma unroll
            for (int mi = 0; mi < 2; mi++) {
                const int mb = wm * 32 + mi * 16;
                af[mi][0] = as_[(mb + g) * ASTR + kb];
                af[mi][1] = as_[(mb + g + 8) * ASTR + kb];
                af[mi][2] = as_[(mb + g) * ASTR + kb + 4];
                af[mi][3] = as_[(mb + g + 8) * ASTR + kb + 4];
            }
#pragma unroll
            for (int nj = 0; nj < 4; nj++) {
                const int nbase = wn * 32 + nj * 8;
                bf[nj][0] = bs_[kb * BSTR + nbase + g];
                bf[nj][1] = bs_[(kb + 4) * BSTR + nbase + g];
            }
#pragma unroll
            for (int mi = 0; mi < 2; mi++)
#pragma unroll
                for (int nj = 0; nj < 4; nj++)
                    mma8(acc[mi][nj], af[mi], bf[nj]);
        }
        __syncthreads();
    }

#pragma unroll
    for (int mi = 0; mi < 2; mi++) {
        const int r0 = row0 + wm * 32 + mi * 16 + g;
#pragma unroll
        for (int nj = 0; nj < 4; nj++) {
            const int c = col0 + wn * 32 + nj * 8 + 2 * cc;
            *(float2*)&Cp[(size_t)r0 * 1024 + c] =
                make_float2(acc[mi][nj][0], acc[mi][nj][1]);
            *(float2*)&Cp[(size_t)(r0 + 8) * 1024 + c] =
                make_float2(acc[mi][nj][2], acc[mi][nj][3]);
        }
    }
}

// ---------------------------------------------------------------------------
// Reduce split-K partials + bias. 1M elems, N=1024.
// ---------------------------------------------------------------------------
__global__ __launch_bounds__(256)
void reduce_bias(const float* __restrict__ parts, int nparts,
                 const float* __restrict__ bias, float* __restrict__ C)
{
    const size_t idx = ((size_t)blockIdx.x * 256 + threadIdx.x) * 4;
    float4 s = *(const float4*)&parts[idx];
    for (int p = 1; p < nparts; p++) {
        float4 q = *(const float4*)&parts[p * MEG + idx];
        s.x += q.x; s.y += q.y; s.z += q.z; s.w += q.w;
    }
    const int col = (int)(idx & 1023);
    float4 bv = *(const float4*)&bias[col];
    s.x += bv.x; s.y += bv.y; s.z += bv.z; s.w += bv.w;
    *(float4*)&C[idx] = s;
}

// ---------------------------------------------------------------------------
// Scores + mask + softmax (tf32 mma for Q.K^T, softmax in smem).
// ---------------------------------------------------------------------------
__global__ __launch_bounds__(256)
void attn_scores_tf32(const float* __restrict__ qf,
                      const float* __restrict__ kf,
                      const int* __restrict__ mask,
                      int causal,
                      float* __restrict__ attn)
{
    extern __shared__ float smemf[];
    uint32_t* Qs = (uint32_t*)smemf;        // 64*68
    uint32_t* Ks = Qs + 64 * 68;            // 64*68
    float* Ssm = smemf + 2 * 64 * 68;       // 64*516

    const int bh = blockIdx.y, b = bh >> 4, h = bh & 15;
    const int q0 = blockIdx.x * 64;
    const int t = threadIdx.x, lane = t & 31, w = t >> 5;
    const int g = lane >> 2, cc = lane & 3;
    const int qslot = w & 3, kslot = w >> 2;

#pragma unroll
    for (int i = 0; i < 4; i++) {
        const int idx = t + i * 256;
        const int r = idx >> 4, cq = (idx & 15) << 2;
        float4 v = *(const float4*)&qf[(size_t)(b * SS + q0 + r) * DD + h * DKK + cq];
        *(uint4*)&Qs[r * 68 + cq] = cvt4(v);
    }

    for (int kt = 0; kt < 8; kt++) {
        __syncthreads();
#pragma unroll
        for (int i = 0; i < 4; i++) {
            const int idx = t + i * 256;
            const int r = idx >> 4, cq = (idx & 15) << 2;
            float4 v = *(const float4*)&kf[(size_t)(b * SS + kt * 64 + r) * DD + h * DKK + cq];
            *(uint4*)&Ks[r * 68 + cq] = cvt4(v);
        }
        __syncthreads();

        float acc[4][4] = {};
        uint32_t af[4];
#pragma unroll
        for (int ks = 0; ks < 8; ks++) {
            const int kb = ks * 8 + cc;
            const int mb = qslot * 16;
            af[0] = Qs[(mb + g) * 68 + kb];
            af[1] = Qs[(mb + g + 8) * 68 + kb];
            af[2] = Qs[(mb + g) * 68 + kb + 4];
            af[3] = Qs[(mb + g + 8) * 68 + kb + 4];
#pragma unroll
            for (int nj = 0; nj < 4; nj++) {
                const int nbase = kslot * 32 + nj * 8;
                uint32_t bf[2];
                bf[0] = Ks[(nbase + g) * 68 + kb];
                bf[1] = Ks[(nbase + g) * 68 + kb + 4];
                mma8(acc[nj], af, bf);
            }
        }
#pragma unroll
        for (int nj = 0; nj < 4; nj++) {
            const int colb = kt * 64 + kslot * 32 + nj * 8 + 2 * cc;
            const int rr = qslot * 16 + g;
            *(float2*)&Ssm[rr * 516 + colb]       = make_float2(acc[nj][0], acc[nj][1]);
            *(float2*)&Ssm[(rr + 8) * 516 + colb] = make_float2(acc[nj][2], acc[nj][3]);
        }
    }
    __syncthreads();

    for (int i = 0; i < 8; i++) {
        const int rloc = w * 8 + i;
        const int q = q0 + rloc;
        float vals[16];
        float mx = -1e30f;
#pragma unroll
        for (int j = 0; j < 16; j++) {
            const int col = lane + j * 32;
            float v = Ssm[rloc * 516 + col] * INV_SCALE;
            const int m = causal ? mask[((size_t)b * SS + q) * SS + col]
                                 : mask[(size_t)b * SS + col];
            if (m == 0) v = -1e9f;
            vals[j] = v;
            mx = fmaxf(mx, v);
        }
#pragma unroll
        for (int o = 16; o > 0; o >>= 1)
            mx = fmaxf(mx, __shfl_xor_sync(0xffffffffu, mx, o));
        float sum = 0.0f;
#pragma unroll
        for (int j = 0; j < 16; j++) {
            vals[j] = expf(vals[j] - mx);
            sum += vals[j];
        }
#pragma unroll
        for (int o = 16; o > 0; o >>= 1)
            sum += __shfl_xor_sync(0xffffffffu, sum, o);
        const float inv = 1.0f / sum;
        float* dst = attn + ((size_t)bh * SS + q) * SS;
#pragma unroll
        for (int j = 0; j < 16; j++)
            dst[lane + j * 32] = vals[j] * inv;
    }
}

// ---------------------------------------------------------------------------
// Context: ctx[q,d] = sum_k attn[q,k] * V[k,d], tf32 mma.
// ---------------------------------------------------------------------------
__global__ __launch_bounds__(256)
void attn_ctx_tf32(const float* __restrict__ attn,
                   const float* __restrict__ vf,
                   float* __restrict__ ctx)
{
    __shared__ uint32_t As[64 * 20];
    __shared__ uint32_t Vs[16 * 72];
    const int bh = blockIdx.y, b = bh >> 4, h = bh & 15;
    const int q0 = blockIdx.x * 64;
    const int t = threadIdx.x, lane = t & 31, w = t >> 5;
    const int g = lane >> 2, cc = lane & 3;
    const int qslot = w & 3, dslot = w >> 2;
    const float* Ap = attn + (size_t)bh * SS * SS;
    const float* Vp = vf + (size_t)b * SS * DD + h * DKK;

    float acc[4][4] = {};
    for (int k0 = 0; k0 < SS; k0 += 16) {
        {
            const int r = t >> 2, ak = (t & 3) << 2;
            float4 v = *(const float4*)&Ap[(size_t)(q0 + r) * SS + k0 + ak];
            *(uint4*)&As[r * 20 + ak] = cvt4(v);
        }
        {
            const int kr = t >> 4, cq = (t & 15) << 2;
            float4 v = *(const float4*)&Vp[(size_t)(k0 + kr) * DD + cq];
            *(uint4*)&Vs[kr * 72 + cq] = cvt4(v);
        }
        __syncthreads();

        uint32_t af[4], bf[2];
#pragma unroll
        for (int ks = 0; ks < 2; ks++) {
            const int kb = ks * 8 + cc;
            const int mb = qslot * 16;
            af[0] = As[(mb + g) * 20 + kb];
            af[1] = As[(mb + g + 8) * 20 + kb];
            af[2] = As[(mb + g) * 20 + kb + 4];
            af[3] = As[(mb + g + 8) * 20 + kb + 4];
#pragma unroll
            for (int nj = 0; nj < 4; nj++) {
                const int nbase = dslot * 32 + nj * 8;
                bf[0] = Vs[kb * 72 + nbase + g];
                bf[1] = Vs[(kb + 4) * 72 + nbase + g];
                mma8(acc[nj], af, bf);
            }
        }
        __syncthreads();
    }

    float* Cp = ctx + (size_t)b * SS * DD + h * DKK;
#pragma unroll
    for (int nj = 0; nj < 4; nj++) {
        const int c = dslot * 32 + nj * 8 + 2 * cc;
        const int r = q0 + qslot * 16 + g;
        *(float2*)&Cp[(size_t)r * DD + c]       = make_float2(acc[nj][0], acc[nj][1]);
        *(float2*)&Cp[(size_t)(r + 8) * DD + c] = make_float2(acc[nj][2], acc[nj][3]);
    }
}

// ---------------------------------------------------------------------------
// y = LayerNorm(x + a). a may be nullptr. One block per row (D=1024).
// ---------------------------------------------------------------------------
__global__ __launch_bounds__(256)
void add_ln_kernel(const float* __restrict__ x,
                   const float* __restrict__ a,
                   const float* __restrict__ g,
                   const float* __restrict__ bt,
                   float* __restrict__ y)
{
    const int row = blockIdx.x;
    const int t = threadIdx.x;
    __shared__ float red[256];

    float v[4];
#pragma unroll
    for (int i = 0; i < 4; i++) {
        const int c = t + i * 256;
        float vv = x[(size_t)row * DD + c];
        if (a) vv += a[(size_t)row * DD + c];
        v[i] = vv;
    }
    float s = v[0] + v[1] + v[2] + v[3];
    red[t] = s;
    __syncthreads();
    for (int o = 128; o > 0; o >>= 1) {
        if (t < o) red[t] += red[t + o];
        __syncthreads();
    }
    const float mean = red[0] * (1.0f / DD);
    __syncthreads();

    float s2 = 0.0f;
#pragma unroll
    for (int i = 0; i < 4; i++) {
        const float d = v[i] - mean;
        s2 += d * d;
    }
    red[t] = s2;
    __syncthreads();
    for (int o = 128; o > 0; o >>= 1) {
        if (t < o) red[t] += red[t + o];
        __syncthreads();
    }
    const float var = red[0] * (1.0f / DD);
    const float inv = rsqrtf(var + EPSF);

#pragma unroll
    for (int i = 0; i < 4; i++) {
        const int c = t + i * 256;
        y[(size_t)row * DD + c] = g[c] * (v[i] - mean) * inv + bt[c];
    }
}

// ---------------------------------------------------------------------------
// Host orchestration
// ---------------------------------------------------------------------------
extern "C" void kernel_launch(void* const* d_in, const int* in_sizes, int n_in,
                              void* d_out, int out_size)
{
    const float* src     = (const float*)d_in[0];
    const float* tgt     = (const float*)d_in[1];
    const float* enc_W   = (const float*)d_in[2];
    const float* enc_b   = (const float*)d_in[3];
    const float* enc_W1  = (const float*)d_in[4];
    const float* enc_b1  = (const float*)d_in[5];
    const float* enc_W2  = (const float*)d_in[6];
    const float* enc_b2  = (const float*)d_in[7];
    const float* enc_lng = (const float*)d_in[8];
    const float* enc_lnb = (const float*)d_in[9];
    const float* enc_fg  = (const float*)d_in[10];
    const float* enc_fb  = (const float*)d_in[11];
    const float* dsW     = (const float*)d_in[12];
    const float* dsb     = (const float*)d_in[13];
    const float* dcW     = (const float*)d_in[14];
    const float* dcb     = (const float*)d_in[15];
    const float* dW1     = (const float*)d_in[16];
    const float* db1     = (const float*)d_in[17];
    const float* dW2     = (const float*)d_in[18];
    const float* db2     = (const float*)d_in[19];
    const float* dlng    = (const float*)d_in[20];
    const float* dlnb    = (const float*)d_in[21];
    const float* dfg     = (const float*)d_in[22];
    const float* dfb     = (const float*)d_in[23];
    const int*   src_mask = (const int*)d_in[24];
    const int*   tgt_mask = (const int*)d_in[25];
    float* out = (float*)d_out;

    float* scratch = nullptr;
    cudaGetSymbolAddress((void**)&scratch, g_scratch);

    float* X    = scratch + 0 * MEG;
    float* X2   = scratch + 1 * MEG;
    float* Qb   = scratch + 2 * MEG;   // Q/K/V contiguous for fused QKV gemm
    float* Kb   = scratch + 3 * MEG;
    float* Vb   = scratch + 4 * MEG;
    float* Ab   = scratch + 5 * MEG;
    float* H1   = scratch + 6 * MEG;   // 4M floats
    float* ATT  = scratch + 10 * MEG;  // 8M floats (fallback only)
    float* ENC  = scratch + 18 * MEG;
    float* PRT  = scratch + 19 * MEG;  // 4M floats (split-K partials)
    float* CK   = scratch + 23 * MEG;  // 4M floats (cross K, all layers)
    float* CV   = scratch + 27 * MEG;  // 4M floats (cross V, all layers)

    const size_t SLAB      = (size_t)BB * HH * SS * SS;
    const size_t OFF_ENC   = (size_t)BB * SS * DD;
    const size_t OFF_SELF  = OFF_ENC + (size_t)LL * SLAB;
    const size_t OFF_CROSS = OFF_SELF + (size_t)LL * SLAB;
    const size_t TOTAL     = OFF_CROSS + (size_t)LL * SLAB;
    const bool full = ((size_t)out_size >= TOTAL);

    const int SM_W = 2 * (64 * 36 + 32 * 136) * 4;  // 53248 B
    cudaFuncSetAttribute(gemm_wide, cudaFuncAttributeMaxDynamicSharedMemorySize, SM_W);
    const size_t SC_SMEM = (size_t)(2 * 64 * 68 + 64 * 516) * sizeof(float);
    cudaFuncSetAttribute(attn_scores_tf32,
                         cudaFuncAttributeMaxDynamicSharedMemorySize, (int)SC_SMEM);

    dim3 gQKV(3072 / 128, MROWS / 64);   // 384 CTAs
    dim3 gKVB(4096 / 128, MROWS / 64);   // 512 CTAs (batched cross K or V)
    dim3 gF1(DFFF / 128, MROWS / 64);    // 512 CTAs
    dim3 g64(16, 16);                    // 256 CTAs, 128 thr
    dim3 gSK4(16, 16, 4);                // 1024 CTAs (FFN2 split-K)
    dim3 gS(SS / 64, BB * HH);
    dim3 gC(SS / 64, BB * HH);
    const long long WS = (long long)DD * DD;
    const long long CS = (long long)MEG;

    // ------------------------- Encoder -------------------------
    const float* cur = src;
    for (int l = 0; l < LL; l++) {
        const float* W  = enc_W + (size_t)l * 4 * DD * DD;
        const float* bb = enc_b + (size_t)l * 4 * DD;
        gemm_wide<<<gQKV, 256, SM_W>>>(cur, W, bb, Qb, DD, DD, 0, WS, DD, CS);
        float* adst = full ? out + OFF_ENC + (size_t)l * SLAB : ATT;
        attn_scores_tf32<<<gS, 256, SC_SMEM>>>(Qb, Kb, src_mask, 0, adst);
        attn_ctx_tf32<<<gC, 256>>>(adst, Vb, Qb);
        gemm64<<<g64, 128>>>(Qb, W + 3 * DD * DD, bb + 3 * DD, Ab);
        add_ln_kernel<<<MROWS, 256>>>(cur, Ab, enc_lng + (size_t)l * 2 * DD,
                                      enc_lnb + (size_t)l * 2 * DD, X2);
        gemm_wide<<<gF1, 256, SM_W>>>(X2, enc_W1 + (size_t)l * DD * DFFF,
                                      enc_b1 + (size_t)l * DFFF, H1, DD, DFFF, 1, 0, 0, 0);
        gemm_sk<<<gSK4, 128>>>(H1, enc_W2 + (size_t)l * DFFF * DD, PRT, DFFF, 1024);
        reduce_bias<<<1024, 256>>>(PRT, 4, enc_b2 + (size_t)l * DD, Ab);
        add_ln_kernel<<<MROWS, 256>>>(X2, Ab, enc_lng + (size_t)l * 2 * DD + DD,
                                      enc_lnb + (size_t)l * 2 * DD + DD, X);
        cur = X;
    }
    add_ln_kernel<<<MROWS, 256>>>(cur, nullptr, enc_fg, enc_fb, ENC);

    // Batched cross-attention K/V for all decoder layers (blk = layer)
    gemm_wide<<<gKVB, 256, SM_W>>>(ENC, dcW + (size_t)DD * DD, dcb + DD, CK,
                                   DD, DD, 0, 4LL * DD * DD, 4LL * DD, CS);
    gemm_wide<<<gKVB, 256, SM_W>>>(ENC, dcW + 2 * (size_t)DD * DD, dcb + 2 * DD, CV,
                                   DD, DD, 0, 4LL * DD * DD, 4LL * DD, CS);

    // ------------------------- Decoder -------------------------
    cur = tgt;
    for (int l = 0; l < LL; l++) {
        // self-attention (causal)
        const float* Ws = dsW + (size_t)l * 4 * DD * DD;
        const float* bs = dsb + (size_t)l * 4 * DD;
        gemm_wide<<<gQKV, 256, SM_W>>>(cur, Ws, bs, Qb, DD, DD, 0, WS, DD, CS);
        float* adst = full ? out + OFF_SELF + (size_t)l * SLAB : ATT;
        attn_scores_tf32<<<gS, 256, SC_SMEM>>>(Qb, Kb, tgt_mask, 1, adst);
        attn_ctx_tf32<<<gC, 256>>>(adst, Vb, Qb);
        gemm64<<<g64, 128>>>(Qb, Ws + 3 * DD * DD, bs + 3 * DD, Ab);
        add_ln_kernel<<<MROWS, 256>>>(cur, Ab, dlng + (size_t)l * 3 * DD,
                                      dlnb + (size_t)l * 3 * DD, X);

        // cross-attention (K/V precomputed, batched)
        const float* Wc = dcW + (size_t)l * 4 * DD * DD;
        const float* bc = dcb + (size_t)l * 4 * DD;
        gemm64<<<g64, 128>>>(X, Wc, bc, Qb);
        adst = full ? out + OFF_CROSS + (size_t)l * SLAB : ATT;
        attn_scores_tf32<<<gS, 256, SC_SMEM>>>(Qb, CK + (size_t)l * MEG, src_mask, 0, adst);
        attn_ctx_tf32<<<gC, 256>>>(adst, CV + (size_t)l * MEG, Qb);
        gemm64<<<g64, 128>>>(Qb, Wc + 3 * DD * DD, bc + 3 * DD, Ab);
        add_ln_kernel<<<MROWS, 256>>>(X, Ab, dlng + (size_t)l * 3 * DD + DD,
                                      dlnb + (size_t)l * 3 * DD + DD, X2);

        // FFN
        gemm_wide<<<gF1, 256, SM_W>>>(X2, dW1 + (size_t)l * DD * DFFF,
                                      db1 + (size_t)l * DFFF, H1, DD, DFFF, 1, 0, 0, 0);
        gemm_sk<<<gSK4, 128>>>(H1, dW2 + (size_t)l * DFFF * DD, PRT, DFFF, 1024);
        reduce_bias<<<1024, 256>>>(PRT, 4, db2 + (size_t)l * DD, Ab);
        add_ln_kernel<<<MROWS, 256>>>(X2, Ab, dlng + (size_t)l * 3 * DD + 2 * DD,
                                      dlnb + (size_t)l * 3 * DD + 2 * DD, X);
        cur = X;
    }
    add_ln_kernel<<<MROWS, 256>>>(cur, nullptr, dfg, dfb, out);
}

// round 8
// speedup vs baseline: 1.5802x; 1.0382x over previous
#include <cuda_runtime.h>
#include <cuda_bf16.h>
#include <cstdint>
#include <cstddef>

// ---------------------------------------------------------------------------
// Transformer forward (encoder-decoder), tf32 tensor cores, R8:
// R7 + split-K O-projections with LN-fused reduction, double-buffered ctx,
// one-pass warp-shuffle LayerNorm.
// ---------------------------------------------------------------------------

#define BB   2
#define SS   512
#define DD   1024
#define HH   16
#define DKK  64
#define DFFF 4096
#define LL   4
#define MROWS (BB*SS)          // 1024
#define EPSF 1e-5f
#define INV_SCALE 0.125f       // 1/sqrt(DK)

static const size_t MEG = 1u << 20;
__device__ __align__(16) float g_scratch[31u * (1u << 20)];   // 124 MB

// ---------------------------------------------------------------------------
// tf32 helpers
// ---------------------------------------------------------------------------
__device__ __forceinline__ uint32_t f2t(float x) {
    uint32_t r; asm("cvt.rna.tf32.f32 %0, %1;" : "=r"(r) : "f"(x)); return r;
}
__device__ __forceinline__ void mma8(float* c, const uint32_t* a, const uint32_t* b) {
    asm volatile(
        "mma.sync.aligned.m16n8k8.row.col.f32.tf32.tf32.f32 "
        "{%0,%1,%2,%3}, {%4,%5,%6,%7}, {%8,%9}, {%0,%1,%2,%3};\n"
        : "+f"(c[0]), "+f"(c[1]), "+f"(c[2]), "+f"(c[3])
        : "r"(a[0]), "r"(a[1]), "r"(a[2]), "r"(a[3]), "r"(b[0]), "r"(b[1]));
}
__device__ __forceinline__ uint4 cvt4(float4 v) {
    uint4 u; u.x = f2t(v.x); u.y = f2t(v.y); u.z = f2t(v.z); u.w = f2t(v.w);
    return u;
}

// ---------------------------------------------------------------------------
// Wide tf32 GEMM (64x128 tile, 256 thr, 8 warps 2x4, 32x32 warp tiles).
// Blocked-N support: blk = colg/nb; W += blk*wstride; bias += blk*bstride;
// C += blk*cstride; inner row strides of W and C are nb.
// K-step 32, double buffer. Grid: (totalN/128, M/64). Dyn smem 53248 B.
// ---------------------------------------------------------------------------
__global__ __launch_bounds__(256, 2)
void gemm_wide(const float* __restrict__ A, const float* __restrict__ W,
               const float* __restrict__ bias, float* __restrict__ C,
               int K, int nb, int relu,
               long long wstride, long long bstride, long long cstride)
{
    constexpr int ASTR = 36, BSTR = 136;
    constexpr int ASZ = 64 * ASTR, BSZ = 32 * BSTR, STG = ASZ + BSZ;
    extern __shared__ uint32_t smg[];

    const int t = threadIdx.x;
    const int lane = t & 31, w = t >> 5;
    const int g = lane >> 2, cc = lane & 3;
    const int wm = w >> 2, wn = w & 3;
    const int row0 = blockIdx.y * 64;
    const int colg = blockIdx.x * 128;
    const int blk  = colg / nb;
    const int col0 = colg - blk * nb;
    const float* Wp = W + (size_t)blk * (size_t)wstride;
    const float* bp = bias + (size_t)blk * (size_t)bstride;
    float* Cp = C + (size_t)blk * (size_t)cstride;

    const int ar = t >> 3, ac = (t & 7) << 2;
    const int bk0 = t >> 5, bc = (t & 31) << 2;

    float4 aR[2], bR[4];
    auto loadAB = [&](int k0) {
#pragma unroll
        for (int i = 0; i < 2; i++)
            aR[i] = *(const float4*)&A[(size_t)(row0 + ar + i * 32) * K + k0 + ac];
#pragma unroll
        for (int i = 0; i < 4; i++)
            bR[i] = *(const float4*)&Wp[(size_t)(k0 + bk0 + i * 8) * nb + col0 + bc];
    };
    auto storeAB = [&](int p) {
        uint32_t* as_ = smg + p * STG;
        uint32_t* bs_ = smg + p * STG + ASZ;
#pragma unroll
        for (int i = 0; i < 2; i++)
            *(uint4*)&as_[(ar + i * 32) * ASTR + ac] = cvt4(aR[i]);
#pragma unroll
        for (int i = 0; i < 4; i++)
            *(uint4*)&bs_[(bk0 + i * 8) * BSTR + bc] = cvt4(bR[i]);
    };

    float acc[2][4][4] = {};
    const int NK = K >> 5;
    loadAB(0);
    storeAB(0);
    if (NK > 1) loadAB(32);
    __syncthreads();

    for (int it = 0; it < NK; it++) {
        const int p = it & 1;
        if (it + 1 < NK) storeAB(p ^ 1);
        if (it + 2 < NK) loadAB((it + 2) << 5);

        const uint32_t* as_ = smg + p * STG;
        const uint32_t* bs_ = smg + p * STG + ASZ;
        uint32_t af[2][4], bf[4][2];
#pragma unroll
        for (int ks = 0; ks < 4; ks++) {
            const int kb = ks * 8 + cc;
#pragma unroll
            for (int mi = 0; mi < 2; mi++) {
                const int mb = wm * 32 + mi * 16;
                af[mi][0] = as_[(mb + g) * ASTR + kb];
                af[mi][1] = as_[(mb + g + 8) * ASTR + kb];
                af[mi][2] = as_[(mb + g) * ASTR + kb + 4];
                af[mi][3] = as_[(mb + g + 8) * ASTR + kb + 4];
            }
#pragma unroll
            for (int nj = 0; nj < 4; nj++) {
                const int nbase = wn * 32 + nj * 8;
                bf[nj][0] = bs_[kb * BSTR + nbase + g];
                bf[nj][1] = bs_[(kb + 4) * BSTR + nbase + g];
            }
#pragma unroll
            for (int mi = 0; mi < 2; mi++)
#pragma unroll
                for (int nj = 0; nj < 4; nj++)
                    mma8(acc[mi][nj], af[mi], bf[nj]);
        }
        __syncthreads();
    }

#pragma unroll
    for (int mi = 0; mi < 2; mi++) {
        const int r0 = row0 + wm * 32 + mi * 16 + g;
#pragma unroll
        for (int nj = 0; nj < 4; nj++) {
            const int c = col0 + wn * 32 + nj * 8 + 2 * cc;
            const float b0v = bp[c], b1v = bp[c + 1];
            float v0 = acc[mi][nj][0] + b0v, v1 = acc[mi][nj][1] + b1v;
            float v2 = acc[mi][nj][2] + b0v, v3 = acc[mi][nj][3] + b1v;
            if (relu) {
                v0 = fmaxf(v0, 0.f); v1 = fmaxf(v1, 0.f);
                v2 = fmaxf(v2, 0.f); v3 = fmaxf(v3, 0.f);
            }
            *(float2*)&Cp[(size_t)r0 * nb + c]       = make_float2(v0, v1);
            *(float2*)&Cp[(size_t)(r0 + 8) * nb + c] = make_float2(v2, v3);
        }
    }
}

// ---------------------------------------------------------------------------
// 128-thread 64x64 GEMM with fused bias: C = A[M,1024] @ W[1024,1024] + bias.
// Used only for cross-attention Q projection.
// ---------------------------------------------------------------------------
__global__ __launch_bounds__(128, 4)
void gemm64(const float* __restrict__ A, const float* __restrict__ W,
            const float* __restrict__ bias, float* __restrict__ C)
{
    constexpr int ASTR = 36, BSTR = 72;
    constexpr int ASZ = 64 * ASTR, BSZ = 32 * BSTR, STG = ASZ + BSZ;
    __shared__ uint32_t smg[2 * STG];

    const int t = threadIdx.x;
    const int lane = t & 31, w = t >> 5;
    const int g = lane >> 2, cc = lane & 3;
    const int wm = w >> 1, wn = w & 1;
    const int row0 = blockIdx.y * 64;
    const int col0 = blockIdx.x * 64;

    const int ar = t >> 3, ac = (t & 7) << 2;
    const int bk = t >> 4, bc = (t & 15) << 2;

    float4 aR[4], bR[4];
    auto loadAB = [&](int k0) {
#pragma unroll
        for (int i = 0; i < 4; i++)
            aR[i] = *(const float4*)&A[(size_t)(row0 + ar + i * 16) * 1024 + k0 + ac];
#pragma unroll
        for (int i = 0; i < 4; i++)
            bR[i] = *(const float4*)&W[(size_t)(k0 + bk + i * 8) * 1024 + col0 + bc];
    };
    auto storeAB = [&](int p) {
        uint32_t* as_ = smg + p * STG;
        uint32_t* bs_ = smg + p * STG + ASZ;
#pragma unroll
        for (int i = 0; i < 4; i++)
            *(uint4*)&as_[(ar + i * 16) * ASTR + ac] = cvt4(aR[i]);
#pragma unroll
        for (int i = 0; i < 4; i++)
            *(uint4*)&bs_[(bk + i * 8) * BSTR + bc] = cvt4(bR[i]);
    };

    float acc[2][4][4] = {};
    const int NK = 32;
    loadAB(0);
    storeAB(0);
    loadAB(32);
    __syncthreads();

    for (int it = 0; it < NK; it++) {
        const int p = it & 1;
        if (it + 1 < NK) storeAB(p ^ 1);
        if (it + 2 < NK) loadAB((it + 2) << 5);

        const uint32_t* as_ = smg + p * STG;
        const uint32_t* bs_ = smg + p * STG + ASZ;
        uint32_t af[2][4], bf[4][2];
#pragma unroll
        for (int ks = 0; ks < 4; ks++) {
            const int kb = ks * 8 + cc;
#pragma unroll
            for (int mi = 0; mi < 2; mi++) {
                const int mb = wm * 32 + mi * 16;
                af[mi][0] = as_[(mb + g) * ASTR + kb];
                af[mi][1] = as_[(mb + g + 8) * ASTR + kb];
                af[mi][2] = as_[(mb + g) * ASTR + kb + 4];
                af[mi][3] = as_[(mb + g + 8) * ASTR + kb + 4];
            }
#pragma unroll
            for (int nj = 0; nj < 4; nj++) {
                const int nbase = wn * 32 + nj * 8;
                bf[nj][0] = bs_[kb * BSTR + nbase + g];
                bf[nj][1] = bs_[(kb + 4) * BSTR + nbase + g];
            }
#pragma unroll
            for (int mi = 0; mi < 2; mi++)
#pragma unroll
                for (int nj = 0; nj < 4; nj++)
                    mma8(acc[mi][nj], af[mi], bf[nj]);
        }
        __syncthreads();
    }

#pragma unroll
    for (int mi = 0; mi < 2; mi++) {
        const int r0 = row0 + wm * 32 + mi * 16 + g;
#pragma unroll
        for (int nj = 0; nj < 4; nj++) {
            const int c = col0 + wn * 32 + nj * 8 + 2 * cc;
            const float b0v = bias[c], b1v = bias[c + 1];
            *(float2*)&C[(size_t)r0 * 1024 + c] =
                make_float2(acc[mi][nj][0] + b0v, acc[mi][nj][1] + b1v);
            *(float2*)&C[(size_t)(r0 + 8) * 1024 + c] =
                make_float2(acc[mi][nj][2] + b0v, acc[mi][nj][3] + b1v);
        }
    }
}

// ---------------------------------------------------------------------------
// Split-K tf32 GEMM, N=1024: parts[z] = A[:, z*Kc:(z+1)*Kc] @ W-slice.
// Grid: (16, 16, nsplit). No bias (applied downstream).
// ---------------------------------------------------------------------------
__global__ __launch_bounds__(128, 4)
void gemm_sk(const float* __restrict__ A, const float* __restrict__ W,
             float* __restrict__ parts, int lda, int Kc)
{
    constexpr int ASTR = 36, BSTR = 72;
    constexpr int ASZ = 64 * ASTR, BSZ = 32 * BSTR, STG = ASZ + BSZ;
    __shared__ uint32_t smg[2 * STG];

    const int z = blockIdx.z;
    const float* Az = A + (size_t)z * Kc;
    const float* Wz = W + (size_t)z * Kc * 1024;
    float* Cp = parts + (size_t)z * MEG;

    const int t = threadIdx.x;
    const int lane = t & 31, w = t >> 5;
    const int g = lane >> 2, cc = lane & 3;
    const int wm = w >> 1, wn = w & 1;
    const int row0 = blockIdx.y * 64;
    const int col0 = blockIdx.x * 64;

    const int ar = t >> 3, ac = (t & 7) << 2;
    const int bk = t >> 4, bc = (t & 15) << 2;

    float4 aR[4], bR[4];
    auto loadAB = [&](int k0) {
#pragma unroll
        for (int i = 0; i < 4; i++)
            aR[i] = *(const float4*)&Az[(size_t)(row0 + ar + i * 16) * lda + k0 + ac];
#pragma unroll
        for (int i = 0; i < 4; i++)
            bR[i] = *(const float4*)&Wz[(size_t)(k0 + bk + i * 8) * 1024 + col0 + bc];
    };
    auto storeAB = [&](int p) {
        uint32_t* as_ = smg + p * STG;
        uint32_t* bs_ = smg + p * STG + ASZ;
#pragma unroll
        for (int i = 0; i < 4; i++)
            *(uint4*)&as_[(ar + i * 16) * ASTR + ac] = cvt4(aR[i]);
#pragma unroll
        for (int i = 0; i < 4; i++)
            *(uint4*)&bs_[(bk + i * 8) * BSTR + bc] = cvt4(bR[i]);
    };

    float acc[2][4][4] = {};
    const int NK = Kc >> 5;
    loadAB(0);
    storeAB(0);
    if (NK > 1) loadAB(32);
    __syncthreads();

    for (int it = 0; it < NK; it++) {
        const int p = it & 1;
        if (it + 1 < NK) storeAB(p ^ 1);
        if (it + 2 < NK) loadAB((it + 2) << 5);

        const uint32_t* as_ = smg + p * STG;
        const uint32_t* bs_ = smg + p * STG + ASZ;
        uint32_t af[2][4], bf[4][2];
#pragma unroll
        for (int ks = 0; ks < 4; ks++) {
            const int kb = ks * 8 + cc;
#pragma unroll
            for (int mi = 0; mi < 2; mi++) {
                const int mb = wm * 32 + mi * 16;
                af[mi][0] = as_[(mb + g) * ASTR + kb];
                af[mi][1] = as_[(mb + g + 8) * ASTR + kb];
                af[mi][2] = as_[(mb + g) * ASTR + kb + 4];
                af[mi][3] = as_[(mb + g + 8) * ASTR + kb + 4];
            }
#pragma unroll
            for (int nj = 0; nj < 4; nj++) {
                const int nbase = wn * 32 + nj * 8;
                bf[nj][0] = bs_[kb * BSTR + nbase + g];
                bf[nj][1] = bs_[(kb + 4) * BSTR + nbase + g];
            }
#pragma unroll
            for (int mi = 0; mi < 2; mi++)
#pragma unroll
                for (int nj = 0; nj < 4; nj++)
                    mma8(acc[mi][nj], af[mi], bf[nj]);
        }
        __syncthreads();
    }

#pragma unroll
    for (int mi = 0; mi < 2; mi++) {
        const int r0 = row0 + wm * 32 + mi * 16 + g;
#pragma unroll
        for (int nj = 0; nj < 4; nj++) {
            const int c = col0 + wn * 32 + nj * 8 + 2 * cc;
            *(float2*)&Cp[(size_t)r0 * 1024 + c] =
                make_float2(acc[mi][nj][0], acc[mi][nj][1]);
            *(float2*)&Cp[(size_t)(r0 + 8) * 1024 + c] =
                make_float2(acc[mi][nj][2], acc[mi][nj][3]);
        }
    }
}

// ---------------------------------------------------------------------------
// Warp-shuffle helpers for one-pass LayerNorm
// ---------------------------------------------------------------------------
__device__ __forceinline__ void block_reduce2(float& s, float& s2,
                                              float* sh1, float* sh2,
                                              int lane, int w)
{
#pragma unroll
    for (int o = 16; o > 0; o >>= 1) {
        s  += __shfl_xor_sync(0xffffffffu, s, o);
        s2 += __shfl_xor_sync(0xffffffffu, s2, o);
    }
    if (lane == 0) { sh1[w] = s; sh2[w] = s2; }
    __syncthreads();
    if (w == 0) {
        float a = (lane < 8) ? sh1[lane] : 0.f;
        float b = (lane < 8) ? sh2[lane] : 0.f;
#pragma unroll
        for (int o = 4; o > 0; o >>= 1) {
            a += __shfl_xor_sync(0xffffffffu, a, o);
            b += __shfl_xor_sync(0xffffffffu, b, o);
        }
        if (lane == 0) { sh1[0] = a; sh2[0] = b; }
    }
    __syncthreads();
}

// ---------------------------------------------------------------------------
// y = LayerNorm(x + sum_z parts[z] + bias). One block per row (D=1024).
// Fuses split-K reduction + bias + residual + LN.
// ---------------------------------------------------------------------------
__global__ __launch_bounds__(256)
void add_ln_red(const float* __restrict__ x, const float* __restrict__ parts,
                int nparts, const float* __restrict__ bias,
                const float* __restrict__ g, const float* __restrict__ bt,
                float* __restrict__ y)
{
    const int row = blockIdx.x;
    const int t = threadIdx.x;
    const int lane = t & 31, w = t >> 5;
    __shared__ float sh1[8], sh2[8];

    float v[4];
#pragma unroll
    for (int i = 0; i < 4; i++) {
        const int c = t + i * 256;
        const size_t idx = (size_t)row * DD + c;
        float a = parts[idx];
        for (int p = 1; p < nparts; p++) a += parts[(size_t)p * MEG + idx];
        v[i] = x[idx] + a + bias[c];
    }
    float s = 0.f, s2 = 0.f;
#pragma unroll
    for (int i = 0; i < 4; i++) { s += v[i]; s2 += v[i] * v[i]; }
    block_reduce2(s, s2, sh1, sh2, lane, w);
    const float mean = sh1[0] * (1.0f / DD);
    const float var  = sh2[0] * (1.0f / DD) - mean * mean;
    const float inv  = rsqrtf(var + EPSF);

#pragma unroll
    for (int i = 0; i < 4; i++) {
        const int c = t + i * 256;
        y[(size_t)row * DD + c] = g[c] * (v[i] - mean) * inv + bt[c];
    }
}

// ---------------------------------------------------------------------------
// y = LayerNorm(x). One block per row.
// ---------------------------------------------------------------------------
__global__ __launch_bounds__(256)
void ln_plain(const float* __restrict__ x, const float* __restrict__ g,
              const float* __restrict__ bt, float* __restrict__ y)
{
    const int row = blockIdx.x;
    const int t = threadIdx.x;
    const int lane = t & 31, w = t >> 5;
    __shared__ float sh1[8], sh2[8];

    float v[4];
#pragma unroll
    for (int i = 0; i < 4; i++)
        v[i] = x[(size_t)row * DD + t + i * 256];
    float s = 0.f, s2 = 0.f;
#pragma unroll
    for (int i = 0; i < 4; i++) { s += v[i]; s2 += v[i] * v[i]; }
    block_reduce2(s, s2, sh1, sh2, lane, w);
    const float mean = sh1[0] * (1.0f / DD);
    const float var  = sh2[0] * (1.0f / DD) - mean * mean;
    const float inv  = rsqrtf(var + EPSF);

#pragma unroll
    for (int i = 0; i < 4; i++) {
        const int c = t + i * 256;
        y[(size_t)row * DD + c] = g[c] * (v[i] - mean) * inv + bt[c];
    }
}

// ---------------------------------------------------------------------------
// Scores + mask + softmax (tf32 mma for Q.K^T, softmax in smem).
// ---------------------------------------------------------------------------
__global__ __launch_bounds__(256)
void attn_scores_tf32(const float* __restrict__ qf,
                      const float* __restrict__ kf,
                      const int* __restrict__ mask,
                      int causal,
                      float* __restrict__ attn)
{
    extern __shared__ float smemf[];
    uint32_t* Qs = (uint32_t*)smemf;        // 64*68
    uint32_t* Ks = Qs + 64 * 68;            // 64*68
    float* Ssm = smemf + 2 * 64 * 68;       // 64*516

    const int bh = blockIdx.y, b = bh >> 4, h = bh & 15;
    const int q0 = blockIdx.x * 64;
    const int t = threadIdx.x, lane = t & 31, w = t >> 5;
    const int g = lane >> 2, cc = lane & 3;
    const int qslot = w & 3, kslot = w >> 2;

#pragma unroll
    for (int i = 0; i < 4; i++) {
        const int idx = t + i * 256;
        const int r = idx >> 4, cq = (idx & 15) << 2;
        float4 v = *(const float4*)&qf[(size_t)(b * SS + q0 + r) * DD + h * DKK + cq];
        *(uint4*)&Qs[r * 68 + cq] = cvt4(v);
    }

    for (int kt = 0; kt < 8; kt++) {
        __syncthreads();
#pragma unroll
        for (int i = 0; i < 4; i++) {
            const int idx = t + i * 256;
            const int r = idx >> 4, cq = (idx & 15) << 2;
            float4 v = *(const float4*)&kf[(size_t)(b * SS + kt * 64 + r) * DD + h * DKK + cq];
            *(uint4*)&Ks[r * 68 + cq] = cvt4(v);
        }
        __syncthreads();

        float acc[4][4] = {};
        uint32_t af[4];
#pragma unroll
        for (int ks = 0; ks < 8; ks++) {
            const int kb = ks * 8 + cc;
            const int mb = qslot * 16;
            af[0] = Qs[(mb + g) * 68 + kb];
            af[1] = Qs[(mb + g + 8) * 68 + kb];
            af[2] = Qs[(mb + g) * 68 + kb + 4];
            af[3] = Qs[(mb + g + 8) * 68 + kb + 4];
#pragma unroll
            for (int nj = 0; nj < 4; nj++) {
                const int nbase = kslot * 32 + nj * 8;
                uint32_t bf[2];
                bf[0] = Ks[(nbase + g) * 68 + kb];
                bf[1] = Ks[(nbase + g) * 68 + kb + 4];
                mma8(acc[nj], af, bf);
            }
        }
#pragma unroll
        for (int nj = 0; nj < 4; nj++) {
            const int colb = kt * 64 + kslot * 32 + nj * 8 + 2 * cc;
            const int rr = qslot * 16 + g;
            *(float2*)&Ssm[rr * 516 + colb]       = make_float2(acc[nj][0], acc[nj][1]);
            *(float2*)&Ssm[(rr + 8) * 516 + colb] = make_float2(acc[nj][2], acc[nj][3]);
        }
    }
    __syncthreads();

    for (int i = 0; i < 8; i++) {
        const int rloc = w * 8 + i;
        const int q = q0 + rloc;
        float vals[16];
        float mx = -1e30f;
#pragma unroll
        for (int j = 0; j < 16; j++) {
            const int col = lane + j * 32;
            float v = Ssm[rloc * 516 + col] * INV_SCALE;
            const int m = causal ? mask[((size_t)b * SS + q) * SS + col]
                                 : mask[(size_t)b * SS + col];
            if (m == 0) v = -1e9f;
            vals[j] = v;
            mx = fmaxf(mx, v);
        }
#pragma unroll
        for (int o = 16; o > 0; o >>= 1)
            mx = fmaxf(mx, __shfl_xor_sync(0xffffffffu, mx, o));
        float sum = 0.0f;
#pragma unroll
        for (int j = 0; j < 16; j++) {
            vals[j] = expf(vals[j] - mx);
            sum += vals[j];
        }
#pragma unroll
        for (int o = 16; o > 0; o >>= 1)
            sum += __shfl_xor_sync(0xffffffffu, sum, o);
        const float inv = 1.0f / sum;
        float* dst = attn + ((size_t)bh * SS + q) * SS;
#pragma unroll
        for (int j = 0; j < 16; j++)
            dst[lane + j * 32] = vals[j] * inv;
    }
}

// ---------------------------------------------------------------------------
// Context: ctx[q,d] = sum_k attn[q,k] * V[k,d], tf32 mma.
// Double-buffered, K-step 32 (1 sync per iteration, 16 total).
// ---------------------------------------------------------------------------
__global__ __launch_bounds__(256)
void attn_ctx_tf32(const float* __restrict__ attn,
                   const float* __restrict__ vf,
                   float* __restrict__ ctx)
{
    constexpr int ASTR = 36, BSTR = 72;
    constexpr int ASZ = 64 * ASTR, BSZ = 32 * BSTR, STG = ASZ + BSZ;
    __shared__ uint32_t smg[2 * STG];   // 36864 B

    const int bh = blockIdx.y, b = bh >> 4, h = bh & 15;
    const int q0 = blockIdx.x * 64;
    const int t = threadIdx.x, lane = t & 31, w = t >> 5;
    const int g = lane >> 2, cc = lane & 3;
    const int qslot = w & 3, dslot = w >> 2;
    const float* Ap = attn + (size_t)bh * SS * SS;
    const float* Vp = vf + (size_t)b * SS * DD + h * DKK;

    const int ar = t >> 3, ac = (t & 7) << 2;    // A: 64x32, 2 f4/thread
    const int vr = t >> 4, vc = (t & 15) << 2;   // V: 32x64, 2 f4/thread

    float4 aR[2], vR[2];
    auto loadAB = [&](int k0) {
#pragma unroll
        for (int i = 0; i < 2; i++)
            aR[i] = *(const float4*)&Ap[(size_t)(q0 + ar + i * 32) * SS + k0 + ac];
#pragma unroll
        for (int i = 0; i < 2; i++)
            vR[i] = *(const float4*)&Vp[(size_t)(k0 + vr + i * 16) * DD + vc];
    };
    auto storeAB = [&](int p) {
        uint32_t* as_ = smg + p * STG;
        uint32_t* bs_ = smg + p * STG + ASZ;
#pragma unroll
        for (int i = 0; i < 2; i++)
            *(uint4*)&as_[(ar + i * 32) * ASTR + ac] = cvt4(aR[i]);
#pragma unroll
        for (int i = 0; i < 2; i++)
            *(uint4*)&bs_[(vr + i * 16) * BSTR + vc] = cvt4(vR[i]);
    };

    float acc[4][4] = {};
    const int NK = 16;   // 512/32
    loadAB(0);
    storeAB(0);
    loadAB(32);
    __syncthreads();

    for (int it = 0; it < NK; it++) {
        const int p = it & 1;
        if (it + 1 < NK) storeAB(p ^ 1);
        if (it + 2 < NK) loadAB((it + 2) << 5);

        const uint32_t* as_ = smg + p * STG;
        const uint32_t* bs_ = smg + p * STG + ASZ;
        uint32_t af[4], bf[2];
#pragma unroll
        for (int ks = 0; ks < 4; ks++) {
            const int kb = ks * 8 + cc;
            const int mb = qslot * 16;
            af[0] = as_[(mb + g) * ASTR + kb];
            af[1] = as_[(mb + g + 8) * ASTR + kb];
            af[2] = as_[(mb + g) * ASTR + kb + 4];
            af[3] = as_[(mb + g + 8) * ASTR + kb + 4];
#pragma unroll
            for (int nj = 0; nj < 4; nj++) {
                const int nbase = dslot * 32 + nj * 8;
                bf[0] = bs_[kb * BSTR + nbase + g];
                bf[1] = bs_[(kb + 4) * BSTR + nbase + g];
                mma8(acc[nj], af, bf);
            }
        }
        __syncthreads();
    }

    float* Cp = ctx + (size_t)b * SS * DD + h * DKK;
#pragma unroll
    for (int nj = 0; nj < 4; nj++) {
        const int c = dslot * 32 + nj * 8 + 2 * cc;
        const int r = q0 + qslot * 16 + g;
        *(float2*)&Cp[(size_t)r * DD + c]       = make_float2(acc[nj][0], acc[nj][1]);
        *(float2*)&Cp[(size_t)(r + 8) * DD + c] = make_float2(acc[nj][2], acc[nj][3]);
    }
}

// ---------------------------------------------------------------------------
// Host orchestration
// ---------------------------------------------------------------------------
extern "C" void kernel_launch(void* const* d_in, const int* in_sizes, int n_in,
                              void* d_out, int out_size)
{
    const float* src     = (const float*)d_in[0];
    const float* tgt     = (const float*)d_in[1];
    const float* enc_W   = (const float*)d_in[2];
    const float* enc_b   = (const float*)d_in[3];
    const float* enc_W1  = (const float*)d_in[4];
    const float* enc_b1  = (const float*)d_in[5];
    const float* enc_W2  = (const float*)d_in[6];
    const float* enc_b2  = (const float*)d_in[7];
    const float* enc_lng = (const float*)d_in[8];
    const float* enc_lnb = (const float*)d_in[9];
    const float* enc_fg  = (const float*)d_in[10];
    const float* enc_fb  = (const float*)d_in[11];
    const float* dsW     = (const float*)d_in[12];
    const float* dsb     = (const float*)d_in[13];
    const float* dcW     = (const float*)d_in[14];
    const float* dcb     = (const float*)d_in[15];
    const float* dW1     = (const float*)d_in[16];
    const float* db1     = (const float*)d_in[17];
    const float* dW2     = (const float*)d_in[18];
    const float* db2     = (const float*)d_in[19];
    const float* dlng    = (const float*)d_in[20];
    const float* dlnb    = (const float*)d_in[21];
    const float* dfg     = (const float*)d_in[22];
    const float* dfb     = (const float*)d_in[23];
    const int*   src_mask = (const int*)d_in[24];
    const int*   tgt_mask = (const int*)d_in[25];
    float* out = (float*)d_out;

    float* scratch = nullptr;
    cudaGetSymbolAddress((void**)&scratch, g_scratch);

    float* X    = scratch + 0 * MEG;
    float* X2   = scratch + 1 * MEG;
    float* Qb   = scratch + 2 * MEG;   // Q/K/V contiguous for fused QKV gemm
    float* Kb   = scratch + 3 * MEG;
    float* Vb   = scratch + 4 * MEG;
    float* H1   = scratch + 6 * MEG;   // 4M floats
    float* ATT  = scratch + 10 * MEG;  // 8M floats (fallback only)
    float* ENC  = scratch + 18 * MEG;
    float* PRT  = scratch + 19 * MEG;  // 4M floats (split-K partials)
    float* CK   = scratch + 23 * MEG;  // 4M floats (cross K, all layers)
    float* CV   = scratch + 27 * MEG;  // 4M floats (cross V, all layers)
    (void)Kb; (void)Vb;

    const size_t SLAB      = (size_t)BB * HH * SS * SS;
    const size_t OFF_ENC   = (size_t)BB * SS * DD;
    const size_t OFF_SELF  = OFF_ENC + (size_t)LL * SLAB;
    const size_t OFF_CROSS = OFF_SELF + (size_t)LL * SLAB;
    const size_t TOTAL     = OFF_CROSS + (size_t)LL * SLAB;
    const bool full = ((size_t)out_size >= TOTAL);

    const int SM_W = 2 * (64 * 36 + 32 * 136) * 4;  // 53248 B
    cudaFuncSetAttribute(gemm_wide, cudaFuncAttributeMaxDynamicSharedMemorySize, SM_W);
    const size_t SC_SMEM = (size_t)(2 * 64 * 68 + 64 * 516) * sizeof(float);
    cudaFuncSetAttribute(attn_scores_tf32,
                         cudaFuncAttributeMaxDynamicSharedMemorySize, (int)SC_SMEM);

    dim3 gQKV(3072 / 128, MROWS / 64);   // 384 CTAs
    dim3 gKVB(4096 / 128, MROWS / 64);   // 512 CTAs (batched cross K or V)
    dim3 gF1(DFFF / 128, MROWS / 64);    // 512 CTAs
    dim3 g64(16, 16);                    // 256 CTAs, 128 thr (cross-Q only)
    dim3 gSK2(16, 16, 2);                // 512 CTAs (O-proj split-K)
    dim3 gSK4(16, 16, 4);                // 1024 CTAs (FFN2 split-K)
    dim3 gS(SS / 64, BB * HH);
    dim3 gC(SS / 64, BB * HH);
    const long long WS = (long long)DD * DD;
    const long long CS = (long long)MEG;

    // ------------------------- Encoder -------------------------
    const float* cur = src;
    for (int l = 0; l < LL; l++) {
        const float* W  = enc_W + (size_t)l * 4 * DD * DD;
        const float* bb = enc_b + (size_t)l * 4 * DD;
        gemm_wide<<<gQKV, 256, SM_W>>>(cur, W, bb, Qb, DD, DD, 0, WS, DD, CS);
        float* adst = full ? out + OFF_ENC + (size_t)l * SLAB : ATT;
        attn_scores_tf32<<<gS, 256, SC_SMEM>>>(Qb, Kb, src_mask, 0, adst);
        attn_ctx_tf32<<<gC, 256>>>(adst, Vb, Qb);
        gemm_sk<<<gSK2, 128>>>(Qb, W + 3 * DD * DD, PRT, DD, 512);
        add_ln_red<<<MROWS, 256>>>(cur, PRT, 2, bb + 3 * DD,
                                   enc_lng + (size_t)l * 2 * DD,
                                   enc_lnb + (size_t)l * 2 * DD, X2);
        gemm_wide<<<gF1, 256, SM_W>>>(X2, enc_W1 + (size_t)l * DD * DFFF,
                                      enc_b1 + (size_t)l * DFFF, H1, DD, DFFF, 1, 0, 0, 0);
        gemm_sk<<<gSK4, 128>>>(H1, enc_W2 + (size_t)l * DFFF * DD, PRT, DFFF, 1024);
        add_ln_red<<<MROWS, 256>>>(X2, PRT, 4, enc_b2 + (size_t)l * DD,
                                   enc_lng + (size_t)l * 2 * DD + DD,
                                   enc_lnb + (size_t)l * 2 * DD + DD, X);
        cur = X;
    }
    ln_plain<<<MROWS, 256>>>(cur, enc_fg, enc_fb, ENC);

    // Batched cross-attention K/V for all decoder layers (blk = layer)
    gemm_wide<<<gKVB, 256, SM_W>>>(ENC, dcW + (size_t)DD * DD, dcb + DD, CK,
                                   DD, DD, 0, 4LL * DD * DD, 4LL * DD, CS);
    gemm_wide<<<gKVB, 256, SM_W>>>(ENC, dcW + 2 * (size_t)DD * DD, dcb + 2 * DD, CV,
                                   DD, DD, 0, 4LL * DD * DD, 4LL * DD, CS);

    // ------------------------- Decoder -------------------------
    cur = tgt;
    for (int l = 0; l < LL; l++) {
        // self-attention (causal)
        const float* Ws = dsW + (size_t)l * 4 * DD * DD;
        const float* bs = dsb + (size_t)l * 4 * DD;
        gemm_wide<<<gQKV, 256, SM_W>>>(cur, Ws, bs, Qb, DD, DD, 0, WS, DD, CS);
        float* adst = full ? out + OFF_SELF + (size_t)l * SLAB : ATT;
        attn_scores_tf32<<<gS, 256, SC_SMEM>>>(Qb, Kb, tgt_mask, 1, adst);
        attn_ctx_tf32<<<gC, 256>>>(adst, Vb, Qb);
        gemm_sk<<<gSK2, 128>>>(Qb, Ws + 3 * DD * DD, PRT, DD, 512);
        add_ln_red<<<MROWS, 256>>>(cur, PRT, 2, bs + 3 * DD,
                                   dlng + (size_t)l * 3 * DD,
                                   dlnb + (size_t)l * 3 * DD, X);

        // cross-attention (K/V precomputed, batched)
        const float* Wc = dcW + (size_t)l * 4 * DD * DD;
        const float* bc = dcb + (size_t)l * 4 * DD;
        gemm64<<<g64, 128>>>(X, Wc, bc, Qb);
        adst = full ? out + OFF_CROSS + (size_t)l * SLAB : ATT;
        attn_scores_tf32<<<gS, 256, SC_SMEM>>>(Qb, CK + (size_t)l * MEG, src_mask, 0, adst);
        attn_ctx_tf32<<<gC, 256>>>(adst, CV + (size_t)l * MEG, Qb);
        gemm_sk<<<gSK2, 128>>>(Qb, Wc + 3 * DD * DD, PRT, DD, 512);
        add_ln_red<<<MROWS, 256>>>(X, PRT, 2, bc + 3 * DD,
                                   dlng + (size_t)l * 3 * DD + DD,
                                   dlnb + (size_t)l * 3 * DD + DD, X2);

        // FFN
        gemm_wide<<<gF1, 256, SM_W>>>(X2, dW1 + (size_t)l * DD * DFFF,
                                      db1 + (size_t)l * DFFF, H1, DD, DFFF, 1, 0, 0, 0);
        gemm_sk<<<gSK4, 128>>>(H1, dW2 + (size_t)l * DFFF * DD, PRT, DFFF, 1024);
        add_ln_red<<<MROWS, 256>>>(X2, PRT, 4, db2 + (size_t)l * DD,
                                   dlng + (size_t)l * 3 * DD + 2 * DD,
                                   dlnb + (size_t)l * 3 * DD + 2 * DD, X);
        cur = X;
    }
    ln_plain<<<MROWS, 256>>>(cur, dfg, dfb, out);
}

// round 9
// speedup vs baseline: 2.2670x; 1.4346x over previous
#include <cuda_runtime.h>
#include <cuda_fp16.h>
#include <cstdint>
#include <cstddef>

// ---------------------------------------------------------------------------
// Transformer forward (encoder-decoder), R9: fp16 m16n8k16 tensor cores
// (fp32 accumulate) replacing tf32 m16n8k8 in all GEMM/attention kernels.
// Structure identical to R8.
// ---------------------------------------------------------------------------

#define BB   2
#define SS   512
#define DD   1024
#define HH   16
#define DKK  64
#define DFFF 4096
#define LL   4
#define MROWS (BB*SS)          // 1024
#define EPSF 1e-5f
#define INV_SCALE 0.125f       // 1/sqrt(DK)

static const size_t MEG = 1u << 20;
__device__ __align__(16) float g_scratch[31u * (1u << 20)];   // 124 MB

// ---------------------------------------------------------------------------
// fp16 helpers
// ---------------------------------------------------------------------------
__device__ __forceinline__ uint32_t pk(float lo, float hi) {
    __half2 h = __floats2half2_rn(lo, hi);
    return *(uint32_t*)&h;
}
// pack 4 consecutive-k floats into 2 half2 (uint2)
__device__ __forceinline__ uint2 pk4(float4 v) {
    return make_uint2(pk(v.x, v.y), pk(v.z, v.w));
}
// pack two k-rows (even e, odd o) x 4 n-cols into 4 half2 (uint4)
__device__ __forceinline__ uint4 pkT(float4 e, float4 o) {
    return make_uint4(pk(e.x, o.x), pk(e.y, o.y), pk(e.z, o.z), pk(e.w, o.w));
}
__device__ __forceinline__ void mma16(float* c, const uint32_t* a, const uint32_t* b) {
    asm volatile(
        "mma.sync.aligned.m16n8k16.row.col.f32.f16.f16.f32 "
        "{%0,%1,%2,%3}, {%4,%5,%6,%7}, {%8,%9}, {%0,%1,%2,%3};\n"
        : "+f"(c[0]), "+f"(c[1]), "+f"(c[2]), "+f"(c[3])
        : "r"(a[0]), "r"(a[1]), "r"(a[2]), "r"(a[3]), "r"(b[0]), "r"(b[1]));
}

// ---------------------------------------------------------------------------
// Wide fp16 GEMM (64x128 tile, 256 thr, 8 warps 2x4, 32x32 warp tiles).
// Blocked-N support: blk = colg/nb; W += blk*wstride; bias += blk*bstride;
// C += blk*cstride; inner row strides of W and C are nb.
// A smem: [64][16 half2] stride 20. B smem: [16 pair-rows][128] stride 136.
// K-step 32, double buffer. Dyn smem 2*(1280+2176)*4 = 27648 B.
// ---------------------------------------------------------------------------
__global__ __launch_bounds__(256, 2)
void gemm_wide(const float* __restrict__ A, const float* __restrict__ W,
               const float* __restrict__ bias, float* __restrict__ C,
               int K, int nb, int relu,
               long long wstride, long long bstride, long long cstride)
{
    constexpr int ASTR = 20, BSTR = 136;
    constexpr int ASZ = 64 * ASTR, BSZ = 16 * BSTR, STG = ASZ + BSZ;
    extern __shared__ uint32_t smg[];

    const int t = threadIdx.x;
    const int lane = t & 31, w = t >> 5;
    const int g = lane >> 2, cc = lane & 3;
    const int wm = w >> 2, wn = w & 3;
    const int row0 = blockIdx.y * 64;
    const int colg = blockIdx.x * 128;
    const int blk  = colg / nb;
    const int col0 = colg - blk * nb;
    const float* Wp = W + (size_t)blk * (size_t)wstride;
    const float* bp = bias + (size_t)blk * (size_t)bstride;
    float* Cp = C + (size_t)blk * (size_t)cstride;

    const int ar = t >> 3, ac = (t & 7) << 2;        // A: rows ar, ar+32
    const int bk0 = t >> 5, bc = (t & 31) << 2;      // B pair-rows bk0, bk0+8

    float4 aR[2], bE[2], bO[2];
    auto loadAB = [&](int k0) {
#pragma unroll
        for (int i = 0; i < 2; i++)
            aR[i] = *(const float4*)&A[(size_t)(row0 + ar + i * 32) * K + k0 + ac];
#pragma unroll
        for (int i = 0; i < 2; i++) {
            const int p = bk0 + i * 8;
            bE[i] = *(const float4*)&Wp[(size_t)(k0 + 2 * p) * nb + col0 + bc];
            bO[i] = *(const float4*)&Wp[(size_t)(k0 + 2 * p + 1) * nb + col0 + bc];
        }
    };
    auto storeAB = [&](int p) {
        uint32_t* as_ = smg + p * STG;
        uint32_t* bs_ = smg + p * STG + ASZ;
#pragma unroll
        for (int i = 0; i < 2; i++)
            *(uint2*)&as_[(ar + i * 32) * ASTR + (ac >> 1)] = pk4(aR[i]);
#pragma unroll
        for (int i = 0; i < 2; i++)
            *(uint4*)&bs_[(bk0 + i * 8) * BSTR + bc] = pkT(bE[i], bO[i]);
    };

    float acc[2][4][4] = {};
    const int NK = K >> 5;
    loadAB(0);
    storeAB(0);
    if (NK > 1) loadAB(32);
    __syncthreads();

    for (int it = 0; it < NK; it++) {
        const int p = it & 1;
        if (it + 1 < NK) storeAB(p ^ 1);
        if (it + 2 < NK) loadAB((it + 2) << 5);

        const uint32_t* as_ = smg + p * STG;
        const uint32_t* bs_ = smg + p * STG + ASZ;
        uint32_t af[2][4], bf[4][2];
#pragma unroll
        for (int ksi = 0; ksi < 2; ksi++) {
            const int kp = ksi * 8 + cc;
#pragma unroll
            for (int mi = 0; mi < 2; mi++) {
                const int mb = wm * 32 + mi * 16;
                af[mi][0] = as_[(mb + g) * ASTR + kp];
                af[mi][1] = as_[(mb + g + 8) * ASTR + kp];
                af[mi][2] = as_[(mb + g) * ASTR + kp + 4];
                af[mi][3] = as_[(mb + g + 8) * ASTR + kp + 4];
            }
#pragma unroll
            for (int nj = 0; nj < 4; nj++) {
                const int nbase = wn * 32 + nj * 8;
                bf[nj][0] = bs_[kp * BSTR + nbase + g];
                bf[nj][1] = bs_[(kp + 4) * BSTR + nbase + g];
            }
#pragma unroll
            for (int mi = 0; mi < 2; mi++)
#pragma unroll
                for (int nj = 0; nj < 4; nj++)
                    mma16(acc[mi][nj], af[mi], bf[nj]);
        }
        __syncthreads();
    }

#pragma unroll
    for (int mi = 0; mi < 2; mi++) {
        const int r0 = row0 + wm * 32 + mi * 16 + g;
#pragma unroll
        for (int nj = 0; nj < 4; nj++) {
            const int c = col0 + wn * 32 + nj * 8 + 2 * cc;
            const float b0v = bp[c], b1v = bp[c + 1];
            float v0 = acc[mi][nj][0] + b0v, v1 = acc[mi][nj][1] + b1v;
            float v2 = acc[mi][nj][2] + b0v, v3 = acc[mi][nj][3] + b1v;
            if (relu) {
                v0 = fmaxf(v0, 0.f); v1 = fmaxf(v1, 0.f);
                v2 = fmaxf(v2, 0.f); v3 = fmaxf(v3, 0.f);
            }
            *(float2*)&Cp[(size_t)r0 * nb + c]       = make_float2(v0, v1);
            *(float2*)&Cp[(size_t)(r0 + 8) * nb + c] = make_float2(v2, v3);
        }
    }
}

// ---------------------------------------------------------------------------
// 128-thread 64x64 fp16 GEMM core (shared by gemm64 and gemm_sk).
// A smem [64][16] stride 20; B smem [16 pair-rows][64] stride 72.
// Static smem 2*(1280+1152)*4 = 19456 B.
// ---------------------------------------------------------------------------
#define GEMM64_CORE(AP, WP, LDA, NKV)                                          \
    constexpr int ASTR = 20, BSTR = 72;                                        \
    constexpr int ASZ = 64 * ASTR, BSZ = 16 * BSTR, STG = ASZ + BSZ;           \
    __shared__ uint32_t smg[2 * STG];                                          \
    const int t = threadIdx.x;                                                 \
    const int lane = t & 31, w = t >> 5;                                       \
    const int g = lane >> 2, cc = lane & 3;                                    \
    const int wm = w >> 1, wn = w & 1;                                         \
    const int row0 = blockIdx.y * 64;                                          \
    const int col0 = blockIdx.x * 64;                                          \
    const int ar = t >> 3, ac = (t & 7) << 2;                                  \
    const int bk = t >> 4, bc = (t & 15) << 2;                                 \
    float4 aR[4], bE[2], bO[2];                                                \
    auto loadAB = [&](int k0) {                                                \
        _Pragma("unroll")                                                      \
        for (int i = 0; i < 4; i++)                                            \
            aR[i] = *(const float4*)&AP[(size_t)(row0 + ar + i * 16) * LDA + k0 + ac]; \
        _Pragma("unroll")                                                      \
        for (int i = 0; i < 2; i++) {                                          \
            const int p = bk + i * 8;                                          \
            bE[i] = *(const float4*)&WP[(size_t)(k0 + 2 * p) * 1024 + col0 + bc];     \
            bO[i] = *(const float4*)&WP[(size_t)(k0 + 2 * p + 1) * 1024 + col0 + bc]; \
        }                                                                      \
    };                                                                         \
    auto storeAB = [&](int p) {                                                \
        uint32_t* as_ = smg + p * STG;                                         \
        uint32_t* bs_ = smg + p * STG + ASZ;                                   \
        _Pragma("unroll")                                                      \
        for (int i = 0; i < 4; i++)                                            \
            *(uint2*)&as_[(ar + i * 16) * ASTR + (ac >> 1)] = pk4(aR[i]);      \
        _Pragma("unroll")                                                      \
        for (int i = 0; i < 2; i++)                                            \
            *(uint4*)&bs_[(bk + i * 8) * BSTR + bc] = pkT(bE[i], bO[i]);       \
    };                                                                         \
    float acc[2][4][4] = {};                                                   \
    const int NK = (NKV);                                                      \
    loadAB(0);                                                                 \
    storeAB(0);                                                                \
    if (NK > 1) loadAB(32);                                                    \
    __syncthreads();                                                           \
    for (int it = 0; it < NK; it++) {                                          \
        const int p = it & 1;                                                  \
        if (it + 1 < NK) storeAB(p ^ 1);                                       \
        if (it + 2 < NK) loadAB((it + 2) << 5);                                \
        const uint32_t* as_ = smg + p * STG;                                   \
        const uint32_t* bs_ = smg + p * STG + ASZ;                             \
        uint32_t af[2][4], bf[4][2];                                           \
        _Pragma("unroll")                                                      \
        for (int ksi = 0; ksi < 2; ksi++) {                                    \
            const int kp = ksi * 8 + cc;                                       \
            _Pragma("unroll")                                                  \
            for (int mi = 0; mi < 2; mi++) {                                   \
                const int mb = wm * 32 + mi * 16;                              \
                af[mi][0] = as_[(mb + g) * ASTR + kp];                         \
                af[mi][1] = as_[(mb + g + 8) * ASTR + kp];                     \
                af[mi][2] = as_[(mb + g) * ASTR + kp + 4];                     \
                af[mi][3] = as_[(mb + g + 8) * ASTR + kp + 4];                 \
            }                                                                  \
            _Pragma("unroll")                                                  \
            for (int nj = 0; nj < 4; nj++) {                                   \
                const int nbase = wn * 32 + nj * 8;                            \
                bf[nj][0] = bs_[kp * BSTR + nbase + g];                        \
                bf[nj][1] = bs_[(kp + 4) * BSTR + nbase + g];                  \
            }                                                                  \
            _Pragma("unroll")                                                  \
            for (int mi = 0; mi < 2; mi++)                                     \
                _Pragma("unroll")                                              \
                for (int nj = 0; nj < 4; nj++)                                 \
                    mma16(acc[mi][nj], af[mi], bf[nj]);                        \
        }                                                                      \
        __syncthreads();                                                       \
    }

// C = A[M,1024] @ W[1024,1024] + bias (cross-Q projection).
__global__ __launch_bounds__(128, 4)
void gemm64(const float* __restrict__ A, const float* __restrict__ W,
            const float* __restrict__ bias, float* __restrict__ C)
{
    GEMM64_CORE(A, W, 1024, 32)
#pragma unroll
    for (int mi = 0; mi < 2; mi++) {
        const int r0 = row0 + wm * 32 + mi * 16 + g;
#pragma unroll
        for (int nj = 0; nj < 4; nj++) {
            const int c = col0 + wn * 32 + nj * 8 + 2 * cc;
            const float b0v = bias[c], b1v = bias[c + 1];
            *(float2*)&C[(size_t)r0 * 1024 + c] =
                make_float2(acc[mi][nj][0] + b0v, acc[mi][nj][1] + b1v);
            *(float2*)&C[(size_t)(r0 + 8) * 1024 + c] =
                make_float2(acc[mi][nj][2] + b0v, acc[mi][nj][3] + b1v);
        }
    }
}

// Split-K: parts[z] = A[:, z*Kc:(z+1)*Kc] @ W-slice. Grid (16,16,nsplit).
__global__ __launch_bounds__(128, 4)
void gemm_sk(const float* __restrict__ A, const float* __restrict__ W,
             float* __restrict__ parts, int lda, int Kc)
{
    const int z = blockIdx.z;
    const float* Az = A + (size_t)z * Kc;
    const float* Wz = W + (size_t)z * Kc * 1024;
    float* Cp = parts + (size_t)z * MEG;
    GEMM64_CORE(Az, Wz, lda, (Kc >> 5))
#pragma unroll
    for (int mi = 0; mi < 2; mi++) {
        const int r0 = row0 + wm * 32 + mi * 16 + g;
#pragma unroll
        for (int nj = 0; nj < 4; nj++) {
            const int c = col0 + wn * 32 + nj * 8 + 2 * cc;
            *(float2*)&Cp[(size_t)r0 * 1024 + c] =
                make_float2(acc[mi][nj][0], acc[mi][nj][1]);
            *(float2*)&Cp[(size_t)(r0 + 8) * 1024 + c] =
                make_float2(acc[mi][nj][2], acc[mi][nj][3]);
        }
    }
}

// ---------------------------------------------------------------------------
// Warp-shuffle helpers for one-pass LayerNorm
// ---------------------------------------------------------------------------
__device__ __forceinline__ void block_reduce2(float& s, float& s2,
                                              float* sh1, float* sh2,
                                              int lane, int w)
{
#pragma unroll
    for (int o = 16; o > 0; o >>= 1) {
        s  += __shfl_xor_sync(0xffffffffu, s, o);
        s2 += __shfl_xor_sync(0xffffffffu, s2, o);
    }
    if (lane == 0) { sh1[w] = s; sh2[w] = s2; }
    __syncthreads();
    if (w == 0) {
        float a = (lane < 8) ? sh1[lane] : 0.f;
        float b = (lane < 8) ? sh2[lane] : 0.f;
#pragma unroll
        for (int o = 4; o > 0; o >>= 1) {
            a += __shfl_xor_sync(0xffffffffu, a, o);
            b += __shfl_xor_sync(0xffffffffu, b, o);
        }
        if (lane == 0) { sh1[0] = a; sh2[0] = b; }
    }
    __syncthreads();
}

// y = LayerNorm(x + sum_z parts[z] + bias). One block per row (D=1024).
__global__ __launch_bounds__(256)
void add_ln_red(const float* __restrict__ x, const float* __restrict__ parts,
                int nparts, const float* __restrict__ bias,
                const float* __restrict__ g, const float* __restrict__ bt,
                float* __restrict__ y)
{
    const int row = blockIdx.x;
    const int t = threadIdx.x;
    const int lane = t & 31, w = t >> 5;
    __shared__ float sh1[8], sh2[8];

    float v[4];
#pragma unroll
    for (int i = 0; i < 4; i++) {
        const int c = t + i * 256;
        const size_t idx = (size_t)row * DD + c;
        float a = parts[idx];
        for (int p = 1; p < nparts; p++) a += parts[(size_t)p * MEG + idx];
        v[i] = x[idx] + a + bias[c];
    }
    float s = 0.f, s2 = 0.f;
#pragma unroll
    for (int i = 0; i < 4; i++) { s += v[i]; s2 += v[i] * v[i]; }
    block_reduce2(s, s2, sh1, sh2, lane, w);
    const float mean = sh1[0] * (1.0f / DD);
    const float var  = sh2[0] * (1.0f / DD) - mean * mean;
    const float inv  = rsqrtf(var + EPSF);

#pragma unroll
    for (int i = 0; i < 4; i++) {
        const int c = t + i * 256;
        y[(size_t)row * DD + c] = g[c] * (v[i] - mean) * inv + bt[c];
    }
}

// y = LayerNorm(x).
__global__ __launch_bounds__(256)
void ln_plain(const float* __restrict__ x, const float* __restrict__ g,
              const float* __restrict__ bt, float* __restrict__ y)
{
    const int row = blockIdx.x;
    const int t = threadIdx.x;
    const int lane = t & 31, w = t >> 5;
    __shared__ float sh1[8], sh2[8];

    float v[4];
#pragma unroll
    for (int i = 0; i < 4; i++)
        v[i] = x[(size_t)row * DD + t + i * 256];
    float s = 0.f, s2 = 0.f;
#pragma unroll
    for (int i = 0; i < 4; i++) { s += v[i]; s2 += v[i] * v[i]; }
    block_reduce2(s, s2, sh1, sh2, lane, w);
    const float mean = sh1[0] * (1.0f / DD);
    const float var  = sh2[0] * (1.0f / DD) - mean * mean;
    const float inv  = rsqrtf(var + EPSF);

#pragma unroll
    for (int i = 0; i < 4; i++) {
        const int c = t + i * 256;
        y[(size_t)row * DD + c] = g[c] * (v[i] - mean) * inv + bt[c];
    }
}

// ---------------------------------------------------------------------------
// Scores + mask + softmax. fp16 mma for Q.K^T (both operands packed along d).
// Qs2/Ks2: [64 rows][32 half2] stride 36. S in fp32 smem.
// Dyn smem: (2*64*36 + 64*516)*4 = 150528 B.
// ---------------------------------------------------------------------------
__global__ __launch_bounds__(256)
void attn_scores_f16(const float* __restrict__ qf,
                     const float* __restrict__ kf,
                     const int* __restrict__ mask,
                     int causal,
                     float* __restrict__ attn)
{
    extern __shared__ float smemf[];
    uint32_t* Qs = (uint32_t*)smemf;        // 64*36
    uint32_t* Ks = Qs + 64 * 36;            // 64*36
    float* Ssm = smemf + 2 * 64 * 36;       // 64*516

    const int bh = blockIdx.y, b = bh >> 4, h = bh & 15;
    const int q0 = blockIdx.x * 64;
    const int t = threadIdx.x, lane = t & 31, w = t >> 5;
    const int g = lane >> 2, cc = lane & 3;
    const int qslot = w & 3, kslot = w >> 2;

#pragma unroll
    for (int i = 0; i < 4; i++) {
        const int idx = t + i * 256;
        const int r = idx >> 4, cq = (idx & 15) << 2;
        float4 v = *(const float4*)&qf[(size_t)(b * SS + q0 + r) * DD + h * DKK + cq];
        *(uint2*)&Qs[r * 36 + (cq >> 1)] = pk4(v);
    }

    for (int kt = 0; kt < 8; kt++) {
        __syncthreads();
#pragma unroll
        for (int i = 0; i < 4; i++) {
            const int idx = t + i * 256;
            const int r = idx >> 4, cq = (idx & 15) << 2;
            float4 v = *(const float4*)&kf[(size_t)(b * SS + kt * 64 + r) * DD + h * DKK + cq];
            *(uint2*)&Ks[r * 36 + (cq >> 1)] = pk4(v);
        }
        __syncthreads();

        float acc[4][4] = {};
        uint32_t af[4];
#pragma unroll
        for (int ksi = 0; ksi < 4; ksi++) {
            const int kp = ksi * 8 + cc;
            const int mb = qslot * 16;
            af[0] = Qs[(mb + g) * 36 + kp];
            af[1] = Qs[(mb + g + 8) * 36 + kp];
            af[2] = Qs[(mb + g) * 36 + kp + 4];
            af[3] = Qs[(mb + g + 8) * 36 + kp + 4];
#pragma unroll
            for (int nj = 0; nj < 4; nj++) {
                const int nbase = kslot * 32 + nj * 8;
                uint32_t bf[2];
                bf[0] = Ks[(nbase + g) * 36 + kp];
                bf[1] = Ks[(nbase + g) * 36 + kp + 4];
                mma16(acc[nj], af, bf);
            }
        }
#pragma unroll
        for (int nj = 0; nj < 4; nj++) {
            const int colb = kt * 64 + kslot * 32 + nj * 8 + 2 * cc;
            const int rr = qslot * 16 + g;
            *(float2*)&Ssm[rr * 516 + colb]       = make_float2(acc[nj][0], acc[nj][1]);
            *(float2*)&Ssm[(rr + 8) * 516 + colb] = make_float2(acc[nj][2], acc[nj][3]);
        }
    }
    __syncthreads();

    for (int i = 0; i < 8; i++) {
        const int rloc = w * 8 + i;
        const int q = q0 + rloc;
        float vals[16];
        float mx = -1e30f;
#pragma unroll
        for (int j = 0; j < 16; j++) {
            const int col = lane + j * 32;
            float v = Ssm[rloc * 516 + col] * INV_SCALE;
            const int m = causal ? mask[((size_t)b * SS + q) * SS + col]
                                 : mask[(size_t)b * SS + col];
            if (m == 0) v = -1e9f;
            vals[j] = v;
            mx = fmaxf(mx, v);
        }
#pragma unroll
        for (int o = 16; o > 0; o >>= 1)
            mx = fmaxf(mx, __shfl_xor_sync(0xffffffffu, mx, o));
        float sum = 0.0f;
#pragma unroll
        for (int j = 0; j < 16; j++) {
            vals[j] = expf(vals[j] - mx);
            sum += vals[j];
        }
#pragma unroll
        for (int o = 16; o > 0; o >>= 1)
            sum += __shfl_xor_sync(0xffffffffu, sum, o);
        const float inv = 1.0f / sum;
        float* dst = attn + ((size_t)bh * SS + q) * SS;
#pragma unroll
        for (int j = 0; j < 16; j++)
            dst[lane + j * 32] = vals[j] * inv;
    }
}

// ---------------------------------------------------------------------------
// Context: ctx[q,d] = sum_k attn[q,k] * V[k,d], fp16 mma, double-buffered.
// A smem [64][16] stride 20; V smem [16 pair-rows][64] stride 72.
// ---------------------------------------------------------------------------
__global__ __launch_bounds__(256)
void attn_ctx_f16(const float* __restrict__ attn,
                  const float* __restrict__ vf,
                  float* __restrict__ ctx)
{
    constexpr int ASTR = 20, BSTR = 72;
    constexpr int ASZ = 64 * ASTR, BSZ = 16 * BSTR, STG = ASZ + BSZ;
    __shared__ uint32_t smg[2 * STG];   // 19456 B

    const int bh = blockIdx.y, b = bh >> 4, h = bh & 15;
    const int q0 = blockIdx.x * 64;
    const int t = threadIdx.x, lane = t & 31, w = t >> 5;
    const int g = lane >> 2, cc = lane & 3;
    const int qslot = w & 3, dslot = w >> 2;
    const float* Ap = attn + (size_t)bh * SS * SS;
    const float* Vp = vf + (size_t)b * SS * DD + h * DKK;

    const int ar = t >> 3, ac = (t & 7) << 2;    // A rows ar, ar+32
    const int vr = t >> 4, vc = (t & 15) << 2;   // V pair-row vr (0..15)

    float4 aR[2], vE, vO;
    auto loadAB = [&](int k0) {
#pragma unroll
        for (int i = 0; i < 2; i++)
            aR[i] = *(const float4*)&Ap[(size_t)(q0 + ar + i * 32) * SS + k0 + ac];
        vE = *(const float4*)&Vp[(size_t)(k0 + 2 * vr) * DD + vc];
        vO = *(const float4*)&Vp[(size_t)(k0 + 2 * vr + 1) * DD + vc];
    };
    auto storeAB = [&](int p) {
        uint32_t* as_ = smg + p * STG;
        uint32_t* bs_ = smg + p * STG + ASZ;
#pragma unroll
        for (int i = 0; i < 2; i++)
            *(uint2*)&as_[(ar + i * 32) * ASTR + (ac >> 1)] = pk4(aR[i]);
        *(uint4*)&bs_[vr * BSTR + vc] = pkT(vE, vO);
    };

    float acc[4][4] = {};
    const int NK = 16;   // 512/32
    loadAB(0);
    storeAB(0);
    loadAB(32);
    __syncthreads();

    for (int it = 0; it < NK; it++) {
        const int p = it & 1;
        if (it + 1 < NK) storeAB(p ^ 1);
        if (it + 2 < NK) loadAB((it + 2) << 5);

        const uint32_t* as_ = smg + p * STG;
        const uint32_t* bs_ = smg + p * STG + ASZ;
        uint32_t af[4], bf[2];
#pragma unroll
        for (int ksi = 0; ksi < 2; ksi++) {
            const int kp = ksi * 8 + cc;
            const int mb = qslot * 16;
            af[0] = as_[(mb + g) * ASTR + kp];
            af[1] = as_[(mb + g + 8) * ASTR + kp];
            af[2] = as_[(mb + g) * ASTR + kp + 4];
            af[3] = as_[(mb + g + 8) * ASTR + kp + 4];
#pragma unroll
            for (int nj = 0; nj < 4; nj++) {
                const int nbase = dslot * 32 + nj * 8;
                bf[0] = bs_[kp * BSTR + nbase + g];
                bf[1] = bs_[(kp + 4) * BSTR + nbase + g];
                mma16(acc[nj], af, bf);
            }
        }
        __syncthreads();
    }

    float* Cp = ctx + (size_t)b * SS * DD + h * DKK;
#pragma unroll
    for (int nj = 0; nj < 4; nj++) {
        const int c = dslot * 32 + nj * 8 + 2 * cc;
        const int r = q0 + qslot * 16 + g;
        *(float2*)&Cp[(size_t)r * DD + c]       = make_float2(acc[nj][0], acc[nj][1]);
        *(float2*)&Cp[(size_t)(r + 8) * DD + c] = make_float2(acc[nj][2], acc[nj][3]);
    }
}

// ---------------------------------------------------------------------------
// Host orchestration
// ---------------------------------------------------------------------------
extern "C" void kernel_launch(void* const* d_in, const int* in_sizes, int n_in,
                              void* d_out, int out_size)
{
    const float* src     = (const float*)d_in[0];
    const float* tgt     = (const float*)d_in[1];
    const float* enc_W   = (const float*)d_in[2];
    const float* enc_b   = (const float*)d_in[3];
    const float* enc_W1  = (const float*)d_in[4];
    const float* enc_b1  = (const float*)d_in[5];
    const float* enc_W2  = (const float*)d_in[6];
    const float* enc_b2  = (const float*)d_in[7];
    const float* enc_lng = (const float*)d_in[8];
    const float* enc_lnb = (const float*)d_in[9];
    const float* enc_fg  = (const float*)d_in[10];
    const float* enc_fb  = (const float*)d_in[11];
    const float* dsW     = (const float*)d_in[12];
    const float* dsb     = (const float*)d_in[13];
    const float* dcW     = (const float*)d_in[14];
    const float* dcb     = (const float*)d_in[15];
    const float* dW1     = (const float*)d_in[16];
    const float* db1     = (const float*)d_in[17];
    const float* dW2     = (const float*)d_in[18];
    const float* db2     = (const float*)d_in[19];
    const float* dlng    = (const float*)d_in[20];
    const float* dlnb    = (const float*)d_in[21];
    const float* dfg     = (const float*)d_in[22];
    const float* dfb     = (const float*)d_in[23];
    const int*   src_mask = (const int*)d_in[24];
    const int*   tgt_mask = (const int*)d_in[25];
    float* out = (float*)d_out;

    float* scratch = nullptr;
    cudaGetSymbolAddress((void**)&scratch, g_scratch);

    float* X    = scratch + 0 * MEG;
    float* X2   = scratch + 1 * MEG;
    float* Qb   = scratch + 2 * MEG;   // Q/K/V contiguous for fused QKV gemm
    float* Kb   = scratch + 3 * MEG;
    float* Vb   = scratch + 4 * MEG;
    float* H1   = scratch + 6 * MEG;   // 4M floats
    float* ATT  = scratch + 10 * MEG;  // 8M floats (fallback only)
    float* ENC  = scratch + 18 * MEG;
    float* PRT  = scratch + 19 * MEG;  // 4M floats (split-K partials)
    float* CK   = scratch + 23 * MEG;  // 4M floats (cross K, all layers)
    float* CV   = scratch + 27 * MEG;  // 4M floats (cross V, all layers)
    (void)Kb; (void)Vb;

    const size_t SLAB      = (size_t)BB * HH * SS * SS;
    const size_t OFF_ENC   = (size_t)BB * SS * DD;
    const size_t OFF_SELF  = OFF_ENC + (size_t)LL * SLAB;
    const size_t OFF_CROSS = OFF_SELF + (size_t)LL * SLAB;
    const size_t TOTAL     = OFF_CROSS + (size_t)LL * SLAB;
    const bool full = ((size_t)out_size >= TOTAL);

    const int SM_W = 2 * (64 * 20 + 16 * 136) * 4;  // 27648 B
    cudaFuncSetAttribute(gemm_wide, cudaFuncAttributeMaxDynamicSharedMemorySize, SM_W);
    const size_t SC_SMEM = (size_t)(2 * 64 * 36 + 64 * 516) * sizeof(float);
    cudaFuncSetAttribute(attn_scores_f16,
                         cudaFuncAttributeMaxDynamicSharedMemorySize, (int)SC_SMEM);

    dim3 gQKV(3072 / 128, MROWS / 64);   // 384 CTAs
    dim3 gKVB(4096 / 128, MROWS / 64);   // 512 CTAs (batched cross K or V)
    dim3 gF1(DFFF / 128, MROWS / 64);    // 512 CTAs
    dim3 g64(16, 16);                    // 256 CTAs, 128 thr (cross-Q only)
    dim3 gSK2(16, 16, 2);                // 512 CTAs (O-proj split-K)
    dim3 gSK4(16, 16, 4);                // 1024 CTAs (FFN2 split-K)
    dim3 gS(SS / 64, BB * HH);
    dim3 gC(SS / 64, BB * HH);
    const long long WS = (long long)DD * DD;
    const long long CS = (long long)MEG;

    // ------------------------- Encoder -------------------------
    const float* cur = src;
    for (int l = 0; l < LL; l++) {
        const float* W  = enc_W + (size_t)l * 4 * DD * DD;
        const float* bb = enc_b + (size_t)l * 4 * DD;
        gemm_wide<<<gQKV, 256, SM_W>>>(cur, W, bb, Qb, DD, DD, 0, WS, DD, CS);
        float* adst = full ? out + OFF_ENC + (size_t)l * SLAB : ATT;
        attn_scores_f16<<<gS, 256, SC_SMEM>>>(Qb, Kb, src_mask, 0, adst);
        attn_ctx_f16<<<gC, 256>>>(adst, Vb, Qb);
        gemm_sk<<<gSK2, 128>>>(Qb, W + 3 * DD * DD, PRT, DD, 512);
        add_ln_red<<<MROWS, 256>>>(cur, PRT, 2, bb + 3 * DD,
                                   enc_lng + (size_t)l * 2 * DD,
                                   enc_lnb + (size_t)l * 2 * DD, X2);
        gemm_wide<<<gF1, 256, SM_W>>>(X2, enc_W1 + (size_t)l * DD * DFFF,
                                      enc_b1 + (size_t)l * DFFF, H1, DD, DFFF, 1, 0, 0, 0);
        gemm_sk<<<gSK4, 128>>>(H1, enc_W2 + (size_t)l * DFFF * DD, PRT, DFFF, 1024);
        add_ln_red<<<MROWS, 256>>>(X2, PRT, 4, enc_b2 + (size_t)l * DD,
                                   enc_lng + (size_t)l * 2 * DD + DD,
                                   enc_lnb + (size_t)l * 2 * DD + DD, X);
        cur = X;
    }
    ln_plain<<<MROWS, 256>>>(cur, enc_fg, enc_fb, ENC);

    // Batched cross-attention K/V for all decoder layers (blk = layer)
    gemm_wide<<<gKVB, 256, SM_W>>>(ENC, dcW + (size_t)DD * DD, dcb + DD, CK,
                                   DD, DD, 0, 4LL * DD * DD, 4LL * DD, CS);
    gemm_wide<<<gKVB, 256, SM_W>>>(ENC, dcW + 2 * (size_t)DD * DD, dcb + 2 * DD, CV,
                                   DD, DD, 0, 4LL * DD * DD, 4LL * DD, CS);

    // ------------------------- Decoder -------------------------
    cur = tgt;
    for (int l = 0; l < LL; l++) {
        // self-attention (causal)
        const float* Ws = dsW + (size_t)l * 4 * DD * DD;
        const float* bs = dsb + (size_t)l * 4 * DD;
        gemm_wide<<<gQKV, 256, SM_W>>>(cur, Ws, bs, Qb, DD, DD, 0, WS, DD, CS);
        float* adst = full ? out + OFF_SELF + (size_t)l * SLAB : ATT;
        attn_scores_f16<<<gS, 256, SC_SMEM>>>(Qb, Kb, tgt_mask, 1, adst);
        attn_ctx_f16<<<gC, 256>>>(adst, Vb, Qb);
        gemm_sk<<<gSK2, 128>>>(Qb, Ws + 3 * DD * DD, PRT, DD, 512);
        add_ln_red<<<MROWS, 256>>>(cur, PRT, 2, bs + 3 * DD,
                                   dlng + (size_t)l * 3 * DD,
                                   dlnb + (size_t)l * 3 * DD, X);

        // cross-attention (K/V precomputed, batched)
        const float* Wc = dcW + (size_t)l * 4 * DD * DD;
        const float* bc = dcb + (size_t)l * 4 * DD;
        gemm64<<<g64, 128>>>(X, Wc, bc, Qb);
        adst = full ? out + OFF_CROSS + (size_t)l * SLAB : ATT;
        attn_scores_f16<<<gS, 256, SC_SMEM>>>(Qb, CK + (size_t)l * MEG, src_mask, 0, adst);
        attn_ctx_f16<<<gC, 256>>>(adst, CV + (size_t)l * MEG, Qb);
        gemm_sk<<<gSK2, 128>>>(Qb, Wc + 3 * DD * DD, PRT, DD, 512);
        add_ln_red<<<MROWS, 256>>>(X, PRT, 2, bc + 3 * DD,
                                   dlng + (size_t)l * 3 * DD + DD,
                                   dlnb + (size_t)l * 3 * DD + DD, X2);

        // FFN
        gemm_wide<<<gF1, 256, SM_W>>>(X2, dW1 + (size_t)l * DD * DFFF,
                                      db1 + (size_t)l * DFFF, H1, DD, DFFF, 1, 0, 0, 0);
        gemm_sk<<<gSK4, 128>>>(H1, dW2 + (size_t)l * DFFF * DD, PRT, DFFF, 1024);
        add_ln_red<<<MROWS, 256>>>(X2, PRT, 4, db2 + (size_t)l * DD,
                                   dlng + (size_t)l * 3 * DD + 2 * DD,
                                   dlnb + (size_t)l * 3 * DD + 2 * DD, X);
        cur = X;
    }
    ln_plain<<<MROWS, 256>>>(cur, dfg, dfb, out);
}

// round 10
// speedup vs baseline: 2.2680x; 1.0004x over previous
#include <cuda_runtime.h>
#include <cuda_fp16.h>
#include <cstdint>
#include <cstddef>

// ---------------------------------------------------------------------------
// Transformer forward (encoder-decoder), R10: fp16 activations end-to-end.
// GEMM epilogues write fp16 (QKV/H1/cross-Q/KV); attention + split-K GEMMs
// consume fp16 directly (no per-load conversion). P / residual / LN stay fp32.
// ---------------------------------------------------------------------------

#define BB   2
#define SS   512
#define DD   1024
#define HH   16
#define DKK  64
#define DFFF 4096
#define LL   4
#define MROWS (BB*SS)          // 1024
#define EPSF 1e-5f
#define INV_SCALE 0.125f       // 1/sqrt(DK)

static const size_t MEG = 1u << 20;
__device__ __align__(16) float g_scratch[31u * (1u << 20)];   // 124 MB

// ---------------------------------------------------------------------------
// fp16 helpers
// ---------------------------------------------------------------------------
__device__ __forceinline__ uint32_t pk(float lo, float hi) {
    __half2 h = __floats2half2_rn(lo, hi);
    return *(uint32_t*)&h;
}
__device__ __forceinline__ uint2 pk4(float4 v) {
    return make_uint2(pk(v.x, v.y), pk(v.z, v.w));
}
// pack two k-rows (even e, odd o) x 4 n-cols into 4 half2 (uint4)
__device__ __forceinline__ uint4 pkT(float4 e, float4 o) {
    return make_uint4(pk(e.x, o.x), pk(e.y, o.y), pk(e.z, o.z), pk(e.w, o.w));
}
// interleave two rows of 4 halves (uint2 each) into 4 half2 columns
__device__ __forceinline__ uint4 permT(uint2 e, uint2 o) {
    uint4 r;
    r.x = __byte_perm(e.x, o.x, 0x5410);
    r.y = __byte_perm(e.x, o.x, 0x7632);
    r.z = __byte_perm(e.y, o.y, 0x5410);
    r.w = __byte_perm(e.y, o.y, 0x7632);
    return r;
}
__device__ __forceinline__ void mma16(float* c, const uint32_t* a, const uint32_t* b) {
    asm volatile(
        "mma.sync.aligned.m16n8k16.row.col.f32.f16.f16.f32 "
        "{%0,%1,%2,%3}, {%4,%5,%6,%7}, {%8,%9}, {%0,%1,%2,%3};\n"
        : "+f"(c[0]), "+f"(c[1]), "+f"(c[2]), "+f"(c[3])
        : "r"(a[0]), "r"(a[1]), "r"(a[2]), "r"(a[3]), "r"(b[0]), "r"(b[1]));
}

// ---------------------------------------------------------------------------
// Wide fp16 GEMM (64x128 tile, 256 thr): fp32 A & W in, fp16 C out (+bias,
// optional ReLU). Blocked-N: blk = colg/nb; W += blk*wstride;
// bias += blk*bstride; C += blk*cstride (half elements); row strides nb.
// ---------------------------------------------------------------------------
__global__ __launch_bounds__(256, 2)
void gemm_wide(const float* __restrict__ A, const float* __restrict__ W,
               const float* __restrict__ bias, __half* __restrict__ C,
               int K, int nb, int relu,
               long long wstride, long long bstride, long long cstride)
{
    constexpr int ASTR = 20, BSTR = 136;
    constexpr int ASZ = 64 * ASTR, BSZ = 16 * BSTR, STG = ASZ + BSZ;
    extern __shared__ uint32_t smg[];

    const int t = threadIdx.x;
    const int lane = t & 31, w = t >> 5;
    const int g = lane >> 2, cc = lane & 3;
    const int wm = w >> 2, wn = w & 3;
    const int row0 = blockIdx.y * 64;
    const int colg = blockIdx.x * 128;
    const int blk  = colg / nb;
    const int col0 = colg - blk * nb;
    const float* Wp = W + (size_t)blk * (size_t)wstride;
    const float* bp = bias + (size_t)blk * (size_t)bstride;
    __half* Cp = C + (size_t)blk * (size_t)cstride;

    const int ar = t >> 3, ac = (t & 7) << 2;
    const int bk0 = t >> 5, bc = (t & 31) << 2;

    float4 aR[2], bE[2], bO[2];
    auto loadAB = [&](int k0) {
#pragma unroll
        for (int i = 0; i < 2; i++)
            aR[i] = *(const float4*)&A[(size_t)(row0 + ar + i * 32) * K + k0 + ac];
#pragma unroll
        for (int i = 0; i < 2; i++) {
            const int p = bk0 + i * 8;
            bE[i] = *(const float4*)&Wp[(size_t)(k0 + 2 * p) * nb + col0 + bc];
            bO[i] = *(const float4*)&Wp[(size_t)(k0 + 2 * p + 1) * nb + col0 + bc];
        }
    };
    auto storeAB = [&](int p) {
        uint32_t* as_ = smg + p * STG;
        uint32_t* bs_ = smg + p * STG + ASZ;
#pragma unroll
        for (int i = 0; i < 2; i++)
            *(uint2*)&as_[(ar + i * 32) * ASTR + (ac >> 1)] = pk4(aR[i]);
#pragma unroll
        for (int i = 0; i < 2; i++)
            *(uint4*)&bs_[(bk0 + i * 8) * BSTR + bc] = pkT(bE[i], bO[i]);
    };

    float acc[2][4][4] = {};
    const int NK = K >> 5;
    loadAB(0);
    storeAB(0);
    if (NK > 1) loadAB(32);
    __syncthreads();

    for (int it = 0; it < NK; it++) {
        const int p = it & 1;
        if (it + 1 < NK) storeAB(p ^ 1);
        if (it + 2 < NK) loadAB((it + 2) << 5);

        const uint32_t* as_ = smg + p * STG;
        const uint32_t* bs_ = smg + p * STG + ASZ;
        uint32_t af[2][4], bf[4][2];
#pragma unroll
        for (int ksi = 0; ksi < 2; ksi++) {
            const int kp = ksi * 8 + cc;
#pragma unroll
            for (int mi = 0; mi < 2; mi++) {
                const int mb = wm * 32 + mi * 16;
                af[mi][0] = as_[(mb + g) * ASTR + kp];
                af[mi][1] = as_[(mb + g + 8) * ASTR + kp];
                af[mi][2] = as_[(mb + g) * ASTR + kp + 4];
                af[mi][3] = as_[(mb + g + 8) * ASTR + kp + 4];
            }
#pragma unroll
            for (int nj = 0; nj < 4; nj++) {
                const int nbase = wn * 32 + nj * 8;
                bf[nj][0] = bs_[kp * BSTR + nbase + g];
                bf[nj][1] = bs_[(kp + 4) * BSTR + nbase + g];
            }
#pragma unroll
            for (int mi = 0; mi < 2; mi++)
#pragma unroll
                for (int nj = 0; nj < 4; nj++)
                    mma16(acc[mi][nj], af[mi], bf[nj]);
        }
        __syncthreads();
    }

#pragma unroll
    for (int mi = 0; mi < 2; mi++) {
        const int r0 = row0 + wm * 32 + mi * 16 + g;
#pragma unroll
        for (int nj = 0; nj < 4; nj++) {
            const int c = col0 + wn * 32 + nj * 8 + 2 * cc;
            const float b0v = bp[c], b1v = bp[c + 1];
            float v0 = acc[mi][nj][0] + b0v, v1 = acc[mi][nj][1] + b1v;
            float v2 = acc[mi][nj][2] + b0v, v3 = acc[mi][nj][3] + b1v;
            if (relu) {
                v0 = fmaxf(v0, 0.f); v1 = fmaxf(v1, 0.f);
                v2 = fmaxf(v2, 0.f); v3 = fmaxf(v3, 0.f);
            }
            *(uint32_t*)&Cp[(size_t)r0 * nb + c]       = pk(v0, v1);
            *(uint32_t*)&Cp[(size_t)(r0 + 8) * nb + c] = pk(v2, v3);
        }
    }
}

// ---------------------------------------------------------------------------
// gemm64: fp32 A @ fp32 W -> fp16 C (+bias). 128 thr, 64x64 tile.
// Used only for cross-attention Q projection (A = LN output, fp32).
// ---------------------------------------------------------------------------
__global__ __launch_bounds__(128, 4)
void gemm64(const float* __restrict__ A, const float* __restrict__ W,
            const float* __restrict__ bias, __half* __restrict__ C)
{
    constexpr int ASTR = 20, BSTR = 72;
    constexpr int ASZ = 64 * ASTR, BSZ = 16 * BSTR, STG = ASZ + BSZ;
    __shared__ uint32_t smg[2 * STG];

    const int t = threadIdx.x;
    const int lane = t & 31, w = t >> 5;
    const int g = lane >> 2, cc = lane & 3;
    const int wm = w >> 1, wn = w & 1;
    const int row0 = blockIdx.y * 64;
    const int col0 = blockIdx.x * 64;
    const int ar = t >> 3, ac = (t & 7) << 2;
    const int bk = t >> 4, bc = (t & 15) << 2;

    float4 aR[4], bE[2], bO[2];
    auto loadAB = [&](int k0) {
#pragma unroll
        for (int i = 0; i < 4; i++)
            aR[i] = *(const float4*)&A[(size_t)(row0 + ar + i * 16) * 1024 + k0 + ac];
#pragma unroll
        for (int i = 0; i < 2; i++) {
            const int p = bk + i * 8;
            bE[i] = *(const float4*)&W[(size_t)(k0 + 2 * p) * 1024 + col0 + bc];
            bO[i] = *(const float4*)&W[(size_t)(k0 + 2 * p + 1) * 1024 + col0 + bc];
        }
    };
    auto storeAB = [&](int p) {
        uint32_t* as_ = smg + p * STG;
        uint32_t* bs_ = smg + p * STG + ASZ;
#pragma unroll
        for (int i = 0; i < 4; i++)
            *(uint2*)&as_[(ar + i * 16) * ASTR + (ac >> 1)] = pk4(aR[i]);
#pragma unroll
        for (int i = 0; i < 2; i++)
            *(uint4*)&bs_[(bk + i * 8) * BSTR + bc] = pkT(bE[i], bO[i]);
    };

    float acc[2][4][4] = {};
    const int NK = 32;
    loadAB(0);
    storeAB(0);
    loadAB(32);
    __syncthreads();

    for (int it = 0; it < NK; it++) {
        const int p = it & 1;
        if (it + 1 < NK) storeAB(p ^ 1);
        if (it + 2 < NK) loadAB((it + 2) << 5);

        const uint32_t* as_ = smg + p * STG;
        const uint32_t* bs_ = smg + p * STG + ASZ;
        uint32_t af[2][4], bf[4][2];
#pragma unroll
        for (int ksi = 0; ksi < 2; ksi++) {
            const int kp = ksi * 8 + cc;
#pragma unroll
            for (int mi = 0; mi < 2; mi++) {
                const int mb = wm * 32 + mi * 16;
                af[mi][0] = as_[(mb + g) * ASTR + kp];
                af[mi][1] = as_[(mb + g + 8) * ASTR + kp];
                af[mi][2] = as_[(mb + g) * ASTR + kp + 4];
                af[mi][3] = as_[(mb + g + 8) * ASTR + kp + 4];
            }
#pragma unroll
            for (int nj = 0; nj < 4; nj++) {
                const int nbase = wn * 32 + nj * 8;
                bf[nj][0] = bs_[kp * BSTR + nbase + g];
                bf[nj][1] = bs_[(kp + 4) * BSTR + nbase + g];
            }
#pragma unroll
            for (int mi = 0; mi < 2; mi++)
#pragma unroll
                for (int nj = 0; nj < 4; nj++)
                    mma16(acc[mi][nj], af[mi], bf[nj]);
        }
        __syncthreads();
    }

#pragma unroll
    for (int mi = 0; mi < 2; mi++) {
        const int r0 = row0 + wm * 32 + mi * 16 + g;
#pragma unroll
        for (int nj = 0; nj < 4; nj++) {
            const int c = col0 + wn * 32 + nj * 8 + 2 * cc;
            const float b0v = bias[c], b1v = bias[c + 1];
            *(uint32_t*)&C[(size_t)r0 * 1024 + c] =
                pk(acc[mi][nj][0] + b0v, acc[mi][nj][1] + b1v);
            *(uint32_t*)&C[(size_t)(r0 + 8) * 1024 + c] =
                pk(acc[mi][nj][2] + b0v, acc[mi][nj][3] + b1v);
        }
    }
}

// ---------------------------------------------------------------------------
// Split-K GEMM: fp16 A @ fp32 W -> fp32 partials. Grid (16,16,nsplit).
// A loads are direct fp16 copies (no conversion).
// ---------------------------------------------------------------------------
__global__ __launch_bounds__(128, 4)
void gemm_sk(const __half* __restrict__ A, const float* __restrict__ W,
             float* __restrict__ parts, int lda, int Kc)
{
    constexpr int ASTR = 20, BSTR = 72;
    constexpr int ASZ = 64 * ASTR, BSZ = 16 * BSTR, STG = ASZ + BSZ;
    __shared__ uint32_t smg[2 * STG];

    const int z = blockIdx.z;
    const __half* Az = A + (size_t)z * Kc;
    const float* Wz = W + (size_t)z * Kc * 1024;
    float* Cp = parts + (size_t)z * MEG;

    const int t = threadIdx.x;
    const int lane = t & 31, w = t >> 5;
    const int g = lane >> 2, cc = lane & 3;
    const int wm = w >> 1, wn = w & 1;
    const int row0 = blockIdx.y * 64;
    const int col0 = blockIdx.x * 64;
    const int ar = t >> 3, ac = (t & 7) << 2;
    const int bk = t >> 4, bc = (t & 15) << 2;

    uint2 aR[4];
    float4 bE[2], bO[2];
    auto loadAB = [&](int k0) {
#pragma unroll
        for (int i = 0; i < 4; i++)
            aR[i] = *(const uint2*)&Az[(size_t)(row0 + ar + i * 16) * lda + k0 + ac];
#pragma unroll
        for (int i = 0; i < 2; i++) {
            const int p = bk + i * 8;
            bE[i] = *(const float4*)&Wz[(size_t)(k0 + 2 * p) * 1024 + col0 + bc];
            bO[i] = *(const float4*)&Wz[(size_t)(k0 + 2 * p + 1) * 1024 + col0 + bc];
        }
    };
    auto storeAB = [&](int p) {
        uint32_t* as_ = smg + p * STG;
        uint32_t* bs_ = smg + p * STG + ASZ;
#pragma unroll
        for (int i = 0; i < 4; i++)
            *(uint2*)&as_[(ar + i * 16) * ASTR + (ac >> 1)] = aR[i];
#pragma unroll
        for (int i = 0; i < 2; i++)
            *(uint4*)&bs_[(bk + i * 8) * BSTR + bc] = pkT(bE[i], bO[i]);
    };

    float acc[2][4][4] = {};
    const int NK = Kc >> 5;
    loadAB(0);
    storeAB(0);
    if (NK > 1) loadAB(32);
    __syncthreads();

    for (int it = 0; it < NK; it++) {
        const int p = it & 1;
        if (it + 1 < NK) storeAB(p ^ 1);
        if (it + 2 < NK) loadAB((it + 2) << 5);

        const uint32_t* as_ = smg + p * STG;
        const uint32_t* bs_ = smg + p * STG + ASZ;
        uint32_t af[2][4], bf[4][2];
#pragma unroll
        for (int ksi = 0; ksi < 2; ksi++) {
            const int kp = ksi * 8 + cc;
#pragma unroll
            for (int mi = 0; mi < 2; mi++) {
                const int mb = wm * 32 + mi * 16;
                af[mi][0] = as_[(mb + g) * ASTR + kp];
                af[mi][1] = as_[(mb + g + 8) * ASTR + kp];
                af[mi][2] = as_[(mb + g) * ASTR + kp + 4];
                af[mi][3] = as_[(mb + g + 8) * ASTR + kp + 4];
            }
#pragma unroll
            for (int nj = 0; nj < 4; nj++) {
                const int nbase = wn * 32 + nj * 8;
                bf[nj][0] = bs_[kp * BSTR + nbase + g];
                bf[nj][1] = bs_[(kp + 4) * BSTR + nbase + g];
            }
#pragma unroll
            for (int mi = 0; mi < 2; mi++)
#pragma unroll
                for (int nj = 0; nj < 4; nj++)
                    mma16(acc[mi][nj], af[mi], bf[nj]);
        }
        __syncthreads();
    }

#pragma unroll
    for (int mi = 0; mi < 2; mi++) {
        const int r0 = row0 + wm * 32 + mi * 16 + g;
#pragma unroll
        for (int nj = 0; nj < 4; nj++) {
            const int c = col0 + wn * 32 + nj * 8 + 2 * cc;
            *(float2*)&Cp[(size_t)r0 * 1024 + c] =
                make_float2(acc[mi][nj][0], acc[mi][nj][1]);
            *(float2*)&Cp[(size_t)(r0 + 8) * 1024 + c] =
                make_float2(acc[mi][nj][2], acc[mi][nj][3]);
        }
    }
}

// ---------------------------------------------------------------------------
// Warp-shuffle helpers for one-pass LayerNorm
// ---------------------------------------------------------------------------
__device__ __forceinline__ void block_reduce2(float& s, float& s2,
                                              float* sh1, float* sh2,
                                              int lane, int w)
{
#pragma unroll
    for (int o = 16; o > 0; o >>= 1) {
        s  += __shfl_xor_sync(0xffffffffu, s, o);
        s2 += __shfl_xor_sync(0xffffffffu, s2, o);
    }
    if (lane == 0) { sh1[w] = s; sh2[w] = s2; }
    __syncthreads();
    if (w == 0) {
        float a = (lane < 8) ? sh1[lane] : 0.f;
        float b = (lane < 8) ? sh2[lane] : 0.f;
#pragma unroll
        for (int o = 4; o > 0; o >>= 1) {
            a += __shfl_xor_sync(0xffffffffu, a, o);
            b += __shfl_xor_sync(0xffffffffu, b, o);
        }
        if (lane == 0) { sh1[0] = a; sh2[0] = b; }
    }
    __syncthreads();
}

// y = LayerNorm(x + sum_z parts[z] + bias). One block per row (D=1024).
__global__ __launch_bounds__(256)
void add_ln_red(const float* __restrict__ x, const float* __restrict__ parts,
                int nparts, const float* __restrict__ bias,
                const float* __restrict__ g, const float* __restrict__ bt,
                float* __restrict__ y)
{
    const int row = blockIdx.x;
    const int t = threadIdx.x;
    const int lane = t & 31, w = t >> 5;
    __shared__ float sh1[8], sh2[8];

    float v[4];
#pragma unroll
    for (int i = 0; i < 4; i++) {
        const int c = t + i * 256;
        const size_t idx = (size_t)row * DD + c;
        float a = parts[idx];
        for (int p = 1; p < nparts; p++) a += parts[(size_t)p * MEG + idx];
        v[i] = x[idx] + a + bias[c];
    }
    float s = 0.f, s2 = 0.f;
#pragma unroll
    for (int i = 0; i < 4; i++) { s += v[i]; s2 += v[i] * v[i]; }
    block_reduce2(s, s2, sh1, sh2, lane, w);
    const float mean = sh1[0] * (1.0f / DD);
    const float var  = sh2[0] * (1.0f / DD) - mean * mean;
    const float inv  = rsqrtf(var + EPSF);

#pragma unroll
    for (int i = 0; i < 4; i++) {
        const int c = t + i * 256;
        y[(size_t)row * DD + c] = g[c] * (v[i] - mean) * inv + bt[c];
    }
}

// y = LayerNorm(x).
__global__ __launch_bounds__(256)
void ln_plain(const float* __restrict__ x, const float* __restrict__ g,
              const float* __restrict__ bt, float* __restrict__ y)
{
    const int row = blockIdx.x;
    const int t = threadIdx.x;
    const int lane = t & 31, w = t >> 5;
    __shared__ float sh1[8], sh2[8];

    float v[4];
#pragma unroll
    for (int i = 0; i < 4; i++)
        v[i] = x[(size_t)row * DD + t + i * 256];
    float s = 0.f, s2 = 0.f;
#pragma unroll
    for (int i = 0; i < 4; i++) { s += v[i]; s2 += v[i] * v[i]; }
    block_reduce2(s, s2, sh1, sh2, lane, w);
    const float mean = sh1[0] * (1.0f / DD);
    const float var  = sh2[0] * (1.0f / DD) - mean * mean;
    const float inv  = rsqrtf(var + EPSF);

#pragma unroll
    for (int i = 0; i < 4; i++) {
        const int c = t + i * 256;
        y[(size_t)row * DD + c] = g[c] * (v[i] - mean) * inv + bt[c];
    }
}

// ---------------------------------------------------------------------------
// Scores + mask + softmax. fp16 Q/K inputs -> direct smem copies, fp16 mma.
// Qs/Ks: [64 rows][32 half2] stride 36. S in fp32 smem.
// Dyn smem: (2*64*36 + 64*516)*4 = 150528 B.
// ---------------------------------------------------------------------------
__global__ __launch_bounds__(256)
void attn_scores_f16(const __half* __restrict__ qf,
                     const __half* __restrict__ kf,
                     const int* __restrict__ mask,
                     int causal,
                     float* __restrict__ attn)
{
    extern __shared__ float smemf[];
    uint32_t* Qs = (uint32_t*)smemf;        // 64*36
    uint32_t* Ks = Qs + 64 * 36;            // 64*36
    float* Ssm = smemf + 2 * 64 * 36;       // 64*516

    const int bh = blockIdx.y, b = bh >> 4, h = bh & 15;
    const int q0 = blockIdx.x * 64;
    const int t = threadIdx.x, lane = t & 31, w = t >> 5;
    const int g = lane >> 2, cc = lane & 3;
    const int qslot = w & 3, kslot = w >> 2;

    // Q tile: 64 rows x 64 halves; 8 uint4 chunks per row, 512 total
#pragma unroll
    for (int i = 0; i < 2; i++) {
        const int idx = t + i * 256;
        const int r = idx >> 3, ch = idx & 7;
        uint4 v = *(const uint4*)&qf[(size_t)(b * SS + q0 + r) * DD + h * DKK + ch * 8];
        *(uint4*)&Qs[r * 36 + ch * 4] = v;
    }

    // hoist padding-mask (row-invariant) loads
    int mreg[16];
    if (!causal) {
#pragma unroll
        for (int j = 0; j < 16; j++)
            mreg[j] = mask[(size_t)b * SS + lane + j * 32];
    }

    for (int kt = 0; kt < 8; kt++) {
        __syncthreads();
#pragma unroll
        for (int i = 0; i < 2; i++) {
            const int idx = t + i * 256;
            const int r = idx >> 3, ch = idx & 7;
            uint4 v = *(const uint4*)&kf[(size_t)(b * SS + kt * 64 + r) * DD + h * DKK + ch * 8];
            *(uint4*)&Ks[r * 36 + ch * 4] = v;
        }
        __syncthreads();

        float acc[4][4] = {};
        uint32_t af[4];
#pragma unroll
        for (int ksi = 0; ksi < 4; ksi++) {
            const int kp = ksi * 8 + cc;
            const int mb = qslot * 16;
            af[0] = Qs[(mb + g) * 36 + kp];
            af[1] = Qs[(mb + g + 8) * 36 + kp];
            af[2] = Qs[(mb + g) * 36 + kp + 4];
            af[3] = Qs[(mb + g + 8) * 36 + kp + 4];
#pragma unroll
            for (int nj = 0; nj < 4; nj++) {
                const int nbase = kslot * 32 + nj * 8;
                uint32_t bf[2];
                bf[0] = Ks[(nbase + g) * 36 + kp];
                bf[1] = Ks[(nbase + g) * 36 + kp + 4];
                mma16(acc[nj], af, bf);
            }
        }
#pragma unroll
        for (int nj = 0; nj < 4; nj++) {
            const int colb = kt * 64 + kslot * 32 + nj * 8 + 2 * cc;
            const int rr = qslot * 16 + g;
            *(float2*)&Ssm[rr * 516 + colb]       = make_float2(acc[nj][0], acc[nj][1]);
            *(float2*)&Ssm[(rr + 8) * 516 + colb] = make_float2(acc[nj][2], acc[nj][3]);
        }
    }
    __syncthreads();

    for (int i = 0; i < 8; i++) {
        const int rloc = w * 8 + i;
        const int q = q0 + rloc;
        float vals[16];
        float mx = -1e30f;
#pragma unroll
        for (int j = 0; j < 16; j++) {
            const int col = lane + j * 32;
            float v = Ssm[rloc * 516 + col] * INV_SCALE;
            const int m = causal ? mask[((size_t)b * SS + q) * SS + col] : mreg[j];
            if (m == 0) v = -1e9f;
            vals[j] = v;
            mx = fmaxf(mx, v);
        }
#pragma unroll
        for (int o = 16; o > 0; o >>= 1)
            mx = fmaxf(mx, __shfl_xor_sync(0xffffffffu, mx, o));
        float sum = 0.0f;
#pragma unroll
        for (int j = 0; j < 16; j++) {
            vals[j] = expf(vals[j] - mx);
            sum += vals[j];
        }
#pragma unroll
        for (int o = 16; o > 0; o >>= 1)
            sum += __shfl_xor_sync(0xffffffffu, sum, o);
        const float inv = 1.0f / sum;
        float* dst = attn + ((size_t)bh * SS + q) * SS;
#pragma unroll
        for (int j = 0; j < 16; j++)
            dst[lane + j * 32] = vals[j] * inv;
    }
}

// ---------------------------------------------------------------------------
// Context: ctx[q,d] = sum_k attn[q,k] * V[k,d]. P fp32, V fp16, ctx fp16 out.
// Double-buffered, K-step 32.
// ---------------------------------------------------------------------------
__global__ __launch_bounds__(256)
void attn_ctx_f16(const float* __restrict__ attn,
                  const __half* __restrict__ vf,
                  __half* __restrict__ ctx)
{
    constexpr int ASTR = 20, BSTR = 72;
    constexpr int ASZ = 64 * ASTR, BSZ = 16 * BSTR, STG = ASZ + BSZ;
    __shared__ uint32_t smg[2 * STG];   // 19456 B

    const int bh = blockIdx.y, b = bh >> 4, h = bh & 15;
    const int q0 = blockIdx.x * 64;
    const int t = threadIdx.x, lane = t & 31, w = t >> 5;
    const int g = lane >> 2, cc = lane & 3;
    const int qslot = w & 3, dslot = w >> 2;
    const float* Ap = attn + (size_t)bh * SS * SS;
    const __half* Vp = vf + (size_t)b * SS * DD + h * DKK;

    const int ar = t >> 3, ac = (t & 7) << 2;    // A rows ar, ar+32
    const int vr = t >> 4, vc = (t & 15) << 2;   // V pair-row vr (0..15)

    float4 aR[2];
    uint2 vE, vO;
    auto loadAB = [&](int k0) {
#pragma unroll
        for (int i = 0; i < 2; i++)
            aR[i] = *(const float4*)&Ap[(size_t)(q0 + ar + i * 32) * SS + k0 + ac];
        vE = *(const uint2*)&Vp[(size_t)(k0 + 2 * vr) * DD + vc];
        vO = *(const uint2*)&Vp[(size_t)(k0 + 2 * vr + 1) * DD + vc];
    };
    auto storeAB = [&](int p) {
        uint32_t* as_ = smg + p * STG;
        uint32_t* bs_ = smg + p * STG + ASZ;
#pragma unroll
        for (int i = 0; i < 2; i++)
            *(uint2*)&as_[(ar + i * 32) * ASTR + (ac >> 1)] = pk4(aR[i]);
        *(uint4*)&bs_[vr * BSTR + vc] = permT(vE, vO);
    };

    float acc[4][4] = {};
    const int NK = 16;   // 512/32
    loadAB(0);
    storeAB(0);
    loadAB(32);
    __syncthreads();

    for (int it = 0; it < NK; it++) {
        const int p = it & 1;
        if (it + 1 < NK) storeAB(p ^ 1);
        if (it + 2 < NK) loadAB((it + 2) << 5);

        const uint32_t* as_ = smg + p * STG;
        const uint32_t* bs_ = smg + p * STG + ASZ;
        uint32_t af[4], bf[2];
#pragma unroll
        for (int ksi = 0; ksi < 2; ksi++) {
            const int kp = ksi * 8 + cc;
            const int mb = qslot * 16;
            af[0] = as_[(mb + g) * ASTR + kp];
            af[1] = as_[(mb + g + 8) * ASTR + kp];
            af[2] = as_[(mb + g) * ASTR + kp + 4];
            af[3] = as_[(mb + g + 8) * ASTR + kp + 4];
#pragma unroll
            for (int nj = 0; nj < 4; nj++) {
                const int nbase = dslot * 32 + nj * 8;
                bf[0] = bs_[kp * BSTR + nbase + g];
                bf[1] = bs_[(kp + 4) * BSTR + nbase + g];
                mma16(acc[nj], af, bf);
            }
        }
        __syncthreads();
    }

    __half* Cp = ctx + (size_t)b * SS * DD + h * DKK;
#pragma unroll
    for (int nj = 0; nj < 4; nj++) {
        const int c = dslot * 32 + nj * 8 + 2 * cc;
        const int r = q0 + qslot * 16 + g;
        *(uint32_t*)&Cp[(size_t)r * DD + c]       = pk(acc[nj][0], acc[nj][1]);
        *(uint32_t*)&Cp[(size_t)(r + 8) * DD + c] = pk(acc[nj][2], acc[nj][3]);
    }
}

// ---------------------------------------------------------------------------
// Host orchestration
// ---------------------------------------------------------------------------
extern "C" void kernel_launch(void* const* d_in, const int* in_sizes, int n_in,
                              void* d_out, int out_size)
{
    const float* src     = (const float*)d_in[0];
    const float* tgt     = (const float*)d_in[1];
    const float* enc_W   = (const float*)d_in[2];
    const float* enc_b   = (const float*)d_in[3];
    const float* enc_W1  = (const float*)d_in[4];
    const float* enc_b1  = (const float*)d_in[5];
    const float* enc_W2  = (const float*)d_in[6];
    const float* enc_b2  = (const float*)d_in[7];
    const float* enc_lng = (const float*)d_in[8];
    const float* enc_lnb = (const float*)d_in[9];
    const float* enc_fg  = (const float*)d_in[10];
    const float* enc_fb  = (const float*)d_in[11];
    const float* dsW     = (const float*)d_in[12];
    const float* dsb     = (const float*)d_in[13];
    const float* dcW     = (const float*)d_in[14];
    const float* dcb     = (const float*)d_in[15];
    const float* dW1     = (const float*)d_in[16];
    const float* db1     = (const float*)d_in[17];
    const float* dW2     = (const float*)d_in[18];
    const float* db2     = (const float*)d_in[19];
    const float* dlng    = (const float*)d_in[20];
    const float* dlnb    = (const float*)d_in[21];
    const float* dfg     = (const float*)d_in[22];
    const float* dfb     = (const float*)d_in[23];
    const int*   src_mask = (const int*)d_in[24];
    const int*   tgt_mask = (const int*)d_in[25];
    float* out = (float*)d_out;

    float* scratch = nullptr;
    cudaGetSymbolAddress((void**)&scratch, g_scratch);

    float* X    = scratch + 0 * MEG;
    float* X2   = scratch + 1 * MEG;
    __half* Qh  = (__half*)(scratch + 2 * MEG);   // Q,K,V: 3M halves (6 MB)
    __half* H1h = (__half*)(scratch + 6 * MEG);   // 4M halves (8 MB)
    float* ATT  = scratch + 10 * MEG;             // 8M floats (fallback only)
    float* ENC  = scratch + 18 * MEG;
    float* PRT  = scratch + 19 * MEG;             // 4M floats (split-K partials)
    __half* CKh = (__half*)(scratch + 23 * MEG);  // 4M halves (cross K, all layers)
    __half* CVh = (__half*)(scratch + 27 * MEG);  // 4M halves (cross V, all layers)

    const size_t SLAB      = (size_t)BB * HH * SS * SS;
    const size_t OFF_ENC   = (size_t)BB * SS * DD;
    const size_t OFF_SELF  = OFF_ENC + (size_t)LL * SLAB;
    const size_t OFF_CROSS = OFF_SELF + (size_t)LL * SLAB;
    const size_t TOTAL     = OFF_CROSS + (size_t)LL * SLAB;
    const bool full = ((size_t)out_size >= TOTAL);

    const int SM_W = 2 * (64 * 20 + 16 * 136) * 4;  // 27648 B
    cudaFuncSetAttribute(gemm_wide, cudaFuncAttributeMaxDynamicSharedMemorySize, SM_W);
    const size_t SC_SMEM = (size_t)(2 * 64 * 36 + 64 * 516) * sizeof(float);
    cudaFuncSetAttribute(attn_scores_f16,
                         cudaFuncAttributeMaxDynamicSharedMemorySize, (int)SC_SMEM);

    dim3 gQKV(3072 / 128, MROWS / 64);   // 384 CTAs
    dim3 gKVB(4096 / 128, MROWS / 64);   // 512 CTAs (batched cross K or V)
    dim3 gF1(DFFF / 128, MROWS / 64);    // 512 CTAs
    dim3 g64(16, 16);                    // 256 CTAs, 128 thr (cross-Q only)
    dim3 gSK2(16, 16, 2);                // 512 CTAs (O-proj split-K)
    dim3 gSK4(16, 16, 4);                // 1024 CTAs (FFN2 split-K)
    dim3 gS(SS / 64, BB * HH);
    dim3 gC(SS / 64, BB * HH);
    const long long WS = (long long)DD * DD;
    const long long CS = (long long)MEG;   // element (half) stride between blocks

    // ------------------------- Encoder -------------------------
    const float* cur = src;
    for (int l = 0; l < LL; l++) {
        const float* W  = enc_W + (size_t)l * 4 * DD * DD;
        const float* bb = enc_b + (size_t)l * 4 * DD;
        gemm_wide<<<gQKV, 256, SM_W>>>(cur, W, bb, Qh, DD, DD, 0, WS, DD, CS);
        float* adst = full ? out + OFF_ENC + (size_t)l * SLAB : ATT;
        attn_scores_f16<<<gS, 256, SC_SMEM>>>(Qh, Qh + MEG, src_mask, 0, adst);
        attn_ctx_f16<<<gC, 256>>>(adst, Qh + 2 * MEG, Qh);
        gemm_sk<<<gSK2, 128>>>(Qh, W + 3 * DD * DD, PRT, DD, 512);
        add_ln_red<<<MROWS, 256>>>(cur, PRT, 2, bb + 3 * DD,
                                   enc_lng + (size_t)l * 2 * DD,
                                   enc_lnb + (size_t)l * 2 * DD, X2);
        gemm_wide<<<gF1, 256, SM_W>>>(X2, enc_W1 + (size_t)l * DD * DFFF,
                                      enc_b1 + (size_t)l * DFFF, H1h, DD, DFFF, 1, 0, 0, 0);
        gemm_sk<<<gSK4, 128>>>(H1h, enc_W2 + (size_t)l * DFFF * DD, PRT, DFFF, 1024);
        add_ln_red<<<MROWS, 256>>>(X2, PRT, 4, enc_b2 + (size_t)l * DD,
                                   enc_lng + (size_t)l * 2 * DD + DD,
                                   enc_lnb + (size_t)l * 2 * DD + DD, X);
        cur = X;
    }
    ln_plain<<<MROWS, 256>>>(cur, enc_fg, enc_fb, ENC);

    // Batched cross-attention K/V for all decoder layers (blk = layer)
    gemm_wide<<<gKVB, 256, SM_W>>>(ENC, dcW + (size_t)DD * DD, dcb + DD, CKh,
                                   DD, DD, 0, 4LL * DD * DD, 4LL * DD, CS);
    gemm_wide<<<gKVB, 256, SM_W>>>(ENC, dcW + 2 * (size_t)DD * DD, dcb + 2 * DD, CVh,
                                   DD, DD, 0, 4LL * DD * DD, 4LL * DD, CS);

    // ------------------------- Decoder -------------------------
    cur = tgt;
    for (int l = 0; l < LL; l++) {
        // self-attention (causal)
        const float* Ws = dsW + (size_t)l * 4 * DD * DD;
        const float* bs = dsb + (size_t)l * 4 * DD;
        gemm_wide<<<gQKV, 256, SM_W>>>(cur, Ws, bs, Qh, DD, DD, 0, WS, DD, CS);
        float* adst = full ? out + OFF_SELF + (size_t)l * SLAB : ATT;
        attn_scores_f16<<<gS, 256, SC_SMEM>>>(Qh, Qh + MEG, tgt_mask, 1, adst);
        attn_ctx_f16<<<gC, 256>>>(adst, Qh + 2 * MEG, Qh);
        gemm_sk<<<gSK2, 128>>>(Qh, Ws + 3 * DD * DD, PRT, DD, 512);
        add_ln_red<<<MROWS, 256>>>(cur, PRT, 2, bs + 3 * DD,
                                   dlng + (size_t)l * 3 * DD,
                                   dlnb + (size_t)l * 3 * DD, X);

        // cross-attention (K/V precomputed, batched)
        const float* Wc = dcW + (size_t)l * 4 * DD * DD;
        const float* bc = dcb + (size_t)l * 4 * DD;
        gemm64<<<g64, 128>>>(X, Wc, bc, Qh);
        adst = full ? out + OFF_CROSS + (size_t)l * SLAB : ATT;
        attn_scores_f16<<<gS, 256, SC_SMEM>>>(Qh, CKh + (size_t)l * MEG, src_mask, 0, adst);
        attn_ctx_f16<<<gC, 256>>>(adst, CVh + (size_t)l * MEG, Qh);
        gemm_sk<<<gSK2, 128>>>(Qh, Wc + 3 * DD * DD, PRT, DD, 512);
        add_ln_red<<<MROWS, 256>>>(X, PRT, 2, bc + 3 * DD,
                                   dlng + (size_t)l * 3 * DD + DD,
                                   dlnb + (size_t)l * 3 * DD + DD, X2);

        // FFN
        gemm_wide<<<gF1, 256, SM_W>>>(X2, dW1 + (size_t)l * DD * DFFF,
                                      db1 + (size_t)l * DFFF, H1h, DD, DFFF, 1, 0, 0, 0);
        gemm_sk<<<gSK4, 128>>>(H1h, dW2 + (size_t)l * DFFF * DD, PRT, DFFF, 1024);
        add_ln_red<<<MROWS, 256>>>(X2, PRT, 4, db2 + (size_t)l * DD,
                                   dlng + (size_t)l * 3 * DD + 2 * DD,
                                   dlnb + (size_t)l * 3 * DD + 2 * DD, X);
        cur = X;
    }
    ln_plain<<<MROWS, 256>>>(cur, dfg, dfb, out);
}

// round 11
// speedup vs baseline: 2.3644x; 1.0425x over previous
#include <cuda_runtime.h>
#include <cuda_fp16.h>
#include <cstdint>
#include <cstddef>

// ---------------------------------------------------------------------------
// Transformer forward, R11: fp16 weights (pre-transposed [N][K]) + fp16
// activations, cp.async 4-stage GEMM pipelines. Attention kernels as R10.
// ---------------------------------------------------------------------------

#define BB   2
#define SS   512
#define DD   1024
#define HH   16
#define DKK  64
#define DFFF 4096
#define LL   4
#define MROWS (BB*SS)          // 1024
#define EPSF 1e-5f
#define INV_SCALE 0.125f       // 1/sqrt(DK)

static const size_t MEG = 1u << 20;
__device__ __align__(16) float g_scratch[84u * (1u << 20)];   // 336 MB

// ---------------------------------------------------------------------------
// helpers
// ---------------------------------------------------------------------------
__device__ __forceinline__ uint32_t pk(float lo, float hi) {
    __half2 h = __floats2half2_rn(lo, hi);
    return *(uint32_t*)&h;
}
__device__ __forceinline__ uint2 pk4(float4 v) {
    return make_uint2(pk(v.x, v.y), pk(v.z, v.w));
}
__device__ __forceinline__ uint4 permT(uint2 e, uint2 o) {
    uint4 r;
    r.x = __byte_perm(e.x, o.x, 0x5410);
    r.y = __byte_perm(e.x, o.x, 0x7632);
    r.z = __byte_perm(e.y, o.y, 0x5410);
    r.w = __byte_perm(e.y, o.y, 0x7632);
    return r;
}
__device__ __forceinline__ void mma16(float* c, const uint32_t* a, const uint32_t* b) {
    asm volatile(
        "mma.sync.aligned.m16n8k16.row.col.f32.f16.f16.f32 "
        "{%0,%1,%2,%3}, {%4,%5,%6,%7}, {%8,%9}, {%0,%1,%2,%3};\n"
        : "+f"(c[0]), "+f"(c[1]), "+f"(c[2]), "+f"(c[3])
        : "r"(a[0]), "r"(a[1]), "r"(a[2]), "r"(a[3]), "r"(b[0]), "r"(b[1]));
}
__device__ __forceinline__ uint32_t smaddr(const void* p) {
    return (uint32_t)__cvta_generic_to_shared(p);
}
__device__ __forceinline__ void cpa16(uint32_t dsm, const void* gsrc) {
    asm volatile("cp.async.cg.shared.global [%0], [%1], 16;" :: "r"(dsm), "l"(gsrc));
}
#define CP_COMMIT() asm volatile("cp.async.commit_group;")
#define CP_WAIT2()  asm volatile("cp.async.wait_group 2;")

// ---------------------------------------------------------------------------
// Prepass: fp32 -> fp16 convert (n multiple of 1024)
// ---------------------------------------------------------------------------
__global__ __launch_bounds__(256)
void cvt16(const float* __restrict__ x, __half* __restrict__ y, int n)
{
    const int i = (blockIdx.x * 256 + threadIdx.x) * 4;
    if (i < n) {
        float4 v = *(const float4*)&x[i];
        *(uint2*)&y[i] = pk4(v);
    }
}

// Prepass: batched transpose+convert  W[K,N] fp32 -> Wt[N,K] fp16.
// Grid (N/32, K/32, batch); block 256 (32x8).
__global__ __launch_bounds__(256)
void tcvt(const float* __restrict__ src, __half* __restrict__ dst, int K, int N)
{
    const size_t zoff = (size_t)blockIdx.z * K * N;
    src += zoff; dst += zoff;
    __shared__ float tile[32][33];
    const int tx = threadIdx.x & 31, ty = threadIdx.x >> 5;
    const int x0 = blockIdx.x * 32, y0 = blockIdx.y * 32;
#pragma unroll
    for (int j = 0; j < 4; j++)
        tile[ty + j * 8][tx] = src[(size_t)(y0 + ty + j * 8) * N + x0 + tx];
    __syncthreads();
#pragma unroll
    for (int j = 0; j < 4; j++)
        dst[(size_t)(x0 + ty + j * 8) * K + y0 + tx] =
            __float2half_rn(tile[tx][ty + j * 8]);
}

// ---------------------------------------------------------------------------
// Wide GEMM: fp16 A[M][K] @ fp16 Wt[N][K] -> fp16 C (+fp32 bias, opt ReLU).
// 64x128 tile, 256 thr (8 warps 2x4, 32x32 tiles), cp.async 4-stage.
// Blocked-N: blk = colg/nb; Wt += blk*wstride; bias += blk*bstride;
// C += blk*cstride. Row stride of Wt = K. Dyn smem 4*3840*4 = 61440 B.
// ---------------------------------------------------------------------------
__global__ __launch_bounds__(256, 2)
void gemm_wide_h(const __half* __restrict__ A, const __half* __restrict__ Wt,
                 const float* __restrict__ bias, __half* __restrict__ C,
                 int K, int nb, int relu,
                 long long wstride, long long bstride, long long cstride)
{
    constexpr int ASTR = 20, BSTR = 20;
    constexpr int ASZ = 64 * ASTR, BSZ = 128 * BSTR, STG = ASZ + BSZ;  // 3840
    extern __shared__ uint32_t smg[];

    const int t = threadIdx.x, lane = t & 31, w = t >> 5;
    const int g = lane >> 2, cc = lane & 3;
    const int wm = w >> 2, wn = w & 3;
    const int row0 = blockIdx.y * 64;
    const int colg = blockIdx.x * 128;
    const int blk  = colg / nb;
    const int col0 = colg - blk * nb;
    const __half* Wp = Wt + (size_t)blk * (size_t)wstride;
    const float* bp = bias + (size_t)blk * (size_t)bstride;
    __half* Cp = C + (size_t)blk * (size_t)cstride;

    const uint32_t sb = smaddr(smg);
    const int arow = t >> 2, ach = t & 3;

    auto issue = [&](int it) {
        const int k0 = it << 5;
        const uint32_t base = sb + (uint32_t)((it & 3) * STG) * 4u;
        cpa16(base + (uint32_t)(arow * ASTR + ach * 4) * 4u,
              A + (size_t)(row0 + arow) * K + k0 + ach * 8);
#pragma unroll
        for (int i = 0; i < 2; i++) {
            const int idx = t + i * 256;
            const int br = idx >> 2, bch = idx & 3;
            cpa16(base + (uint32_t)(ASZ + br * BSTR + bch * 4) * 4u,
                  Wp + (size_t)(col0 + br) * K + k0 + bch * 8);
        }
    };

    float acc[2][4][4] = {};
    const int NK = K >> 5;
    issue(0); CP_COMMIT();
    issue(1); CP_COMMIT();
    issue(2); CP_COMMIT();

    for (int it = 0; it < NK; it++) {
        CP_WAIT2();
        __syncthreads();
        if (it + 3 < NK) issue(it + 3);
        CP_COMMIT();

        const uint32_t* as_ = smg + (it & 3) * STG;
        const uint32_t* bs_ = smg + (it & 3) * STG + ASZ;
        uint32_t af[2][4], bf[4][2];
#pragma unroll
        for (int ksi = 0; ksi < 2; ksi++) {
            const int kp = ksi * 8 + cc;
#pragma unroll
            for (int mi = 0; mi < 2; mi++) {
                const int mb = wm * 32 + mi * 16;
                af[mi][0] = as_[(mb + g) * ASTR + kp];
                af[mi][1] = as_[(mb + g + 8) * ASTR + kp];
                af[mi][2] = as_[(mb + g) * ASTR + kp + 4];
                af[mi][3] = as_[(mb + g + 8) * ASTR + kp + 4];
            }
#pragma unroll
            for (int nj = 0; nj < 4; nj++) {
                const int nrow = wn * 32 + nj * 8 + g;
                bf[nj][0] = bs_[nrow * BSTR + kp];
                bf[nj][1] = bs_[nrow * BSTR + kp + 4];
            }
#pragma unroll
            for (int mi = 0; mi < 2; mi++)
#pragma unroll
                for (int nj = 0; nj < 4; nj++)
                    mma16(acc[mi][nj], af[mi], bf[nj]);
        }
    }

#pragma unroll
    for (int mi = 0; mi < 2; mi++) {
        const int r0 = row0 + wm * 32 + mi * 16 + g;
#pragma unroll
        for (int nj = 0; nj < 4; nj++) {
            const int c = col0 + wn * 32 + nj * 8 + 2 * cc;
            const float b0v = bp[c], b1v = bp[c + 1];
            float v0 = acc[mi][nj][0] + b0v, v1 = acc[mi][nj][1] + b1v;
            float v2 = acc[mi][nj][2] + b0v, v3 = acc[mi][nj][3] + b1v;
            if (relu) {
                v0 = fmaxf(v0, 0.f); v1 = fmaxf(v1, 0.f);
                v2 = fmaxf(v2, 0.f); v3 = fmaxf(v3, 0.f);
            }
            *(uint32_t*)&Cp[(size_t)r0 * nb + c]       = pk(v0, v1);
            *(uint32_t*)&Cp[(size_t)(r0 + 8) * nb + c] = pk(v2, v3);
        }
    }
}

// ---------------------------------------------------------------------------
// 128-thread 64x64 cp.async core (fp16 A[.][lda], fp16 Wt rows [.][ldw]).
// Static smem 4*2560*4 = 40960 B.
// ---------------------------------------------------------------------------
#define GEMMH64_CORE(AP, WP, LDA, LDW, NKV)                                     \
    constexpr int ASTR = 20, BSTR = 20;                                         \
    constexpr int ASZ = 64 * ASTR, BSZ = 64 * BSTR, STG = ASZ + BSZ;            \
    __shared__ uint32_t smg[4 * STG];                                           \
    const int t = threadIdx.x, lane = t & 31, w = t >> 5;                       \
    const int g = lane >> 2, cc = lane & 3;                                     \
    const int wm = w >> 1, wn = w & 1;                                          \
    const int row0 = blockIdx.y * 64;                                           \
    const int col0 = blockIdx.x * 64;                                           \
    const uint32_t sb = smaddr(smg);                                            \
    auto issue = [&](int it) {                                                  \
        const int k0 = it << 5;                                                 \
        const uint32_t base = sb + (uint32_t)((it & 3) * STG) * 4u;             \
        _Pragma("unroll")                                                       \
        for (int i = 0; i < 2; i++) {                                           \
            const int idx = t + i * 128;                                        \
            const int r = idx >> 2, ch = idx & 3;                               \
            cpa16(base + (uint32_t)(r * ASTR + ch * 4) * 4u,                    \
                  AP + (size_t)(row0 + r) * LDA + k0 + ch * 8);                 \
            cpa16(base + (uint32_t)(ASZ + r * BSTR + ch * 4) * 4u,              \
                  WP + (size_t)(col0 + r) * LDW + k0 + ch * 8);                 \
        }                                                                       \
    };                                                                          \
    float acc[2][4][4] = {};                                                    \
    const int NK = (NKV);                                                       \
    issue(0); CP_COMMIT();                                                      \
    issue(1); CP_COMMIT();                                                      \
    issue(2); CP_COMMIT();                                                      \
    for (int it = 0; it < NK; it++) {                                           \
        CP_WAIT2();                                                             \
        __syncthreads();                                                        \
        if (it + 3 < NK) issue(it + 3);                                         \
        CP_COMMIT();                                                            \
        const uint32_t* as_ = smg + (it & 3) * STG;                             \
        const uint32_t* bs_ = smg + (it & 3) * STG + ASZ;                       \
        uint32_t af[2][4], bf[4][2];                                            \
        _Pragma("unroll")                                                       \
        for (int ksi = 0; ksi < 2; ksi++) {                                     \
            const int kp = ksi * 8 + cc;                                        \
            _Pragma("unroll")                                                   \
            for (int mi = 0; mi < 2; mi++) {                                    \
                const int mb = wm * 32 + mi * 16;                               \
                af[mi][0] = as_[(mb + g) * ASTR + kp];                          \
                af[mi][1] = as_[(mb + g + 8) * ASTR + kp];                      \
                af[mi][2] = as_[(mb + g) * ASTR + kp + 4];                      \
                af[mi][3] = as_[(mb + g + 8) * ASTR + kp + 4];                  \
            }                                                                   \
            _Pragma("unroll")                                                   \
            for (int nj = 0; nj < 4; nj++) {                                    \
                const int nrow = wn * 32 + nj * 8 + g;                          \
                bf[nj][0] = bs_[nrow * BSTR + kp];                              \
                bf[nj][1] = bs_[nrow * BSTR + kp + 4];                          \
            }                                                                   \
            _Pragma("unroll")                                                   \
            for (int mi = 0; mi < 2; mi++)                                      \
                _Pragma("unroll")                                               \
                for (int nj = 0; nj < 4; nj++)                                  \
                    mma16(acc[mi][nj], af[mi], bf[nj]);                         \
        }                                                                       \
    }

// cross-Q: fp16 A @ Wt + bias -> fp16 C.
__global__ __launch_bounds__(128, 4)
void gemm_h64(const __half* __restrict__ A, const __half* __restrict__ Wt,
              const float* __restrict__ bias, __half* __restrict__ C)
{
    GEMMH64_CORE(A, Wt, 1024, 1024, 32)
#pragma unroll
    for (int mi = 0; mi < 2; mi++) {
        const int r0 = row0 + wm * 32 + mi * 16 + g;
#pragma unroll
        for (int nj = 0; nj < 4; nj++) {
            const int c = col0 + wn * 32 + nj * 8 + 2 * cc;
            const float b0v = bias[c], b1v = bias[c + 1];
            *(uint32_t*)&C[(size_t)r0 * 1024 + c] =
                pk(acc[mi][nj][0] + b0v, acc[mi][nj][1] + b1v);
            *(uint32_t*)&C[(size_t)(r0 + 8) * 1024 + c] =
                pk(acc[mi][nj][2] + b0v, acc[mi][nj][3] + b1v);
        }
    }
}

// Split-K: parts[z] = A[:, zKc:(z+1)Kc] @ Wt-cols-slice. Grid (16,16,nsplit).
__global__ __launch_bounds__(128, 4)
void gemm_sk_h(const __half* __restrict__ A, const __half* __restrict__ Wt,
               float* __restrict__ parts, int lda, int ldw, int Kc)
{
    const int z = blockIdx.z;
    const __half* Az = A + (size_t)z * Kc;
    const __half* Wz = Wt + (size_t)z * Kc;
    float* Cp = parts + (size_t)z * MEG;
    GEMMH64_CORE(Az, Wz, lda, ldw, (Kc >> 5))
#pragma unroll
    for (int mi = 0; mi < 2; mi++) {
        const int r0 = row0 + wm * 32 + mi * 16 + g;
#pragma unroll
        for (int nj = 0; nj < 4; nj++) {
            const int c = col0 + wn * 32 + nj * 8 + 2 * cc;
            *(float2*)&Cp[(size_t)r0 * 1024 + c] =
                make_float2(acc[mi][nj][0], acc[mi][nj][1]);
            *(float2*)&Cp[(size_t)(r0 + 8) * 1024 + c] =
                make_float2(acc[mi][nj][2], acc[mi][nj][3]);
        }
    }
}

// ---------------------------------------------------------------------------
// LayerNorm (one-pass). Writes fp32 y and optional fp16 yh.
// ---------------------------------------------------------------------------
__device__ __forceinline__ void block_reduce2(float& s, float& s2,
                                              float* sh1, float* sh2,
                                              int lane, int w)
{
#pragma unroll
    for (int o = 16; o > 0; o >>= 1) {
        s  += __shfl_xor_sync(0xffffffffu, s, o);
        s2 += __shfl_xor_sync(0xffffffffu, s2, o);
    }
    if (lane == 0) { sh1[w] = s; sh2[w] = s2; }
    __syncthreads();
    if (w == 0) {
        float a = (lane < 8) ? sh1[lane] : 0.f;
        float b = (lane < 8) ? sh2[lane] : 0.f;
#pragma unroll
        for (int o = 4; o > 0; o >>= 1) {
            a += __shfl_xor_sync(0xffffffffu, a, o);
            b += __shfl_xor_sync(0xffffffffu, b, o);
        }
        if (lane == 0) { sh1[0] = a; sh2[0] = b; }
    }
    __syncthreads();
}

__global__ __launch_bounds__(256)
void add_ln_red(const float* __restrict__ x, const float* __restrict__ parts,
                int nparts, const float* __restrict__ bias,
                const float* __restrict__ g, const float* __restrict__ bt,
                float* __restrict__ y, __half* __restrict__ yh)
{
    const int row = blockIdx.x;
    const int t = threadIdx.x;
    const int lane = t & 31, w = t >> 5;
    __shared__ float sh1[8], sh2[8];

    float v[4];
#pragma unroll
    for (int i = 0; i < 4; i++) {
        const int c = t + i * 256;
        const size_t idx = (size_t)row * DD + c;
        float a = parts[idx];
        for (int p = 1; p < nparts; p++) a += parts[(size_t)p * MEG + idx];
        v[i] = x[idx] + a + bias[c];
    }
    float s = 0.f, s2 = 0.f;
#pragma unroll
    for (int i = 0; i < 4; i++) { s += v[i]; s2 += v[i] * v[i]; }
    block_reduce2(s, s2, sh1, sh2, lane, w);
    const float mean = sh1[0] * (1.0f / DD);
    const float var  = sh2[0] * (1.0f / DD) - mean * mean;
    const float inv  = rsqrtf(var + EPSF);

    float r[4];
#pragma unroll
    for (int i = 0; i < 4; i++) {
        const int c = t + i * 256;
        r[i] = g[c] * (v[i] - mean) * inv + bt[c];
        y[(size_t)row * DD + c] = r[i];
    }
    if (yh) {
#pragma unroll
        for (int i = 0; i < 4; i++)
            yh[(size_t)row * DD + t + i * 256] = __float2half_rn(r[i]);
    }
}

__global__ __launch_bounds__(256)
void ln_plain(const float* __restrict__ x, const float* __restrict__ g,
              const float* __restrict__ bt, float* __restrict__ y,
              __half* __restrict__ yh)
{
    const int row = blockIdx.x;
    const int t = threadIdx.x;
    const int lane = t & 31, w = t >> 5;
    __shared__ float sh1[8], sh2[8];

    float v[4];
#pragma unroll
    for (int i = 0; i < 4; i++)
        v[i] = x[(size_t)row * DD + t + i * 256];
    float s = 0.f, s2 = 0.f;
#pragma unroll
    for (int i = 0; i < 4; i++) { s += v[i]; s2 += v[i] * v[i]; }
    block_reduce2(s, s2, sh1, sh2, lane, w);
    const float mean = sh1[0] * (1.0f / DD);
    const float var  = sh2[0] * (1.0f / DD) - mean * mean;
    const float inv  = rsqrtf(var + EPSF);

    float r[4];
#pragma unroll
    for (int i = 0; i < 4; i++) {
        const int c = t + i * 256;
        r[i] = g[c] * (v[i] - mean) * inv + bt[c];
        y[(size_t)row * DD + c] = r[i];
    }
    if (yh) {
#pragma unroll
        for (int i = 0; i < 4; i++)
            yh[(size_t)row * DD + t + i * 256] = __float2half_rn(r[i]);
    }
}

// ---------------------------------------------------------------------------
// Scores + mask + softmax (fp16 Q/K direct copies, fp16 mma). As R10.
// ---------------------------------------------------------------------------
__global__ __launch_bounds__(256)
void attn_scores_f16(const __half* __restrict__ qf,
                     const __half* __restrict__ kf,
                     const int* __restrict__ mask,
                     int causal,
                     float* __restrict__ attn)
{
    extern __shared__ float smemf[];
    uint32_t* Qs = (uint32_t*)smemf;        // 64*36
    uint32_t* Ks = Qs + 64 * 36;            // 64*36
    float* Ssm = smemf + 2 * 64 * 36;       // 64*516

    const int bh = blockIdx.y, b = bh >> 4, h = bh & 15;
    const int q0 = blockIdx.x * 64;
    const int t = threadIdx.x, lane = t & 31, w = t >> 5;
    const int g = lane >> 2, cc = lane & 3;
    const int qslot = w & 3, kslot = w >> 2;

#pragma unroll
    for (int i = 0; i < 2; i++) {
        const int idx = t + i * 256;
        const int r = idx >> 3, ch = idx & 7;
        uint4 v = *(const uint4*)&qf[(size_t)(b * SS + q0 + r) * DD + h * DKK + ch * 8];
        *(uint4*)&Qs[r * 36 + ch * 4] = v;
    }

    int mreg[16];
    if (!causal) {
#pragma unroll
        for (int j = 0; j < 16; j++)
            mreg[j] = mask[(size_t)b * SS + lane + j * 32];
    }

    for (int kt = 0; kt < 8; kt++) {
        __syncthreads();
#pragma unroll
        for (int i = 0; i < 2; i++) {
            const int idx = t + i * 256;
            const int r = idx >> 3, ch = idx & 7;
            uint4 v = *(const uint4*)&kf[(size_t)(b * SS + kt * 64 + r) * DD + h * DKK + ch * 8];
            *(uint4*)&Ks[r * 36 + ch * 4] = v;
        }
        __syncthreads();

        float acc[4][4] = {};
        uint32_t af[4];
#pragma unroll
        for (int ksi = 0; ksi < 4; ksi++) {
            const int kp = ksi * 8 + cc;
            const int mb = qslot * 16;
            af[0] = Qs[(mb + g) * 36 + kp];
            af[1] = Qs[(mb + g + 8) * 36 + kp];
            af[2] = Qs[(mb + g) * 36 + kp + 4];
            af[3] = Qs[(mb + g + 8) * 36 + kp + 4];
#pragma unroll
            for (int nj = 0; nj < 4; nj++) {
                const int nbase = kslot * 32 + nj * 8;
                uint32_t bf[2];
                bf[0] = Ks[(nbase + g) * 36 + kp];
                bf[1] = Ks[(nbase + g) * 36 + kp + 4];
                mma16(acc[nj], af, bf);
            }
        }
#pragma unroll
        for (int nj = 0; nj < 4; nj++) {
            const int colb = kt * 64 + kslot * 32 + nj * 8 + 2 * cc;
            const int rr = qslot * 16 + g;
            *(float2*)&Ssm[rr * 516 + colb]       = make_float2(acc[nj][0], acc[nj][1]);
            *(float2*)&Ssm[(rr + 8) * 516 + colb] = make_float2(acc[nj][2], acc[nj][3]);
        }
    }
    __syncthreads();

    for (int i = 0; i < 8; i++) {
        const int rloc = w * 8 + i;
        const int q = q0 + rloc;
        float vals[16];
        float mx = -1e30f;
#pragma unroll
        for (int j = 0; j < 16; j++) {
            const int col = lane + j * 32;
            float v = Ssm[rloc * 516 + col] * INV_SCALE;
            const int m = causal ? mask[((size_t)b * SS + q) * SS + col] : mreg[j];
            if (m == 0) v = -1e9f;
            vals[j] = v;
            mx = fmaxf(mx, v);
        }
#pragma unroll
        for (int o = 16; o > 0; o >>= 1)
            mx = fmaxf(mx, __shfl_xor_sync(0xffffffffu, mx, o));
        float sum = 0.0f;
#pragma unroll
        for (int j = 0; j < 16; j++) {
            vals[j] = expf(vals[j] - mx);
            sum += vals[j];
        }
#pragma unroll
        for (int o = 16; o > 0; o >>= 1)
            sum += __shfl_xor_sync(0xffffffffu, sum, o);
        const float inv = 1.0f / sum;
        float* dst = attn + ((size_t)bh * SS + q) * SS;
#pragma unroll
        for (int j = 0; j < 16; j++)
            dst[lane + j * 32] = vals[j] * inv;
    }
}

// ---------------------------------------------------------------------------
// Context: P fp32 @ V fp16 -> ctx fp16. Double-buffered K-step 32. As R10.
// ---------------------------------------------------------------------------
__global__ __launch_bounds__(256)
void attn_ctx_f16(const float* __restrict__ attn,
                  const __half* __restrict__ vf,
                  __half* __restrict__ ctx)
{
    constexpr int ASTR = 20, BSTR = 72;
    constexpr int ASZ = 64 * ASTR, BSZ = 16 * BSTR, STG = ASZ + BSZ;
    __shared__ uint32_t smg[2 * STG];

    const int bh = blockIdx.y, b = bh >> 4, h = bh & 15;
    const int q0 = blockIdx.x * 64;
    const int t = threadIdx.x, lane = t & 31, w = t >> 5;
    const int g = lane >> 2, cc = lane & 3;
    const int qslot = w & 3, dslot = w >> 2;
    const float* Ap = attn + (size_t)bh * SS * SS;
    const __half* Vp = vf + (size_t)b * SS * DD + h * DKK;

    const int ar = t >> 3, ac = (t & 7) << 2;
    const int vr = t >> 4, vc = (t & 15) << 2;

    float4 aR[2];
    uint2 vE, vO;
    auto loadAB = [&](int k0) {
#pragma unroll
        for (int i = 0; i < 2; i++)
            aR[i] = *(const float4*)&Ap[(size_t)(q0 + ar + i * 32) * SS + k0 + ac];
        vE = *(const uint2*)&Vp[(size_t)(k0 + 2 * vr) * DD + vc];
        vO = *(const uint2*)&Vp[(size_t)(k0 + 2 * vr + 1) * DD + vc];
    };
    auto storeAB = [&](int p) {
        uint32_t* as_ = smg + p * STG;
        uint32_t* bs_ = smg + p * STG + ASZ;
#pragma unroll
        for (int i = 0; i < 2; i++)
            *(uint2*)&as_[(ar + i * 32) * ASTR + (ac >> 1)] = pk4(aR[i]);
        *(uint4*)&bs_[vr * BSTR + vc] = permT(vE, vO);
    };

    float acc[4][4] = {};
    const int NK = 16;
    loadAB(0);
    storeAB(0);
    loadAB(32);
    __syncthreads();

    for (int it = 0; it < NK; it++) {
        const int p = it & 1;
        if (it + 1 < NK) storeAB(p ^ 1);
        if (it + 2 < NK) loadAB((it + 2) << 5);

        const uint32_t* as_ = smg + p * STG;
        const uint32_t* bs_ = smg + p * STG + ASZ;
        uint32_t af[4], bf[2];
#pragma unroll
        for (int ksi = 0; ksi < 2; ksi++) {
            const int kp = ksi * 8 + cc;
            const int mb = qslot * 16;
            af[0] = as_[(mb + g) * ASTR + kp];
            af[1] = as_[(mb + g + 8) * ASTR + kp];
            af[2] = as_[(mb + g) * ASTR + kp + 4];
            af[3] = as_[(mb + g + 8) * ASTR + kp + 4];
#pragma unroll
            for (int nj = 0; nj < 4; nj++) {
                const int nbase = dslot * 32 + nj * 8;
                bf[0] = bs_[kp * BSTR + nbase + g];
                bf[1] = bs_[(kp + 4) * BSTR + nbase + g];
                mma16(acc[nj], af, bf);
            }
        }
        __syncthreads();
    }

    __half* Cp = ctx + (size_t)b * SS * DD + h * DKK;
#pragma unroll
    for (int nj = 0; nj < 4; nj++) {
        const int c = dslot * 32 + nj * 8 + 2 * cc;
        const int r = q0 + qslot * 16 + g;
        *(uint32_t*)&Cp[(size_t)r * DD + c]       = pk(acc[nj][0], acc[nj][1]);
        *(uint32_t*)&Cp[(size_t)(r + 8) * DD + c] = pk(acc[nj][2], acc[nj][3]);
    }
}

// ---------------------------------------------------------------------------
// Host orchestration
// ---------------------------------------------------------------------------
extern "C" void kernel_launch(void* const* d_in, const int* in_sizes, int n_in,
                              void* d_out, int out_size)
{
    const float* src     = (const float*)d_in[0];
    const float* tgt     = (const float*)d_in[1];
    const float* enc_W   = (const float*)d_in[2];
    const float* enc_b   = (const float*)d_in[3];
    const float* enc_W1  = (const float*)d_in[4];
    const float* enc_b1  = (const float*)d_in[5];
    const float* enc_W2  = (const float*)d_in[6];
    const float* enc_b2  = (const float*)d_in[7];
    const float* enc_lng = (const float*)d_in[8];
    const float* enc_lnb = (const float*)d_in[9];
    const float* enc_fg  = (const float*)d_in[10];
    const float* enc_fb  = (const float*)d_in[11];
    const float* dsW     = (const float*)d_in[12];
    const float* dsb     = (const float*)d_in[13];
    const float* dcW     = (const float*)d_in[14];
    const float* dcb     = (const float*)d_in[15];
    const float* dW1     = (const float*)d_in[16];
    const float* db1     = (const float*)d_in[17];
    const float* dW2     = (const float*)d_in[18];
    const float* db2     = (const float*)d_in[19];
    const float* dlng    = (const float*)d_in[20];
    const float* dlnb    = (const float*)d_in[21];
    const float* dfg     = (const float*)d_in[22];
    const float* dfb     = (const float*)d_in[23];
    const int*   src_mask = (const int*)d_in[24];
    const int*   tgt_mask = (const int*)d_in[25];
    float* out = (float*)d_out;

    float* scratch = nullptr;
    cudaGetSymbolAddress((void**)&scratch, g_scratch);

    float*  X    = scratch + 0 * MEG;
    float*  X2   = scratch + 1 * MEG;
    __half* Qh   = (__half*)(scratch + 2 * MEG);   // Q,K,V: 3M halves
    __half* H1h  = (__half*)(scratch + 4 * MEG);   // 4M halves
    __half* Xh   = (__half*)(scratch + 6 * MEG);   // 1M halves
    __half* X2h  = (__half*)(scratch + 7 * MEG);
    __half* srch = (__half*)(scratch + 8 * MEG);
    __half* tgth = (__half*)(scratch + 9 * MEG);
    __half* ENCh = (__half*)(scratch + 10 * MEG);
    float*  ATT  = scratch + 11 * MEG;             // 8M floats (fallback)
    float*  ENC  = scratch + 19 * MEG;
    float*  PRT  = scratch + 20 * MEG;             // 4M floats
    __half* CKh  = (__half*)(scratch + 24 * MEG);  // 4M halves
    __half* CVh  = (__half*)(scratch + 26 * MEG);  // 4M halves
    __half* WH   = (__half*)(scratch + 28 * MEG);  // 112M halves

    const size_t M1 = MEG;
    __half* encWt = WH;                 // [L*4][1024][1024]
    __half* dsWt  = WH + 16 * M1;
    __half* dcWt  = WH + 32 * M1;
    __half* eW1t  = WH + 48 * M1;       // [L][4096][1024]
    __half* eW2t  = WH + 64 * M1;       // [L][1024][4096]
    __half* dW1t  = WH + 80 * M1;
    __half* dW2t  = WH + 96 * M1;

    const size_t SLAB      = (size_t)BB * HH * SS * SS;
    const size_t OFF_ENC   = (size_t)BB * SS * DD;
    const size_t OFF_SELF  = OFF_ENC + (size_t)LL * SLAB;
    const size_t OFF_CROSS = OFF_SELF + (size_t)LL * SLAB;
    const size_t TOTAL     = OFF_CROSS + (size_t)LL * SLAB;
    const bool full = ((size_t)out_size >= TOTAL);

    const int SM_W = 4 * (64 * 20 + 128 * 20) * 4;  // 61440 B
    cudaFuncSetAttribute(gemm_wide_h, cudaFuncAttributeMaxDynamicSharedMemorySize, SM_W);
    const size_t SC_SMEM = (size_t)(2 * 64 * 36 + 64 * 516) * sizeof(float);
    cudaFuncSetAttribute(attn_scores_f16,
                         cudaFuncAttributeMaxDynamicSharedMemorySize, (int)SC_SMEM);

    // ---------------- Prepass: weights -> fp16 [N][K]; src/tgt -> fp16 ------
    cvt16<<<1024, 256>>>(src, srch, MROWS * DD);
    cvt16<<<1024, 256>>>(tgt, tgth, MROWS * DD);
    tcvt<<<dim3(32, 32, 16), 256>>>(enc_W, encWt, 1024, 1024);
    tcvt<<<dim3(32, 32, 16), 256>>>(dsW, dsWt, 1024, 1024);
    tcvt<<<dim3(32, 32, 16), 256>>>(dcW, dcWt, 1024, 1024);
    tcvt<<<dim3(128, 32, 4), 256>>>(enc_W1, eW1t, 1024, 4096);
    tcvt<<<dim3(32, 128, 4), 256>>>(enc_W2, eW2t, 4096, 1024);
    tcvt<<<dim3(128, 32, 4), 256>>>(dW1, dW1t, 1024, 4096);
    tcvt<<<dim3(32, 128, 4), 256>>>(dW2, dW2t, 4096, 1024);

    dim3 gQKV(3072 / 128, MROWS / 64);   // 384 CTAs
    dim3 gKVB(4096 / 128, MROWS / 64);   // 512 CTAs
    dim3 gF1(DFFF / 128, MROWS / 64);    // 512 CTAs
    dim3 g64(16, 16);                    // 256 CTAs
    dim3 gSK2(16, 16, 2);
    dim3 gSK4(16, 16, 4);
    dim3 gS(SS / 64, BB * HH);
    dim3 gC(SS / 64, BB * HH);

    // ------------------------- Encoder -------------------------
    const float* cur = src;
    const __half* curh = srch;
    for (int l = 0; l < LL; l++) {
        const float* bb = enc_b + (size_t)l * 4 * DD;
        gemm_wide_h<<<gQKV, 256, SM_W>>>(curh, encWt + (size_t)l * 4 * M1, bb, Qh,
                                         DD, DD, 0, (long long)M1, DD, (long long)M1);
        float* adst = full ? out + OFF_ENC + (size_t)l * SLAB : ATT;
        attn_scores_f16<<<gS, 256, SC_SMEM>>>(Qh, Qh + M1, src_mask, 0, adst);
        attn_ctx_f16<<<gC, 256>>>(adst, Qh + 2 * M1, Qh);
        gemm_sk_h<<<gSK2, 128>>>(Qh, encWt + ((size_t)l * 4 + 3) * M1, PRT, 1024, 1024, 512);
        add_ln_red<<<MROWS, 256>>>(cur, PRT, 2, bb + 3 * DD,
                                   enc_lng + (size_t)l * 2 * DD,
                                   enc_lnb + (size_t)l * 2 * DD, X2, X2h);
        gemm_wide_h<<<gF1, 256, SM_W>>>(X2h, eW1t + (size_t)l * 4 * M1,
                                        enc_b1 + (size_t)l * DFFF, H1h,
                                        DD, DFFF, 1, 0, 0, 0);
        gemm_sk_h<<<gSK4, 128>>>(H1h, eW2t + (size_t)l * 4 * M1, PRT, 4096, 4096, 1024);
        add_ln_red<<<MROWS, 256>>>(X2, PRT, 4, enc_b2 + (size_t)l * DD,
                                   enc_lng + (size_t)l * 2 * DD + DD,
                                   enc_lnb + (size_t)l * 2 * DD + DD, X, Xh);
        cur = X; curh = Xh;
    }
    ln_plain<<<MROWS, 256>>>(cur, enc_fg, enc_fb, ENC, ENCh);

    // Batched cross-attention K/V (blk = layer)
    gemm_wide_h<<<gKVB, 256, SM_W>>>(ENCh, dcWt + M1, dcb + DD, CKh,
                                     DD, DD, 0, 4LL * M1, 4LL * DD, (long long)M1);
    gemm_wide_h<<<gKVB, 256, SM_W>>>(ENCh, dcWt + 2 * M1, dcb + 2 * DD, CVh,
                                     DD, DD, 0, 4LL * M1, 4LL * DD, (long long)M1);

    // ------------------------- Decoder -------------------------
    cur = tgt; curh = tgth;
    for (int l = 0; l < LL; l++) {
        const float* bs = dsb + (size_t)l * 4 * DD;
        gemm_wide_h<<<gQKV, 256, SM_W>>>(curh, dsWt + (size_t)l * 4 * M1, bs, Qh,
                                         DD, DD, 0, (long long)M1, DD, (long long)M1);
        float* adst = full ? out + OFF_SELF + (size_t)l * SLAB : ATT;
        attn_scores_f16<<<gS, 256, SC_SMEM>>>(Qh, Qh + M1, tgt_mask, 1, adst);
        attn_ctx_f16<<<gC, 256>>>(adst, Qh + 2 * M1, Qh);
        gemm_sk_h<<<gSK2, 128>>>(Qh, dsWt + ((size_t)l * 4 + 3) * M1, PRT, 1024, 1024, 512);
        add_ln_red<<<MROWS, 256>>>(cur, PRT, 2, bs + 3 * DD,
                                   dlng + (size_t)l * 3 * DD,
                                   dlnb + (size_t)l * 3 * DD, X, Xh);

        const float* bc = dcb + (size_t)l * 4 * DD;
        gemm_h64<<<g64, 128>>>(Xh, dcWt + (size_t)l * 4 * M1, bc, Qh);
        adst = full ? out + OFF_CROSS + (size_t)l * SLAB : ATT;
        attn_scores_f16<<<gS, 256, SC_SMEM>>>(Qh, CKh + (size_t)l * M1, src_mask, 0, adst);
        attn_ctx_f16<<<gC, 256>>>(adst, CVh + (size_t)l * M1, Qh);
        gemm_sk_h<<<gSK2, 128>>>(Qh, dcWt + ((size_t)l * 4 + 3) * M1, PRT, 1024, 1024, 512);
        add_ln_red<<<MROWS, 256>>>(X, PRT, 2, bc + 3 * DD,
                                   dlng + (size_t)l * 3 * DD + DD,
                                   dlnb + (size_t)l * 3 * DD + DD, X2, X2h);

        gemm_wide_h<<<gF1, 256, SM_W>>>(X2h, dW1t + (size_t)l * 4 * M1,
                                        db1 + (size_t)l * DFFF, H1h,
                                        DD, DFFF, 1, 0, 0, 0);
        gemm_sk_h<<<gSK4, 128>>>(H1h, dW2t + (size_t)l * 4 * M1, PRT, 4096, 4096, 1024);
        add_ln_red<<<MROWS, 256>>>(X2, PRT, 4, db2 + (size_t)l * DD,
                                   dlng + (size_t)l * 3 * DD + 2 * DD,
                                   dlnb + (size_t)l * 3 * DD + 2 * DD, X, Xh);
        cur = X; curh = Xh;
    }
    ln_plain<<<MROWS, 256>>>(cur, dfg, dfb, out, nullptr);
}

// round 12
// speedup vs baseline: 2.3792x; 1.0062x over previous
#include <cuda_runtime.h>
#include <cuda_fp16.h>
#include <cstdint>
#include <cstddef>

// ---------------------------------------------------------------------------
// Transformer forward, R12: R11 + vectorized weight transpose, 32-row
// score tiles (2 CTAs/SM), fp16 P feeding the ctx GEMM.
// ---------------------------------------------------------------------------

#define BB   2
#define SS   512
#define DD   1024
#define HH   16
#define DKK  64
#define DFFF 4096
#define LL   4
#define MROWS (BB*SS)          // 1024
#define EPSF 1e-5f
#define INV_SCALE 0.125f       // 1/sqrt(DK)

static const size_t MEG = 1u << 20;
__device__ __align__(16) float g_scratch[89u * (1u << 20)];   // 356 MB

// ---------------------------------------------------------------------------
// helpers
// ---------------------------------------------------------------------------
__device__ __forceinline__ uint32_t pk(float lo, float hi) {
    __half2 h = __floats2half2_rn(lo, hi);
    return *(uint32_t*)&h;
}
__device__ __forceinline__ uint2 pk4(float4 v) {
    return make_uint2(pk(v.x, v.y), pk(v.z, v.w));
}
__device__ __forceinline__ uint4 permT(uint2 e, uint2 o) {
    uint4 r;
    r.x = __byte_perm(e.x, o.x, 0x5410);
    r.y = __byte_perm(e.x, o.x, 0x7632);
    r.z = __byte_perm(e.y, o.y, 0x5410);
    r.w = __byte_perm(e.y, o.y, 0x7632);
    return r;
}
__device__ __forceinline__ void mma16(float* c, const uint32_t* a, const uint32_t* b) {
    asm volatile(
        "mma.sync.aligned.m16n8k16.row.col.f32.f16.f16.f32 "
        "{%0,%1,%2,%3}, {%4,%5,%6,%7}, {%8,%9}, {%0,%1,%2,%3};\n"
        : "+f"(c[0]), "+f"(c[1]), "+f"(c[2]), "+f"(c[3])
        : "r"(a[0]), "r"(a[1]), "r"(a[2]), "r"(a[3]), "r"(b[0]), "r"(b[1]));
}
__device__ __forceinline__ uint32_t smaddr(const void* p) {
    return (uint32_t)__cvta_generic_to_shared(p);
}
__device__ __forceinline__ void cpa16(uint32_t dsm, const void* gsrc) {
    asm volatile("cp.async.cg.shared.global [%0], [%1], 16;" :: "r"(dsm), "l"(gsrc));
}
#define CP_COMMIT() asm volatile("cp.async.commit_group;")
#define CP_WAIT2()  asm volatile("cp.async.wait_group 2;")

// ---------------------------------------------------------------------------
// Prepass: fp32 -> fp16 convert
// ---------------------------------------------------------------------------
__global__ __launch_bounds__(256)
void cvt16(const float* __restrict__ x, __half* __restrict__ y, int n)
{
    const int i = (blockIdx.x * 256 + threadIdx.x) * 4;
    if (i < n) {
        float4 v = *(const float4*)&x[i];
        *(uint2*)&y[i] = pk4(v);
    }
}

// Batched transpose+convert W[K,N] fp32 -> Wt[N,K] fp16, vectorized.
// Grid (N/32, K/32, batch); 256 threads (8x32 load layout).
__global__ __launch_bounds__(256)
void tcvt(const float* __restrict__ src, __half* __restrict__ dst, int K, int N)
{
    const size_t zoff = (size_t)blockIdx.z * K * N;
    src += zoff; dst += zoff;
    __shared__ float tile[32][33];
    const int t = threadIdx.x;
    const int tx = (t & 7) * 4, ty = t >> 3;
    const int x0 = blockIdx.x * 32, y0 = blockIdx.y * 32;

    float4 v = *(const float4*)&src[(size_t)(y0 + ty) * N + x0 + tx];
    tile[ty][tx] = v.x; tile[ty][tx + 1] = v.y;
    tile[ty][tx + 2] = v.z; tile[ty][tx + 3] = v.w;
    __syncthreads();

    const float a = tile[tx][ty], b = tile[tx + 1][ty];
    const float c = tile[tx + 2][ty], d = tile[tx + 3][ty];
    *(uint2*)&dst[(size_t)(x0 + ty) * K + y0 + tx] = make_uint2(pk(a, b), pk(c, d));
}

// ---------------------------------------------------------------------------
// Wide GEMM: fp16 A[M][K] @ fp16 Wt[N][K] -> fp16 C (+fp32 bias, opt ReLU).
// 64x128 tile, 256 thr, cp.async 4-stage. Dyn smem 61440 B.
// ---------------------------------------------------------------------------
__global__ __launch_bounds__(256, 2)
void gemm_wide_h(const __half* __restrict__ A, const __half* __restrict__ Wt,
                 const float* __restrict__ bias, __half* __restrict__ C,
                 int K, int nb, int relu,
                 long long wstride, long long bstride, long long cstride)
{
    constexpr int ASTR = 20, BSTR = 20;
    constexpr int ASZ = 64 * ASTR, BSZ = 128 * BSTR, STG = ASZ + BSZ;
    extern __shared__ uint32_t smg[];

    const int t = threadIdx.x, lane = t & 31, w = t >> 5;
    const int g = lane >> 2, cc = lane & 3;
    const int wm = w >> 2, wn = w & 3;
    const int row0 = blockIdx.y * 64;
    const int colg = blockIdx.x * 128;
    const int blk  = colg / nb;
    const int col0 = colg - blk * nb;
    const __half* Wp = Wt + (size_t)blk * (size_t)wstride;
    const float* bp = bias + (size_t)blk * (size_t)bstride;
    __half* Cp = C + (size_t)blk * (size_t)cstride;

    const uint32_t sb = smaddr(smg);
    const int arow = t >> 2, ach = t & 3;

    auto issue = [&](int it) {
        const int k0 = it << 5;
        const uint32_t base = sb + (uint32_t)((it & 3) * STG) * 4u;
        cpa16(base + (uint32_t)(arow * ASTR + ach * 4) * 4u,
              A + (size_t)(row0 + arow) * K + k0 + ach * 8);
#pragma unroll
        for (int i = 0; i < 2; i++) {
            const int idx = t + i * 256;
            const int br = idx >> 2, bch = idx & 3;
            cpa16(base + (uint32_t)(ASZ + br * BSTR + bch * 4) * 4u,
                  Wp + (size_t)(col0 + br) * K + k0 + bch * 8);
        }
    };

    float acc[2][4][4] = {};
    const int NK = K >> 5;
    issue(0); CP_COMMIT();
    issue(1); CP_COMMIT();
    issue(2); CP_COMMIT();

    for (int it = 0; it < NK; it++) {
        CP_WAIT2();
        __syncthreads();
        if (it + 3 < NK) issue(it + 3);
        CP_COMMIT();

        const uint32_t* as_ = smg + (it & 3) * STG;
        const uint32_t* bs_ = smg + (it & 3) * STG + ASZ;
        uint32_t af[2][4], bf[4][2];
#pragma unroll
        for (int ksi = 0; ksi < 2; ksi++) {
            const int kp = ksi * 8 + cc;
#pragma unroll
            for (int mi = 0; mi < 2; mi++) {
                const int mb = wm * 32 + mi * 16;
                af[mi][0] = as_[(mb + g) * ASTR + kp];
                af[mi][1] = as_[(mb + g + 8) * ASTR + kp];
                af[mi][2] = as_[(mb + g) * ASTR + kp + 4];
                af[mi][3] = as_[(mb + g + 8) * ASTR + kp + 4];
            }
#pragma unroll
            for (int nj = 0; nj < 4; nj++) {
                const int nrow = wn * 32 + nj * 8 + g;
                bf[nj][0] = bs_[nrow * BSTR + kp];
                bf[nj][1] = bs_[nrow * BSTR + kp + 4];
            }
#pragma unroll
            for (int mi = 0; mi < 2; mi++)
#pragma unroll
                for (int nj = 0; nj < 4; nj++)
                    mma16(acc[mi][nj], af[mi], bf[nj]);
        }
    }

#pragma unroll
    for (int mi = 0; mi < 2; mi++) {
        const int r0 = row0 + wm * 32 + mi * 16 + g;
#pragma unroll
        for (int nj = 0; nj < 4; nj++) {
            const int c = col0 + wn * 32 + nj * 8 + 2 * cc;
            const float b0v = bp[c], b1v = bp[c + 1];
            float v0 = acc[mi][nj][0] + b0v, v1 = acc[mi][nj][1] + b1v;
            float v2 = acc[mi][nj][2] + b0v, v3 = acc[mi][nj][3] + b1v;
            if (relu) {
                v0 = fmaxf(v0, 0.f); v1 = fmaxf(v1, 0.f);
                v2 = fmaxf(v2, 0.f); v3 = fmaxf(v3, 0.f);
            }
            *(uint32_t*)&Cp[(size_t)r0 * nb + c]       = pk(v0, v1);
            *(uint32_t*)&Cp[(size_t)(r0 + 8) * nb + c] = pk(v2, v3);
        }
    }
}

// ---------------------------------------------------------------------------
// 128-thread 64x64 cp.async core (fp16 A, fp16 Wt rows).
// ---------------------------------------------------------------------------
#define GEMMH64_CORE(AP, WP, LDA, LDW, NKV)                                     \
    constexpr int ASTR = 20, BSTR = 20;                                         \
    constexpr int ASZ = 64 * ASTR, BSZ = 64 * BSTR, STG = ASZ + BSZ;            \
    __shared__ uint32_t smg[4 * STG];                                           \
    const int t = threadIdx.x, lane = t & 31, w = t >> 5;                       \
    const int g = lane >> 2, cc = lane & 3;                                     \
    const int wm = w >> 1, wn = w & 1;                                          \
    const int row0 = blockIdx.y * 64;                                           \
    const int col0 = blockIdx.x * 64;                                           \
    const uint32_t sb = smaddr(smg);                                            \
    auto issue = [&](int it) {                                                  \
        const int k0 = it << 5;                                                 \
        const uint32_t base = sb + (uint32_t)((it & 3) * STG) * 4u;             \
        _Pragma("unroll")                                                       \
        for (int i = 0; i < 2; i++) {                                           \
            const int idx = t + i * 128;                                        \
            const int r = idx >> 2, ch = idx & 3;                               \
            cpa16(base + (uint32_t)(r * ASTR + ch * 4) * 4u,                    \
                  AP + (size_t)(row0 + r) * LDA + k0 + ch * 8);                 \
            cpa16(base + (uint32_t)(ASZ + r * BSTR + ch * 4) * 4u,              \
                  WP + (size_t)(col0 + r) * LDW + k0 + ch * 8);                 \
        }                                                                       \
    };                                                                          \
    float acc[2][4][4] = {};                                                    \
    const int NK = (NKV);                                                       \
    issue(0); CP_COMMIT();                                                      \
    issue(1); CP_COMMIT();                                                      \
    issue(2); CP_COMMIT();                                                      \
    for (int it = 0; it < NK; it++) {                                           \
        CP_WAIT2();                                                             \
        __syncthreads();                                                        \
        if (it + 3 < NK) issue(it + 3);                                         \
        CP_COMMIT();                                                            \
        const uint32_t* as_ = smg + (it & 3) * STG;                             \
        const uint32_t* bs_ = smg + (it & 3) * STG + ASZ;                       \
        uint32_t af[2][4], bf[4][2];                                            \
        _Pragma("unroll")                                                       \
        for (int ksi = 0; ksi < 2; ksi++) {                                     \
            const int kp = ksi * 8 + cc;                                        \
            _Pragma("unroll")                                                   \
            for (int mi = 0; mi < 2; mi++) {                                    \
                const int mb = wm * 32 + mi * 16;                               \
                af[mi][0] = as_[(mb + g) * ASTR + kp];                          \
                af[mi][1] = as_[(mb + g + 8) * ASTR + kp];                      \
                af[mi][2] = as_[(mb + g) * ASTR + kp + 4];                      \
                af[mi][3] = as_[(mb + g + 8) * ASTR + kp + 4];                  \
            }                                                                   \
            _Pragma("unroll")                                                   \
            for (int nj = 0; nj < 4; nj++) {                                    \
                const int nrow = wn * 32 + nj * 8 + g;                          \
                bf[nj][0] = bs_[nrow * BSTR + kp];                              \
                bf[nj][1] = bs_[nrow * BSTR + kp + 4];                          \
            }                                                                   \
            _Pragma("unroll")                                                   \
            for (int mi = 0; mi < 2; mi++)                                      \
                _Pragma("unroll")                                               \
                for (int nj = 0; nj < 4; nj++)                                  \
                    mma16(acc[mi][nj], af[mi], bf[nj]);                         \
        }                                                                       \
    }

// cross-Q: fp16 A @ Wt + bias -> fp16 C.
__global__ __launch_bounds__(128, 4)
void gemm_h64(const __half* __restrict__ A, const __half* __restrict__ Wt,
              const float* __restrict__ bias, __half* __restrict__ C)
{
    GEMMH64_CORE(A, Wt, 1024, 1024, 32)
#pragma unroll
    for (int mi = 0; mi < 2; mi++) {
        const int r0 = row0 + wm * 32 + mi * 16 + g;
#pragma unroll
        for (int nj = 0; nj < 4; nj++) {
            const int c = col0 + wn * 32 + nj * 8 + 2 * cc;
            const float b0v = bias[c], b1v = bias[c + 1];
            *(uint32_t*)&C[(size_t)r0 * 1024 + c] =
                pk(acc[mi][nj][0] + b0v, acc[mi][nj][1] + b1v);
            *(uint32_t*)&C[(size_t)(r0 + 8) * 1024 + c] =
                pk(acc[mi][nj][2] + b0v, acc[mi][nj][3] + b1v);
        }
    }
}

// Split-K: parts[z] = A[:, zKc:(z+1)Kc] @ Wt-cols-slice. Grid (16,16,nsplit).
__global__ __launch_bounds__(128, 4)
void gemm_sk_h(const __half* __restrict__ A, const __half* __restrict__ Wt,
               float* __restrict__ parts, int lda, int ldw, int Kc)
{
    const int z = blockIdx.z;
    const __half* Az = A + (size_t)z * Kc;
    const __half* Wz = Wt + (size_t)z * Kc;
    float* Cp = parts + (size_t)z * MEG;
    GEMMH64_CORE(Az, Wz, lda, ldw, (Kc >> 5))
#pragma unroll
    for (int mi = 0; mi < 2; mi++) {
        const int r0 = row0 + wm * 32 + mi * 16 + g;
#pragma unroll
        for (int nj = 0; nj < 4; nj++) {
            const int c = col0 + wn * 32 + nj * 8 + 2 * cc;
            *(float2*)&Cp[(size_t)r0 * 1024 + c] =
                make_float2(acc[mi][nj][0], acc[mi][nj][1]);
            *(float2*)&Cp[(size_t)(r0 + 8) * 1024 + c] =
                make_float2(acc[mi][nj][2], acc[mi][nj][3]);
        }
    }
}

// ---------------------------------------------------------------------------
// LayerNorm (one-pass). Writes fp32 y and optional fp16 yh.
// ---------------------------------------------------------------------------
__device__ __forceinline__ void block_reduce2(float& s, float& s2,
                                              float* sh1, float* sh2,
                                              int lane, int w)
{
#pragma unroll
    for (int o = 16; o > 0; o >>= 1) {
        s  += __shfl_xor_sync(0xffffffffu, s, o);
        s2 += __shfl_xor_sync(0xffffffffu, s2, o);
    }
    if (lane == 0) { sh1[w] = s; sh2[w] = s2; }
    __syncthreads();
    if (w == 0) {
        float a = (lane < 8) ? sh1[lane] : 0.f;
        float b = (lane < 8) ? sh2[lane] : 0.f;
#pragma unroll
        for (int o = 4; o > 0; o >>= 1) {
            a += __shfl_xor_sync(0xffffffffu, a, o);
            b += __shfl_xor_sync(0xffffffffu, b, o);
        }
        if (lane == 0) { sh1[0] = a; sh2[0] = b; }
    }
    __syncthreads();
}

__global__ __launch_bounds__(256)
void add_ln_red(const float* __restrict__ x, const float* __restrict__ parts,
                int nparts, const float* __restrict__ bias,
                const float* __restrict__ g, const float* __restrict__ bt,
                float* __restrict__ y, __half* __restrict__ yh)
{
    const int row = blockIdx.x;
    const int t = threadIdx.x;
    const int lane = t & 31, w = t >> 5;
    __shared__ float sh1[8], sh2[8];

    float v[4];
#pragma unroll
    for (int i = 0; i < 4; i++) {
        const int c = t + i * 256;
        const size_t idx = (size_t)row * DD + c;
        float a = parts[idx];
        for (int p = 1; p < nparts; p++) a += parts[(size_t)p * MEG + idx];
        v[i] = x[idx] + a + bias[c];
    }
    float s = 0.f, s2 = 0.f;
#pragma unroll
    for (int i = 0; i < 4; i++) { s += v[i]; s2 += v[i] * v[i]; }
    block_reduce2(s, s2, sh1, sh2, lane, w);
    const float mean = sh1[0] * (1.0f / DD);
    const float var  = sh2[0] * (1.0f / DD) - mean * mean;
    const float inv  = rsqrtf(var + EPSF);

    float r[4];
#pragma unroll
    for (int i = 0; i < 4; i++) {
        const int c = t + i * 256;
        r[i] = g[c] * (v[i] - mean) * inv + bt[c];
        y[(size_t)row * DD + c] = r[i];
    }
    if (yh) {
#pragma unroll
        for (int i = 0; i < 4; i++)
            yh[(size_t)row * DD + t + i * 256] = __float2half_rn(r[i]);
    }
}

__global__ __launch_bounds__(256)
void ln_plain(const float* __restrict__ x, const float* __restrict__ g,
              const float* __restrict__ bt, float* __restrict__ y,
              __half* __restrict__ yh)
{
    const int row = blockIdx.x;
    const int t = threadIdx.x;
    const int lane = t & 31, w = t >> 5;
    __shared__ float sh1[8], sh2[8];

    float v[4];
#pragma unroll
    for (int i = 0; i < 4; i++)
        v[i] = x[(size_t)row * DD + t + i * 256];
    float s = 0.f, s2 = 0.f;
#pragma unroll
    for (int i = 0; i < 4; i++) { s += v[i]; s2 += v[i] * v[i]; }
    block_reduce2(s, s2, sh1, sh2, lane, w);
    const float mean = sh1[0] * (1.0f / DD);
    const float var  = sh2[0] * (1.0f / DD) - mean * mean;
    const float inv  = rsqrtf(var + EPSF);

    float r[4];
#pragma unroll
    for (int i = 0; i < 4; i++) {
        const int c = t + i * 256;
        r[i] = g[c] * (v[i] - mean) * inv + bt[c];
        y[(size_t)row * DD + c] = r[i];
    }
    if (yh) {
#pragma unroll
        for (int i = 0; i < 4; i++)
            yh[(size_t)row * DD + t + i * 256] = __float2half_rn(r[i]);
    }
}

// ---------------------------------------------------------------------------
// Scores + mask + softmax. 32 q-rows per CTA (512 CTAs, ~80 KB smem).
// 8 warps: qslot = w>>2 (2 x 16 rows), kslot = w&3 (4 x 16 cols per kt-64).
// Writes P fp32 to attn (output) and fp16 to ph (feeds ctx).
// Dyn smem: (32*36 + 64*36 + 32*516)*4 = 79872 B.
// ---------------------------------------------------------------------------
__global__ __launch_bounds__(256)
void attn_scores_f16(const __half* __restrict__ qf,
                     const __half* __restrict__ kf,
                     const int* __restrict__ mask,
                     int causal,
                     float* __restrict__ attn,
                     __half* __restrict__ ph)
{
    extern __shared__ float smemf[];
    uint32_t* Qs = (uint32_t*)smemf;        // 32*36
    uint32_t* Ks = Qs + 32 * 36;            // 64*36
    float* Ssm = smemf + (32 + 64) * 36;    // 32*516

    const int bh = blockIdx.y, b = bh >> 4, h = bh & 15;
    const int q0 = blockIdx.x * 32;
    const int t = threadIdx.x, lane = t & 31, w = t >> 5;
    const int g = lane >> 2, cc = lane & 3;
    const int qslot = w >> 2, kslot = w & 3;

    // Q tile: 32 rows x 8 uint4 chunks = 256
    {
        const int r = t >> 3, ch = t & 7;
        uint4 v = *(const uint4*)&qf[(size_t)(b * SS + q0 + r) * DD + h * DKK + ch * 8];
        *(uint4*)&Qs[r * 36 + ch * 4] = v;
    }

    int mreg[16];
    if (!causal) {
#pragma unroll
        for (int j = 0; j < 16; j++)
            mreg[j] = mask[(size_t)b * SS + lane + j * 32];
    }

    for (int kt = 0; kt < 8; kt++) {
        __syncthreads();
#pragma unroll
        for (int i = 0; i < 2; i++) {
            const int idx = t + i * 256;
            const int r = idx >> 3, ch = idx & 7;
            uint4 v = *(const uint4*)&kf[(size_t)(b * SS + kt * 64 + r) * DD + h * DKK + ch * 8];
            *(uint4*)&Ks[r * 36 + ch * 4] = v;
        }
        __syncthreads();

        float acc[2][4] = {};
        uint32_t af[4];
#pragma unroll
        for (int ksi = 0; ksi < 4; ksi++) {
            const int kp = ksi * 8 + cc;
            const int mb = qslot * 16;
            af[0] = Qs[(mb + g) * 36 + kp];
            af[1] = Qs[(mb + g + 8) * 36 + kp];
            af[2] = Qs[(mb + g) * 36 + kp + 4];
            af[3] = Qs[(mb + g + 8) * 36 + kp + 4];
#pragma unroll
            for (int nj = 0; nj < 2; nj++) {
                const int nbase = kslot * 16 + nj * 8;
                uint32_t bf[2];
                bf[0] = Ks[(nbase + g) * 36 + kp];
                bf[1] = Ks[(nbase + g) * 36 + kp + 4];
                mma16(acc[nj], af, bf);
            }
        }
#pragma unroll
        for (int nj = 0; nj < 2; nj++) {
            const int colb = kt * 64 + kslot * 16 + nj * 8 + 2 * cc;
            const int rr = qslot * 16 + g;
            *(float2*)&Ssm[rr * 516 + colb]       = make_float2(acc[nj][0], acc[nj][1]);
            *(float2*)&Ssm[(rr + 8) * 516 + colb] = make_float2(acc[nj][2], acc[nj][3]);
        }
    }
    __syncthreads();

    // softmax: warp w handles rows w*4 .. w*4+3
    for (int i = 0; i < 4; i++) {
        const int rloc = w * 4 + i;
        const int q = q0 + rloc;
        float vals[16];
        float mx = -1e30f;
#pragma unroll
        for (int j = 0; j < 16; j++) {
            const int col = lane + j * 32;
            float v = Ssm[rloc * 516 + col] * INV_SCALE;
            const int m = causal ? mask[((size_t)b * SS + q) * SS + col] : mreg[j];
            if (m == 0) v = -1e9f;
            vals[j] = v;
            mx = fmaxf(mx, v);
        }
#pragma unroll
        for (int o = 16; o > 0; o >>= 1)
            mx = fmaxf(mx, __shfl_xor_sync(0xffffffffu, mx, o));
        float sum = 0.0f;
#pragma unroll
        for (int j = 0; j < 16; j++) {
            vals[j] = expf(vals[j] - mx);
            sum += vals[j];
        }
#pragma unroll
        for (int o = 16; o > 0; o >>= 1)
            sum += __shfl_xor_sync(0xffffffffu, sum, o);
        const float inv = 1.0f / sum;
        float* dst = attn + ((size_t)bh * SS + q) * SS;
        __half* dsth = ph + ((size_t)bh * SS + q) * SS;
#pragma unroll
        for (int j = 0; j < 16; j++) {
            const float p = vals[j] * inv;
            dst[lane + j * 32] = p;
            dsth[lane + j * 32] = __float2half_rn(p);
        }
    }
}

// ---------------------------------------------------------------------------
// Context: P fp16 @ V fp16 -> ctx fp16. Double-buffered K-step 32.
// ---------------------------------------------------------------------------
__global__ __launch_bounds__(256)
void attn_ctx_f16(const __half* __restrict__ ph,
                  const __half* __restrict__ vf,
                  __half* __restrict__ ctx)
{
    constexpr int ASTR = 20, BSTR = 72;
    constexpr int ASZ = 64 * ASTR, BSZ = 16 * BSTR, STG = ASZ + BSZ;
    __shared__ uint32_t smg[2 * STG];

    const int bh = blockIdx.y, b = bh >> 4, h = bh & 15;
    const int q0 = blockIdx.x * 64;
    const int t = threadIdx.x, lane = t & 31, w = t >> 5;
    const int g = lane >> 2, cc = lane & 3;
    const int qslot = w & 3, dslot = w >> 2;
    const __half* Ap = ph + (size_t)bh * SS * SS;
    const __half* Vp = vf + (size_t)b * SS * DD + h * DKK;

    const int ar = t >> 3, ac = (t & 7) << 2;
    const int vr = t >> 4, vc = (t & 15) << 2;

    uint2 aR[2], vE, vO;
    auto loadAB = [&](int k0) {
#pragma unroll
        for (int i = 0; i < 2; i++)
            aR[i] = *(const uint2*)&Ap[(size_t)(q0 + ar + i * 32) * SS + k0 + ac];
        vE = *(const uint2*)&Vp[(size_t)(k0 + 2 * vr) * DD + vc];
        vO = *(const uint2*)&Vp[(size_t)(k0 + 2 * vr + 1) * DD + vc];
    };
    auto storeAB = [&](int p) {
        uint32_t* as_ = smg + p * STG;
        uint32_t* bs_ = smg + p * STG + ASZ;
#pragma unroll
        for (int i = 0; i < 2; i++)
            *(uint2*)&as_[(ar + i * 32) * ASTR + (ac >> 1)] = aR[i];
        *(uint4*)&bs_[vr * BSTR + vc] = permT(vE, vO);
    };

    float acc[4][4] = {};
    const int NK = 16;
    loadAB(0);
    storeAB(0);
    loadAB(32);
    __syncthreads();

    for (int it = 0; it < NK; it++) {
        const int p = it & 1;
        if (it + 1 < NK) storeAB(p ^ 1);
        if (it + 2 < NK) loadAB((it + 2) << 5);

        const uint32_t* as_ = smg + p * STG;
        const uint32_t* bs_ = smg + p * STG + ASZ;
        uint32_t af[4], bf[2];
#pragma unroll
        for (int ksi = 0; ksi < 2; ksi++) {
            const int kp = ksi * 8 + cc;
            const int mb = qslot * 16;
            af[0] = as_[(mb + g) * ASTR + kp];
            af[1] = as_[(mb + g + 8) * ASTR + kp];
            af[2] = as_[(mb + g) * ASTR + kp + 4];
            af[3] = as_[(mb + g + 8) * ASTR + kp + 4];
#pragma unroll
            for (int nj = 0; nj < 4; nj++) {
                const int nbase = dslot * 32 + nj * 8;
                bf[0] = bs_[kp * BSTR + nbase + g];
                bf[1] = bs_[(kp + 4) * BSTR + nbase + g];
                mma16(acc[nj], af, bf);
            }
        }
        __syncthreads();
    }

    __half* Cp = ctx + (size_t)b * SS * DD + h * DKK;
#pragma unroll
    for (int nj = 0; nj < 4; nj++) {
        const int c = dslot * 32 + nj * 8 + 2 * cc;
        const int r = q0 + qslot * 16 + g;
        *(uint32_t*)&Cp[(size_t)r * DD + c]       = pk(acc[nj][0], acc[nj][1]);
        *(uint32_t*)&Cp[(size_t)(r + 8) * DD + c] = pk(acc[nj][2], acc[nj][3]);
    }
}

// ---------------------------------------------------------------------------
// Host orchestration
// ---------------------------------------------------------------------------
extern "C" void kernel_launch(void* const* d_in, const int* in_sizes, int n_in,
                              void* d_out, int out_size)
{
    const float* src     = (const float*)d_in[0];
    const float* tgt     = (const float*)d_in[1];
    const float* enc_W   = (const float*)d_in[2];
    const float* enc_b   = (const float*)d_in[3];
    const float* enc_W1  = (const float*)d_in[4];
    const float* enc_b1  = (const float*)d_in[5];
    const float* enc_W2  = (const float*)d_in[6];
    const float* enc_b2  = (const float*)d_in[7];
    const float* enc_lng = (const float*)d_in[8];
    const float* enc_lnb = (const float*)d_in[9];
    const float* enc_fg  = (const float*)d_in[10];
    const float* enc_fb  = (const float*)d_in[11];
    const float* dsW     = (const float*)d_in[12];
    const float* dsb     = (const float*)d_in[13];
    const float* dcW     = (const float*)d_in[14];
    const float* dcb     = (const float*)d_in[15];
    const float* dW1     = (const float*)d_in[16];
    const float* db1     = (const float*)d_in[17];
    const float* dW2     = (const float*)d_in[18];
    const float* db2     = (const float*)d_in[19];
    const float* dlng    = (const float*)d_in[20];
    const float* dlnb    = (const float*)d_in[21];
    const float* dfg     = (const float*)d_in[22];
    const float* dfb     = (const float*)d_in[23];
    const int*   src_mask = (const int*)d_in[24];
    const int*   tgt_mask = (const int*)d_in[25];
    float* out = (float*)d_out;

    float* scratch = nullptr;
    cudaGetSymbolAddress((void**)&scratch, g_scratch);

    float*  X    = scratch + 0 * MEG;
    float*  X2   = scratch + 1 * MEG;
    __half* Qh   = (__half*)(scratch + 2 * MEG);   // Q,K,V: 3M halves
    __half* H1h  = (__half*)(scratch + 4 * MEG);   // 4M halves
    __half* Xh   = (__half*)(scratch + 6 * MEG);
    __half* X2h  = (__half*)(scratch + 7 * MEG);
    __half* srch = (__half*)(scratch + 8 * MEG);
    __half* tgth = (__half*)(scratch + 9 * MEG);
    __half* ENCh = (__half*)(scratch + 10 * MEG);
    float*  ATT  = scratch + 11 * MEG;             // 8M floats (fallback)
    float*  ENC  = scratch + 19 * MEG;
    float*  PRT  = scratch + 20 * MEG;             // 4M floats
    __half* CKh  = (__half*)(scratch + 24 * MEG);  // 4M halves
    __half* CVh  = (__half*)(scratch + 26 * MEG);  // 4M halves
    __half* WH   = (__half*)(scratch + 28 * MEG);  // 112M halves
    __half* Ph   = (__half*)(scratch + 84 * MEG);  // 8.4M halves (P fp16)

    const size_t M1 = MEG;
    __half* encWt = WH;                 // [L*4][1024][1024]
    __half* dsWt  = WH + 16 * M1;
    __half* dcWt  = WH + 32 * M1;
    __half* eW1t  = WH + 48 * M1;       // [L][4096][1024]
    __half* eW2t  = WH + 64 * M1;       // [L][1024][4096]
    __half* dW1t  = WH + 80 * M1;
    __half* dW2t  = WH + 96 * M1;

    const size_t SLAB      = (size_t)BB * HH * SS * SS;
    const size_t OFF_ENC   = (size_t)BB * SS * DD;
    const size_t OFF_SELF  = OFF_ENC + (size_t)LL * SLAB;
    const size_t OFF_CROSS = OFF_SELF + (size_t)LL * SLAB;
    const size_t TOTAL     = OFF_CROSS + (size_t)LL * SLAB;
    const bool full = ((size_t)out_size >= TOTAL);

    const int SM_W = 4 * (64 * 20 + 128 * 20) * 4;  // 61440 B
    cudaFuncSetAttribute(gemm_wide_h, cudaFuncAttributeMaxDynamicSharedMemorySize, SM_W);
    const size_t SC_SMEM = (size_t)((32 + 64) * 36 + 32 * 516) * sizeof(float);
    cudaFuncSetAttribute(attn_scores_f16,
                         cudaFuncAttributeMaxDynamicSharedMemorySize, (int)SC_SMEM);

    // ---------------- Prepass ----------------
    cvt16<<<1024, 256>>>(src, srch, MROWS * DD);
    cvt16<<<1024, 256>>>(tgt, tgth, MROWS * DD);
    tcvt<<<dim3(32, 32, 16), 256>>>(enc_W, encWt, 1024, 1024);
    tcvt<<<dim3(32, 32, 16), 256>>>(dsW, dsWt, 1024, 1024);
    tcvt<<<dim3(32, 32, 16), 256>>>(dcW, dcWt, 1024, 1024);
    tcvt<<<dim3(128, 32, 4), 256>>>(enc_W1, eW1t, 1024, 4096);
    tcvt<<<dim3(32, 128, 4), 256>>>(enc_W2, eW2t, 4096, 1024);
    tcvt<<<dim3(128, 32, 4), 256>>>(dW1, dW1t, 1024, 4096);
    tcvt<<<dim3(32, 128, 4), 256>>>(dW2, dW2t, 4096, 1024);

    dim3 gQKV(3072 / 128, MROWS / 64);   // 384 CTAs
    dim3 gKVB(4096 / 128, MROWS / 64);   // 512 CTAs
    dim3 gF1(DFFF / 128, MROWS / 64);    // 512 CTAs
    dim3 g64(16, 16);                    // 256 CTAs
    dim3 gSK2(16, 16, 2);
    dim3 gSK4(16, 16, 4);
    dim3 gS(SS / 32, BB * HH);           // 512 CTAs
    dim3 gC(SS / 64, BB * HH);

    // ------------------------- Encoder -------------------------
    const float* cur = src;
    const __half* curh = srch;
    for (int l = 0; l < LL; l++) {
        const float* bb = enc_b + (size_t)l * 4 * DD;
        gemm_wide_h<<<gQKV, 256, SM_W>>>(curh, encWt + (size_t)l * 4 * M1, bb, Qh,
                                         DD, DD, 0, (long long)M1, DD, (long long)M1);
        float* adst = full ? out + OFF_ENC + (size_t)l * SLAB : ATT;
        attn_scores_f16<<<gS, 256, SC_SMEM>>>(Qh, Qh + M1, src_mask, 0, adst, Ph);
        attn_ctx_f16<<<gC, 256>>>(Ph, Qh + 2 * M1, Qh);
        gemm_sk_h<<<gSK2, 128>>>(Qh, encWt + ((size_t)l * 4 + 3) * M1, PRT, 1024, 1024, 512);
        add_ln_red<<<MROWS, 256>>>(cur, PRT, 2, bb + 3 * DD,
                                   enc_lng + (size_t)l * 2 * DD,
                                   enc_lnb + (size_t)l * 2 * DD, X2, X2h);
        gemm_wide_h<<<gF1, 256, SM_W>>>(X2h, eW1t + (size_t)l * 4 * M1,
                                        enc_b1 + (size_t)l * DFFF, H1h,
                                        DD, DFFF, 1, 0, 0, 0);
        gemm_sk_h<<<gSK4, 128>>>(H1h, eW2t + (size_t)l * 4 * M1, PRT, 4096, 4096, 1024);
        add_ln_red<<<MROWS, 256>>>(X2, PRT, 4, enc_b2 + (size_t)l * DD,
                                   enc_lng + (size_t)l * 2 * DD + DD,
                                   enc_lnb + (size_t)l * 2 * DD + DD, X, Xh);
        cur = X; curh = Xh;
    }
    ln_plain<<<MROWS, 256>>>(cur, enc_fg, enc_fb, ENC, ENCh);

    // Batched cross-attention K/V (blk = layer)
    gemm_wide_h<<<gKVB, 256, SM_W>>>(ENCh, dcWt + M1, dcb + DD, CKh,
                                     DD, DD, 0, 4LL * M1, 4LL * DD, (long long)M1);
    gemm_wide_h<<<gKVB, 256, SM_W>>>(ENCh, dcWt + 2 * M1, dcb + 2 * DD, CVh,
                                     DD, DD, 0, 4LL * M1, 4LL * DD, (long long)M1);

    // ------------------------- Decoder -------------------------
    cur = tgt; curh = tgth;
    for (int l = 0; l < LL; l++) {
        const float* bs = dsb + (size_t)l * 4 * DD;
        gemm_wide_h<<<gQKV, 256, SM_W>>>(curh, dsWt + (size_t)l * 4 * M1, bs, Qh,
                                         DD, DD, 0, (long long)M1, DD, (long long)M1);
        float* adst = full ? out + OFF_SELF + (size_t)l * SLAB : ATT;
        attn_scores_f16<<<gS, 256, SC_SMEM>>>(Qh, Qh + M1, tgt_mask, 1, adst, Ph);
        attn_ctx_f16<<<gC, 256>>>(Ph, Qh + 2 * M1, Qh);
        gemm_sk_h<<<gSK2, 128>>>(Qh, dsWt + ((size_t)l * 4 + 3) * M1, PRT, 1024, 1024, 512);
        add_ln_red<<<MROWS, 256>>>(cur, PRT, 2, bs + 3 * DD,
                                   dlng + (size_t)l * 3 * DD,
                                   dlnb + (size_t)l * 3 * DD, X, Xh);

        const float* bc = dcb + (size_t)l * 4 * DD;
        gemm_h64<<<g64, 128>>>(Xh, dcWt + (size_t)l * 4 * M1, bc, Qh);
        adst = full ? out + OFF_CROSS + (size_t)l * SLAB : ATT;
        attn_scores_f16<<<gS, 256, SC_SMEM>>>(Qh, CKh + (size_t)l * M1, src_mask, 0, adst, Ph);
        attn_ctx_f16<<<gC, 256>>>(Ph, CVh + (size_t)l * M1, Qh);
        gemm_sk_h<<<gSK2, 128>>>(Qh, dcWt + ((size_t)l * 4 + 3) * M1, PRT, 1024, 1024, 512);
        add_ln_red<<<MROWS, 256>>>(X, PRT, 2, bc + 3 * DD,
                                   dlng + (size_t)l * 3 * DD + DD,
                                   dlnb + (size_t)l * 3 * DD + DD, X2, X2h);

        gemm_wide_h<<<gF1, 256, SM_W>>>(X2h, dW1t + (size_t)l * 4 * M1,
                                        db1 + (size_t)l * DFFF, H1h,
                                        DD, DFFF, 1, 0, 0, 0);
        gemm_sk_h<<<gSK4, 128>>>(H1h, dW2t + (size_t)l * 4 * M1, PRT, 4096, 4096, 1024);
        add_ln_red<<<MROWS, 256>>>(X2, PRT, 4, db2 + (size_t)l * DD,
                                   dlng + (size_t)l * 3 * DD + 2 * DD,
                                   dlnb + (size_t)l * 3 * DD + 2 * DD, X, Xh);
        cur = X; curh = Xh;
    }
    ln_plain<<<MROWS, 256>>>(cur, dfg, dfb, out, nullptr);
}